// round 2
// baseline (speedup 1.0000x reference)
#include <cuda_runtime.h>
#include <cstdint>

#define NB 8
#define NSEQ 1024
#define CDIM 1280
#define NH 20
#define DH 64
#define MCTX 77
#define CTXC 768
#define FFD 5120
#define FF2D 10240
#define ROWS (NB*NSEQ)
#define BHD (NB*NH)
#define CROSSROWS (NB*MCTX)

static constexpr size_t SZ_XC = (size_t)ROWS * CDIM;
static constexpr size_t OFF_XN = 0;
static constexpr size_t OFF_Q  = OFF_XN + SZ_XC;
static constexpr size_t OFF_K  = OFF_Q + SZ_XC;
static constexpr size_t OFF_V  = OFF_K + SZ_XC;
static constexpr size_t OFF_O  = OFF_V + SZ_XC;
static constexpr size_t OFF_X1 = OFF_O + SZ_XC;
static constexpr size_t OFF_S  = OFF_X1 + SZ_XC;
static constexpr size_t SZ_S   = (size_t)BHD * NSEQ * NSEQ;
static constexpr size_t OFF_H  = OFF_S + SZ_S;
static constexpr size_t SZ_H   = (size_t)ROWS * FF2D;
static constexpr size_t OFF_G  = OFF_H + SZ_H;
static constexpr size_t SZ_G   = (size_t)ROWS * FFD;
static constexpr size_t OFF_RM = OFF_G + SZ_G;
static constexpr size_t OFF_RZ = OFF_RM + (size_t)BHD * NSEQ;
static constexpr size_t OFF_AM = OFF_RZ + (size_t)BHD * NSEQ;
static constexpr size_t TOTAL_SCRATCH = OFF_AM + 8;

__device__ float g_scratch[TOTAL_SCRATCH];

__global__ void init_amax_kernel(unsigned* amax) {
    if (threadIdx.x < 8) amax[threadIdx.x] = 0u;
}

__device__ __forceinline__ float gelu_tanh(float x) {
    float x3 = x * x * x;
    return 0.5f * x * (1.0f + tanhf(0.7978845608028654f * (x + 0.044715f * x3)));
}

// ---------------- LayerNorm: one block per row ----------------
__global__ void ln_kernel(const float* __restrict__ x, const float* __restrict__ g,
                          const float* __restrict__ bta, float* __restrict__ out)
{
    __shared__ float sx[CDIM];
    __shared__ float red[8];
    int row = blockIdx.x, tid = threadIdx.x;
    const float* xr = x + (size_t)row * CDIM;
    float s = 0.f;
    for (int i = tid; i < CDIM; i += 256) { float v = xr[i]; sx[i] = v; s += v; }
    #pragma unroll
    for (int o = 16; o; o >>= 1) s += __shfl_xor_sync(0xffffffffu, s, o);
    if ((tid & 31) == 0) red[tid >> 5] = s;
    __syncthreads();
    float tot = 0.f;
    #pragma unroll
    for (int w = 0; w < 8; w++) tot += red[w];
    float mean = tot * (1.0f / (float)CDIM);
    float vs = 0.f;
    for (int i = tid; i < CDIM; i += 256) { float d = sx[i] - mean; vs += d * d; }
    __syncthreads();
    #pragma unroll
    for (int o = 16; o; o >>= 1) vs += __shfl_xor_sync(0xffffffffu, vs, o);
    if ((tid & 31) == 0) red[tid >> 5] = vs;
    __syncthreads();
    float tot2 = 0.f;
    #pragma unroll
    for (int w = 0; w < 8; w++) tot2 += red[w];
    float rstd = rsqrtf(tot2 * (1.0f / (float)CDIM) + 1e-5f);
    for (int i = tid; i < CDIM; i += 256)
        out[(size_t)row * CDIM + i] = (sx[i] - mean) * rstd * g[i] + bta[i];
}

// ------------- SGEMM 128x128x16, 8x8 microtile, double buffered -------------
template<bool HAS_BIAS, bool HAS_RES, bool DO_AMAX>
__global__ void __launch_bounds__(256, 2) sgemm_kernel(
    const float* __restrict__ A, const float* __restrict__ Bm, float* __restrict__ Cm,
    int Mn, int Nn, int Kn,
    const float* __restrict__ bias, const float* __restrict__ res, unsigned* amax)
{
    __shared__ __align__(16) float As[2][16][132];
    __shared__ __align__(16) float Bs[2][16][128];
    __shared__ float reds[8];
    int tid = threadIdx.x;
    int tx = tid & 15, ty = tid >> 4;
    int nBase = blockIdx.x * 128, mBase = blockIdx.y * 128;
    const int aRow = tid >> 2, aCol = (tid & 3) << 2;
    const int bRow = tid >> 5, bCol = (tid & 31) << 2;

    float acc[8][8];
    #pragma unroll
    for (int i = 0; i < 8; i++)
        #pragma unroll
        for (int j = 0; j < 8; j++) acc[i][j] = 0.f;

    float4 ra[2], rb[2];
    #pragma unroll
    for (int i = 0; i < 2; i++) {
        int gr = mBase + aRow + i * 64;
        ra[i] = (gr < Mn) ? *(const float4*)(A + (size_t)gr * Kn + aCol)
                          : make_float4(0.f,0.f,0.f,0.f);
        rb[i] = *(const float4*)(Bm + (size_t)(bRow + i * 8) * Nn + (nBase + bCol));
    }
    #pragma unroll
    for (int i = 0; i < 2; i++) {
        As[0][aCol+0][aRow+i*64] = ra[i].x; As[0][aCol+1][aRow+i*64] = ra[i].y;
        As[0][aCol+2][aRow+i*64] = ra[i].z; As[0][aCol+3][aRow+i*64] = ra[i].w;
        *(float4*)&Bs[0][bRow+i*8][bCol] = rb[i];
    }
    __syncthreads();

    int KT = Kn >> 4;
    for (int kt = 0; kt < KT; ++kt) {
        int buf = kt & 1;
        if (kt + 1 < KT) {
            int k0 = (kt + 1) << 4;
            #pragma unroll
            for (int i = 0; i < 2; i++) {
                int gr = mBase + aRow + i * 64;
                ra[i] = (gr < Mn) ? *(const float4*)(A + (size_t)gr * Kn + (k0 + aCol))
                                  : make_float4(0.f,0.f,0.f,0.f);
                rb[i] = *(const float4*)(Bm + (size_t)(k0 + bRow + i * 8) * Nn + (nBase + bCol));
            }
        }
        #pragma unroll
        for (int k = 0; k < 16; k++) {
            float4 a0 = *(const float4*)&As[buf][k][ty*8];
            float4 a1 = *(const float4*)&As[buf][k][ty*8+4];
            float4 b0 = *(const float4*)&Bs[buf][k][tx*8];
            float4 b1 = *(const float4*)&Bs[buf][k][tx*8+4];
            float av[8] = {a0.x,a0.y,a0.z,a0.w,a1.x,a1.y,a1.z,a1.w};
            float bv[8] = {b0.x,b0.y,b0.z,b0.w,b1.x,b1.y,b1.z,b1.w};
            #pragma unroll
            for (int i = 0; i < 8; i++)
                #pragma unroll
                for (int j = 0; j < 8; j++)
                    acc[i][j] = fmaf(av[i], bv[j], acc[i][j]);
        }
        if (kt + 1 < KT) {
            int nb = buf ^ 1;
            #pragma unroll
            for (int i = 0; i < 2; i++) {
                As[nb][aCol+0][aRow+i*64] = ra[i].x; As[nb][aCol+1][aRow+i*64] = ra[i].y;
                As[nb][aCol+2][aRow+i*64] = ra[i].z; As[nb][aCol+3][aRow+i*64] = ra[i].w;
                *(float4*)&Bs[nb][bRow+i*8][bCol] = rb[i];
            }
            __syncthreads();
        }
    }

    float amx = 0.f;
    #pragma unroll
    for (int i = 0; i < 8; i++) {
        int row = mBase + ty * 8 + i;
        if (row < Mn) {
            #pragma unroll
            for (int j = 0; j < 8; j++) {
                int col = nBase + tx * 8 + j;
                float c = acc[i][j];
                if (HAS_BIAS) c += bias[col];
                if (HAS_RES)  c += res[(size_t)row * Nn + col];
                Cm[(size_t)row * Nn + col] = c;
                if (DO_AMAX) amx = fmaxf(amx, fabsf(c));
            }
        }
    }
    if (DO_AMAX) {
        #pragma unroll
        for (int o = 16; o; o >>= 1) amx = fmaxf(amx, __shfl_xor_sync(0xffffffffu, amx, o));
        if ((tid & 31) == 0) reds[tid >> 5] = amx;
        __syncthreads();
        if (tid == 0) {
            float m = reds[0];
            #pragma unroll
            for (int w = 1; w < 8; w++) m = fmaxf(m, reds[w]);
            atomicMax(amax, __float_as_uint(m));
        }
    }
}

// ---------------- per-tensor symmetric fake-quant in place ----------------
__global__ void quant_sym_kernel(float* __restrict__ x, long long n4,
                                 const unsigned* __restrict__ amaxbits)
{
    float delta = fmaxf(__uint_as_float(*amaxbits), 1e-8f) / 127.0f;
    long long stride = (long long)gridDim.x * blockDim.x;
    for (long long i = (long long)blockIdx.x * blockDim.x + threadIdx.x; i < n4; i += stride) {
        float4 v = *(float4*)(x + i * 4);
        float l;
        l = rintf(v.x/delta); l = fminf(fmaxf(l,-128.f),127.f); v.x = l*delta;
        l = rintf(v.y/delta); l = fminf(fmaxf(l,-128.f),127.f); v.y = l*delta;
        l = rintf(v.z/delta); l = fminf(fmaxf(l,-128.f),127.f); v.z = l*delta;
        l = rintf(v.w/delta); l = fminf(fmaxf(l,-128.f),127.f); v.w = l*delta;
        *(float4*)(x + i * 4) = v;
    }
}

// ---------------- self-attn scores S = QK^T / 8 ----------------
__global__ void __launch_bounds__(256) self_scores_kernel(
    const float* __restrict__ q, const float* __restrict__ k, float* __restrict__ S)
{
    __shared__ __align__(16) float Qs[64][68];
    __shared__ __align__(16) float Ks[64][68];
    int tid = threadIdx.x;
    int bh = blockIdx.z, b = bh / NH, h = bh % NH;
    int n0 = blockIdx.x * 64, m0 = blockIdx.y * 64;
    #pragma unroll
    for (int it = 0; it < 4; ++it) {
        int r = (tid >> 4) + it * 16, c = (tid & 15) << 2;
        float4 qv = *(const float4*)(q + ((size_t)(b*NSEQ + n0 + r))*CDIM + h*DH + c);
        Qs[c+0][r]=qv.x; Qs[c+1][r]=qv.y; Qs[c+2][r]=qv.z; Qs[c+3][r]=qv.w;
        float4 kv = *(const float4*)(k + ((size_t)(b*NSEQ + m0 + r))*CDIM + h*DH + c);
        Ks[c+0][r]=kv.x; Ks[c+1][r]=kv.y; Ks[c+2][r]=kv.z; Ks[c+3][r]=kv.w;
    }
    __syncthreads();
    int tx = tid & 15, ty = tid >> 4;
    float acc[4][4];
    #pragma unroll
    for (int i = 0; i < 4; i++)
        #pragma unroll
        for (int j = 0; j < 4; j++) acc[i][j] = 0.f;
    #pragma unroll 8
    for (int d = 0; d < 64; ++d) {
        float4 q4 = *(const float4*)&Qs[d][ty*4];
        float4 k4 = *(const float4*)&Ks[d][tx*4];
        float qa[4]={q4.x,q4.y,q4.z,q4.w}, ka[4]={k4.x,k4.y,k4.z,k4.w};
        #pragma unroll
        for (int i = 0; i < 4; i++)
            #pragma unroll
            for (int j = 0; j < 4; j++) acc[i][j] = fmaf(qa[i], ka[j], acc[i][j]);
    }
    #pragma unroll
    for (int i = 0; i < 4; i++) {
        float4 o = {acc[i][0]*0.125f, acc[i][1]*0.125f, acc[i][2]*0.125f, acc[i][3]*0.125f};
        *(float4*)(S + ((size_t)bh*NSEQ + n0 + ty*4 + i)*NSEQ + m0 + tx*4) = o;
    }
}

// -------- softmax row stats; global max prob = max(1/Z) --------
__global__ void softmax_stats_kernel(const float* __restrict__ S, float* __restrict__ rowmax,
                                     float* __restrict__ rowz, unsigned* wmax, int cols, int stride)
{
    int row = blockIdx.x, tid = threadIdx.x;
    const float* s = S + (size_t)row * stride;
    __shared__ float red[8];
    float m = -3.4e38f;
    for (int i = tid; i < cols; i += 256) m = fmaxf(m, s[i]);
    #pragma unroll
    for (int o = 16; o; o >>= 1) m = fmaxf(m, __shfl_xor_sync(0xffffffffu, m, o));
    if ((tid & 31) == 0) red[tid >> 5] = m;
    __syncthreads();
    float mm = red[0];
    #pragma unroll
    for (int w = 1; w < 8; w++) mm = fmaxf(mm, red[w]);
    __syncthreads();
    float z = 0.f;
    for (int i = tid; i < cols; i += 256) z += expf(s[i] - mm);
    #pragma unroll
    for (int o = 16; o; o >>= 1) z += __shfl_xor_sync(0xffffffffu, z, o);
    if ((tid & 31) == 0) red[tid >> 5] = z;
    __syncthreads();
    if (tid == 0) {
        float zz = 0.f;
        #pragma unroll
        for (int w = 0; w < 8; w++) zz += red[w];
        rowmax[row] = mm; rowz[row] = zz;
        atomicMax(wmax, __float_as_uint(1.0f / zz));
    }
}

// -------- self-attn PV with fused fq_zero on probs --------
__global__ void __launch_bounds__(256) self_pv_kernel(
    const float* __restrict__ S, const float* __restrict__ v,
    const float* __restrict__ rowmax, const float* __restrict__ rowz,
    const unsigned* __restrict__ wmaxbits, float* __restrict__ O)
{
    __shared__ __align__(16) float Ws[64][68];
    __shared__ __align__(16) float Vs[64][68];
    int tid = threadIdx.x;
    int bh = blockIdx.z, b = bh / NH, h = bh % NH;
    int n0 = blockIdx.x * 64;
    int tx = tid & 15, ty = tid >> 4;
    float delta = fmaxf(__uint_as_float(*wmaxbits), 1e-8f) / 255.0f;
    float inv_delta = 1.0f / delta;
    float rm4[4], ri4[4];
    #pragma unroll
    for (int it = 0; it < 4; it++) {
        int r = (tid >> 4) + it * 16;
        rm4[it] = rowmax[(size_t)bh*NSEQ + n0 + r];
        ri4[it] = 1.0f / rowz[(size_t)bh*NSEQ + n0 + r];
    }
    float acc[4][4];
    #pragma unroll
    for (int i = 0; i < 4; i++)
        #pragma unroll
        for (int j = 0; j < 4; j++) acc[i][j] = 0.f;
    for (int mt = 0; mt < 16; ++mt) {
        int m0 = mt * 64;
        __syncthreads();
        #pragma unroll
        for (int it = 0; it < 4; ++it) {
            int r = (tid >> 4) + it * 16, c = (tid & 15) << 2;
            float4 sv = *(const float4*)(S + ((size_t)bh*NSEQ + n0 + r)*NSEQ + m0 + c);
            float rm = rm4[it], ri = ri4[it], p, l;
            p = expf(sv.x-rm); l = rintf(p*ri*inv_delta); l = fminf(fmaxf(l,0.f),255.f); Ws[c+0][r] = l*delta;
            p = expf(sv.y-rm); l = rintf(p*ri*inv_delta); l = fminf(fmaxf(l,0.f),255.f); Ws[c+1][r] = l*delta;
            p = expf(sv.z-rm); l = rintf(p*ri*inv_delta); l = fminf(fmaxf(l,0.f),255.f); Ws[c+2][r] = l*delta;
            p = expf(sv.w-rm); l = rintf(p*ri*inv_delta); l = fminf(fmaxf(l,0.f),255.f); Ws[c+3][r] = l*delta;
            *(float4*)&Vs[r][c] = *(const float4*)(v + ((size_t)(b*NSEQ + m0 + r))*CDIM + h*DH + c);
        }
        __syncthreads();
        #pragma unroll 8
        for (int m = 0; m < 64; m++) {
            float4 w4 = *(const float4*)&Ws[m][ty*4];
            float4 v4 = *(const float4*)&Vs[m][tx*4];
            float wa[4]={w4.x,w4.y,w4.z,w4.w}, va[4]={v4.x,v4.y,v4.z,v4.w};
            #pragma unroll
            for (int i = 0; i < 4; i++)
                #pragma unroll
                for (int j = 0; j < 4; j++) acc[i][j] = fmaf(wa[i], va[j], acc[i][j]);
        }
    }
    #pragma unroll
    for (int i = 0; i < 4; i++) {
        float4 o = {acc[i][0], acc[i][1], acc[i][2], acc[i][3]};
        *(float4*)(O + ((size_t)(b*NSEQ + n0 + ty*4 + i))*CDIM + h*DH + tx*4) = o;
    }
}

// -------- cross-attn scores (M=77, stride 80) --------
__global__ void __launch_bounds__(256) cross_scores_kernel(
    const float* __restrict__ q, const float* __restrict__ k, float* __restrict__ S)
{
    __shared__ __align__(16) float Qs[64][68];
    __shared__ __align__(16) float Ks[80][68];
    int tid = threadIdx.x;
    int bh = blockIdx.y, b = bh / NH, h = bh % NH;
    int n0 = blockIdx.x * 64;
    #pragma unroll
    for (int it = 0; it < 4; ++it) {
        int r = (tid >> 4) + it * 16, c = (tid & 15) << 2;
        float4 qv = *(const float4*)(q + ((size_t)(b*NSEQ + n0 + r))*CDIM + h*DH + c);
        Qs[c+0][r]=qv.x; Qs[c+1][r]=qv.y; Qs[c+2][r]=qv.z; Qs[c+3][r]=qv.w;
    }
    #pragma unroll
    for (int it = 0; it < 5; ++it) {
        int lin = tid + it * 256;
        if (lin < 80 * 16) {
            int r = lin >> 4, c = (lin & 15) << 2;
            float4 kv = (r < MCTX) ? *(const float4*)(k + ((size_t)(b*MCTX + r))*CDIM + h*DH + c)
                                   : make_float4(0.f,0.f,0.f,0.f);
            *(float4*)&Ks[r][c] = kv;
        }
    }
    __syncthreads();
    int tx = tid & 15, ty = tid >> 4;
    float acc[4][5];
    #pragma unroll
    for (int i = 0; i < 4; i++)
        #pragma unroll
        for (int j = 0; j < 5; j++) acc[i][j] = 0.f;
    #pragma unroll 4
    for (int d = 0; d < 64; ++d) {
        float4 q4 = *(const float4*)&Qs[d][ty*4];
        float qa[4]={q4.x,q4.y,q4.z,q4.w};
        #pragma unroll
        for (int jj = 0; jj < 5; jj++) {
            float kv = Ks[tx*5+jj][d];
            #pragma unroll
            for (int i = 0; i < 4; i++) acc[i][jj] = fmaf(qa[i], kv, acc[i][jj]);
        }
    }
    #pragma unroll
    for (int i = 0; i < 4; i++)
        #pragma unroll
        for (int jj = 0; jj < 5; jj++) {
            int m = tx * 5 + jj;
            if (m < MCTX)
                S[((size_t)bh*NSEQ + n0 + ty*4 + i)*80 + m] = acc[i][jj] * 0.125f;
        }
}

// -------- cross-attn PV with fused fq_zero --------
__global__ void __launch_bounds__(256) cross_pv_kernel(
    const float* __restrict__ S, const float* __restrict__ v,
    const float* __restrict__ rowmax, const float* __restrict__ rowz,
    const unsigned* __restrict__ wmaxbits, float* __restrict__ O)
{
    __shared__ __align__(16) float Ws[80][68];
    __shared__ __align__(16) float Vs[80][68];
    int tid = threadIdx.x;
    int bh = blockIdx.y, b = bh / NH, h = bh % NH;
    int n0 = blockIdx.x * 64;
    int tx = tid & 15, ty = tid >> 4;
    float delta = fmaxf(__uint_as_float(*wmaxbits), 1e-8f) / 255.0f;
    float inv_delta = 1.0f / delta;
    #pragma unroll
    for (int it = 0; it < 5; ++it) {
        int lin = tid + it * 256;
        if (lin < MCTX * 16) {
            int r = lin >> 4, c = (lin & 15) << 2;
            *(float4*)&Vs[r][c] = *(const float4*)(v + ((size_t)(b*MCTX + r))*CDIM + h*DH + c);
        }
    }
    #pragma unroll
    for (int it = 0; it < 4; ++it) {
        int r = (tid >> 4) + it * 16;
        float rm = rowmax[(size_t)bh*NSEQ + n0 + r];
        float ri = 1.0f / rowz[(size_t)bh*NSEQ + n0 + r];
        #pragma unroll
        for (int jj = 0; jj < 5; jj++) {
            int m = (tid & 15) * 5 + jj;
            float w = 0.f;
            if (m < MCTX) {
                float s = S[((size_t)bh*NSEQ + n0 + r)*80 + m];
                float p = expf(s - rm);
                float l = rintf(p * ri * inv_delta);
                l = fminf(fmaxf(l, 0.f), 255.f);
                w = l * delta;
            }
            Ws[m][r] = w;
        }
    }
    __syncthreads();
    float acc[4][4];
    #pragma unroll
    for (int i = 0; i < 4; i++)
        #pragma unroll
        for (int j = 0; j < 4; j++) acc[i][j] = 0.f;
    for (int m = 0; m < MCTX; m++) {
        float4 w4 = *(const float4*)&Ws[m][ty*4];
        float4 v4 = *(const float4*)&Vs[m][tx*4];
        float wa[4]={w4.x,w4.y,w4.z,w4.w}, va[4]={v4.x,v4.y,v4.z,v4.w};
        #pragma unroll
        for (int i = 0; i < 4; i++)
            #pragma unroll
            for (int j = 0; j < 4; j++) acc[i][j] = fmaf(wa[i], va[j], acc[i][j]);
    }
    #pragma unroll
    for (int i = 0; i < 4; i++) {
        float4 o = {acc[i][0], acc[i][1], acc[i][2], acc[i][3]};
        *(float4*)(O + ((size_t)(b*NSEQ + n0 + ty*4 + i))*CDIM + h*DH + tx*4) = o;
    }
}

// -------- GEGLU: G = a * gelu(g) --------
__global__ void geglu_kernel(const float* __restrict__ Hh, float* __restrict__ G)
{
    size_t n4 = (size_t)ROWS * FFD / 4;
    size_t stride = (size_t)gridDim.x * blockDim.x;
    for (size_t i = (size_t)blockIdx.x * blockDim.x + threadIdx.x; i < n4; i += stride) {
        size_t col4 = i % (FFD / 4), row = i / (FFD / 4);
        float4 a4 = *(const float4*)(Hh + row * FF2D + col4 * 4);
        float4 g4 = *(const float4*)(Hh + row * FF2D + FFD + col4 * 4);
        float4 o;
        o.x = a4.x * gelu_tanh(g4.x); o.y = a4.y * gelu_tanh(g4.y);
        o.z = a4.z * gelu_tanh(g4.z); o.w = a4.w * gelu_tanh(g4.w);
        *(float4*)(G + i * 4) = o;
    }
}

extern "C" void kernel_launch(void* const* d_in, const int* in_sizes, int n_in,
                              void* d_out, int out_size)
{
    const float* x    = (const float*)d_in[0];
    const float* ctx  = (const float*)d_in[1];
    const float* ln1g = (const float*)d_in[2];
    const float* ln1b = (const float*)d_in[3];
    const float* ln2g = (const float*)d_in[4];
    const float* ln2b = (const float*)d_in[5];
    const float* ln3g = (const float*)d_in[6];
    const float* ln3b = (const float*)d_in[7];
    const float* Wq1  = (const float*)d_in[8];
    const float* Wk1  = (const float*)d_in[9];
    const float* Wv1  = (const float*)d_in[10];
    const float* Wo1  = (const float*)d_in[11];
    const float* bo1  = (const float*)d_in[12];
    const float* Wq2  = (const float*)d_in[13];
    const float* Wk2  = (const float*)d_in[14];
    const float* Wv2  = (const float*)d_in[15];
    const float* Wo2  = (const float*)d_in[16];
    const float* bo2  = (const float*)d_in[17];
    const float* Wff1 = (const float*)d_in[18];
    const float* bff1 = (const float*)d_in[19];
    const float* Wff2 = (const float*)d_in[20];
    const float* bff2 = (const float*)d_in[21];
    float* out = (float*)d_out;

    float* sc = nullptr;
    cudaGetSymbolAddress((void**)&sc, g_scratch);
    float* XN = sc + OFF_XN;  float* Q  = sc + OFF_Q;
    float* K  = sc + OFF_K;   float* V  = sc + OFF_V;
    float* O  = sc + OFF_O;   float* X1 = sc + OFF_X1;
    float* S  = sc + OFF_S;   float* Hb = sc + OFF_H;
    float* G  = sc + OFF_G;   float* RM = sc + OFF_RM;
    float* RZ = sc + OFF_RZ;
    unsigned* AM = (unsigned*)(sc + OFF_AM);

    dim3 g1280(CDIM / 128, ROWS / 128);
    dim3 gcross(CDIM / 128, (CROSSROWS + 127) / 128);
    dim3 gff1(FF2D / 128, ROWS / 128);
    long long n4  = (long long)ROWS * CDIM / 4;
    long long n4c = (long long)CROSSROWS * CDIM / 4;

    init_amax_kernel<<<1, 32>>>(AM);

    // ---- block 1: self attention ----
    ln_kernel<<<ROWS, 256>>>(x, ln1g, ln1b, XN);
    sgemm_kernel<false,false,true><<<g1280,256>>>(XN, Wq1, Q, ROWS, CDIM, CDIM, nullptr, nullptr, AM+0);
    sgemm_kernel<false,false,true><<<g1280,256>>>(XN, Wk1, K, ROWS, CDIM, CDIM, nullptr, nullptr, AM+1);
    sgemm_kernel<false,false,true><<<g1280,256>>>(XN, Wv1, V, ROWS, CDIM, CDIM, nullptr, nullptr, AM+2);
    quant_sym_kernel<<<2048,256>>>(Q, n4, AM+0);
    quant_sym_kernel<<<2048,256>>>(K, n4, AM+1);
    quant_sym_kernel<<<2048,256>>>(V, n4, AM+2);
    self_scores_kernel<<<dim3(16,16,BHD),256>>>(Q, K, S);
    softmax_stats_kernel<<<BHD*NSEQ,256>>>(S, RM, RZ, AM+3, NSEQ, NSEQ);
    self_pv_kernel<<<dim3(16,1,BHD),256>>>(S, V, RM, RZ, AM+3, O);
    sgemm_kernel<true,true,false><<<g1280,256>>>(O, Wo1, X1, ROWS, CDIM, CDIM, bo1, x, nullptr);

    // ---- block 2: cross attention ----
    ln_kernel<<<ROWS,256>>>(X1, ln2g, ln2b, XN);
    sgemm_kernel<false,false,true><<<g1280,256>>>(XN, Wq2, Q, ROWS, CDIM, CDIM, nullptr, nullptr, AM+4);
    sgemm_kernel<false,false,true><<<gcross,256>>>(ctx, Wk2, K, CROSSROWS, CDIM, CTXC, nullptr, nullptr, AM+5);
    sgemm_kernel<false,false,true><<<gcross,256>>>(ctx, Wv2, V, CROSSROWS, CDIM, CTXC, nullptr, nullptr, AM+6);
    quant_sym_kernel<<<2048,256>>>(Q, n4, AM+4);
    quant_sym_kernel<<<512,256>>>(K, n4c, AM+5);
    quant_sym_kernel<<<512,256>>>(V, n4c, AM+6);
    cross_scores_kernel<<<dim3(16,BHD),256>>>(Q, K, S);
    softmax_stats_kernel<<<BHD*NSEQ,256>>>(S, RM, RZ, AM+7, MCTX, 80);
    cross_pv_kernel<<<dim3(16,BHD),256>>>(S, V, RM, RZ, AM+7, O);
    sgemm_kernel<true,true,false><<<g1280,256>>>(O, Wo2, X1, ROWS, CDIM, CDIM, bo2, X1, nullptr);

    // ---- block 3: GEGLU FF ----
    ln_kernel<<<ROWS,256>>>(X1, ln3g, ln3b, XN);
    sgemm_kernel<true,false,false><<<gff1,256>>>(XN, Wff1, Hb, ROWS, FF2D, CDIM, bff1, nullptr, nullptr);
    geglu_kernel<<<4096,256>>>(Hb, G);
    sgemm_kernel<true,true,false><<<g1280,256>>>(G, Wff2, out, ROWS, CDIM, FFD, bff2, X1, nullptr);
}

// round 3
// speedup vs baseline: 1.7851x; 1.7851x over previous
#include <cuda_runtime.h>
#include <cstdint>

#define NB 8
#define NSEQ 1024
#define CDIM 1280
#define NH 20
#define DH 64
#define MCTX 77
#define CTXC 768
#define FFD 5120
#define FF2D 10240
#define ROWS (NB*NSEQ)
#define BHD (NB*NH)
#define CROSSROWS (NB*MCTX)

static constexpr size_t SZ_XC = (size_t)ROWS * CDIM;
static constexpr size_t OFF_XN = 0;
static constexpr size_t OFF_Q  = OFF_XN + SZ_XC;
static constexpr size_t OFF_K  = OFF_Q + SZ_XC;
static constexpr size_t OFF_V  = OFF_K + SZ_XC;
static constexpr size_t OFF_O  = OFF_V + SZ_XC;
static constexpr size_t OFF_X1 = OFF_O + SZ_XC;
static constexpr size_t OFF_S  = OFF_X1 + SZ_XC;
static constexpr size_t SZ_S   = (size_t)BHD * NSEQ * NSEQ;
static constexpr size_t OFF_H  = OFF_S + SZ_S;
static constexpr size_t SZ_H   = (size_t)ROWS * FF2D;
static constexpr size_t OFF_G  = OFF_H + SZ_H;
static constexpr size_t SZ_G   = (size_t)ROWS * FFD;
static constexpr size_t OFF_RM = OFF_G + SZ_G;
static constexpr size_t OFF_RZ = OFF_RM + (size_t)BHD * NSEQ;
static constexpr size_t OFF_AM = OFF_RZ + (size_t)BHD * NSEQ;
static constexpr size_t TOTAL_SCRATCH = OFF_AM + 8;

__device__ float g_scratch[TOTAL_SCRATCH];

__global__ void init_amax_kernel(unsigned* amax) {
    if (threadIdx.x < 8) amax[threadIdx.x] = 0u;
}

__device__ __forceinline__ float gelu_tanh(float x) {
    float x3 = x * x * x;
    return 0.5f * x * (1.0f + tanhf(0.7978845608028654f * (x + 0.044715f * x3)));
}

__device__ __forceinline__ uint32_t f2tf32(float f) {
    uint32_t r;
    asm("cvt.rna.tf32.f32 %0, %1;" : "=r"(r) : "f"(f));
    return r;
}

__device__ __forceinline__ void mma_tf32(float* d, const uint32_t* a, const uint32_t* b) {
    asm volatile("mma.sync.aligned.m16n8k8.row.col.f32.tf32.tf32.f32 "
        "{%0,%1,%2,%3}, {%4,%5,%6,%7}, {%8,%9}, {%0,%1,%2,%3};"
        : "+f"(d[0]), "+f"(d[1]), "+f"(d[2]), "+f"(d[3])
        : "r"(a[0]), "r"(a[1]), "r"(a[2]), "r"(a[3]), "r"(b[0]), "r"(b[1]));
}

// ---------------- LayerNorm: one block per row ----------------
__global__ void ln_kernel(const float* __restrict__ x, const float* __restrict__ g,
                          const float* __restrict__ bta, float* __restrict__ out)
{
    __shared__ float sx[CDIM];
    __shared__ float red[8];
    int row = blockIdx.x, tid = threadIdx.x;
    const float* xr = x + (size_t)row * CDIM;
    float s = 0.f;
    for (int i = tid; i < CDIM; i += 256) { float v = xr[i]; sx[i] = v; s += v; }
    #pragma unroll
    for (int o = 16; o; o >>= 1) s += __shfl_xor_sync(0xffffffffu, s, o);
    if ((tid & 31) == 0) red[tid >> 5] = s;
    __syncthreads();
    float tot = 0.f;
    #pragma unroll
    for (int w = 0; w < 8; w++) tot += red[w];
    float mean = tot * (1.0f / (float)CDIM);
    float vs = 0.f;
    for (int i = tid; i < CDIM; i += 256) { float d = sx[i] - mean; vs += d * d; }
    __syncthreads();
    #pragma unroll
    for (int o = 16; o; o >>= 1) vs += __shfl_xor_sync(0xffffffffu, vs, o);
    if ((tid & 31) == 0) red[tid >> 5] = vs;
    __syncthreads();
    float tot2 = 0.f;
    #pragma unroll
    for (int w = 0; w < 8; w++) tot2 += red[w];
    float rstd = rsqrtf(tot2 * (1.0f / (float)CDIM) + 1e-5f);
    for (int i = tid; i < CDIM; i += 256)
        out[(size_t)row * CDIM + i] = (sx[i] - mean) * rstd * g[i] + bta[i];
}

// ============ TF32 tensor-core GEMM: C = A(MxK) @ B(KxN) ============
// block tile 128(M) x 64(N), K-tile 16, double buffered.
// 8 warps: wm = warp&3 (4 M-warps of 32), wn = warp>>2 (2 N-warps of 32).
// warp tile 32x32 -> mma m16n8k8 grid of 2(M) x 4(N) x 2(K).
template<bool HAS_BIAS, bool HAS_RES, bool DO_AMAX>
__global__ void __launch_bounds__(256) tgemm_kernel(
    const float* __restrict__ A, const float* __restrict__ Bm, float* __restrict__ Cm,
    int Mn, int Nn, int Kn,
    const float* __restrict__ bias, const float* __restrict__ res, unsigned* amax)
{
    __shared__ uint32_t As[2][128][20]; // [m][k] pad 20 -> frag bank = (4m+k)&31 (bijective)
    __shared__ uint32_t Bs[2][16][68];  // [k][n] pad 68 -> frag bank = (4k+n)&31 (bijective)
    __shared__ float reds[8];

    int tid  = threadIdx.x;
    int lane = tid & 31;
    int warp = tid >> 5;
    int wm = warp & 3;      // 0..3
    int wn = warp >> 2;     // 0..1
    int nBase = blockIdx.x * 64;
    int mBase = blockIdx.y * 128;

    // global load indices
    const int aRow = tid >> 2;        // 0..63 (x2)
    const int aCol = (tid & 3) << 2;  // 0,4,8,12
    const int bRow = tid >> 4;        // 0..15
    const int bCol = (tid & 15) << 2; // 0..60

    float acc[2][4][4];
    #pragma unroll
    for (int i = 0; i < 2; i++)
        #pragma unroll
        for (int j = 0; j < 4; j++)
            #pragma unroll
            for (int l = 0; l < 4; l++) acc[i][j][l] = 0.f;

    float4 ra[2], rb;
    // prefetch tile 0
    #pragma unroll
    for (int i = 0; i < 2; i++) {
        int gr = mBase + aRow + i * 64;
        ra[i] = (gr < Mn) ? *(const float4*)(A + (size_t)gr * Kn + aCol)
                          : make_float4(0.f,0.f,0.f,0.f);
    }
    rb = *(const float4*)(Bm + (size_t)bRow * Nn + (nBase + bCol));
    #pragma unroll
    for (int i = 0; i < 2; i++) {
        uint32_t* p = &As[0][aRow + i * 64][aCol];
        p[0] = f2tf32(ra[i].x); p[1] = f2tf32(ra[i].y);
        p[2] = f2tf32(ra[i].z); p[3] = f2tf32(ra[i].w);
    }
    {
        uint32_t* p = &Bs[0][bRow][bCol];
        p[0] = f2tf32(rb.x); p[1] = f2tf32(rb.y);
        p[2] = f2tf32(rb.z); p[3] = f2tf32(rb.w);
    }
    __syncthreads();

    int KT = Kn >> 4;
    int lr = lane >> 2;   // 0..7
    int lc = lane & 3;    // 0..3
    for (int kt = 0; kt < KT; ++kt) {
        int buf = kt & 1;
        if (kt + 1 < KT) {
            int k0 = (kt + 1) << 4;
            #pragma unroll
            for (int i = 0; i < 2; i++) {
                int gr = mBase + aRow + i * 64;
                ra[i] = (gr < Mn) ? *(const float4*)(A + (size_t)gr * Kn + (k0 + aCol))
                                  : make_float4(0.f,0.f,0.f,0.f);
            }
            rb = *(const float4*)(Bm + (size_t)(k0 + bRow) * Nn + (nBase + bCol));
        }
        #pragma unroll
        for (int ks = 0; ks < 2; ks++) {
            uint32_t af[2][4], bf[4][2];
            #pragma unroll
            for (int mt = 0; mt < 2; mt++) {
                int r0 = wm * 32 + mt * 16 + lr;
                int c  = ks * 8 + lc;
                af[mt][0] = As[buf][r0][c];
                af[mt][1] = As[buf][r0 + 8][c];
                af[mt][2] = As[buf][r0][c + 4];
                af[mt][3] = As[buf][r0 + 8][c + 4];
            }
            #pragma unroll
            for (int nt = 0; nt < 4; nt++) {
                int col = wn * 32 + nt * 8 + lr;
                bf[nt][0] = Bs[buf][ks * 8 + lc][col];
                bf[nt][1] = Bs[buf][ks * 8 + lc + 4][col];
            }
            #pragma unroll
            for (int mt = 0; mt < 2; mt++)
                #pragma unroll
                for (int nt = 0; nt < 4; nt++)
                    mma_tf32(acc[mt][nt], af[mt], bf[nt]);
        }
        if (kt + 1 < KT) {
            int nb = buf ^ 1;
            #pragma unroll
            for (int i = 0; i < 2; i++) {
                uint32_t* p = &As[nb][aRow + i * 64][aCol];
                p[0] = f2tf32(ra[i].x); p[1] = f2tf32(ra[i].y);
                p[2] = f2tf32(ra[i].z); p[3] = f2tf32(ra[i].w);
            }
            uint32_t* p = &Bs[nb][bRow][bCol];
            p[0] = f2tf32(rb.x); p[1] = f2tf32(rb.y);
            p[2] = f2tf32(rb.z); p[3] = f2tf32(rb.w);
            __syncthreads();
        }
    }

    // epilogue: acc layout c0:(r,c) c1:(r,c+1) c2:(r+8,c) c3:(r+8,c+1)
    float amx = 0.f;
    #pragma unroll
    for (int mt = 0; mt < 2; mt++) {
        #pragma unroll
        for (int nt = 0; nt < 4; nt++) {
            int row0 = mBase + wm * 32 + mt * 16 + lr;
            int col0 = nBase + wn * 32 + nt * 8 + lc * 2;
            #pragma unroll
            for (int half = 0; half < 2; half++) {
                int row = row0 + half * 8;
                if (row < Mn) {
                    float c0 = acc[mt][nt][half * 2 + 0];
                    float c1 = acc[mt][nt][half * 2 + 1];
                    if (HAS_BIAS) { c0 += bias[col0]; c1 += bias[col0 + 1]; }
                    if (HAS_RES)  {
                        c0 += res[(size_t)row * Nn + col0];
                        c1 += res[(size_t)row * Nn + col0 + 1];
                    }
                    float2 o = {c0, c1};
                    *(float2*)(Cm + (size_t)row * Nn + col0) = o;
                    if (DO_AMAX) amx = fmaxf(amx, fmaxf(fabsf(c0), fabsf(c1)));
                }
            }
        }
    }
    if (DO_AMAX) {
        #pragma unroll
        for (int o = 16; o; o >>= 1) amx = fmaxf(amx, __shfl_xor_sync(0xffffffffu, amx, o));
        if (lane == 0) reds[warp] = amx;
        __syncthreads();
        if (tid == 0) {
            float m = reds[0];
            #pragma unroll
            for (int w = 1; w < 8; w++) m = fmaxf(m, reds[w]);
            atomicMax(amax, __float_as_uint(m));
        }
    }
}

// ---------------- per-tensor symmetric fake-quant in place ----------------
__global__ void quant_sym_kernel(float* __restrict__ x, long long n4,
                                 const unsigned* __restrict__ amaxbits)
{
    float delta = fmaxf(__uint_as_float(*amaxbits), 1e-8f) / 127.0f;
    long long stride = (long long)gridDim.x * blockDim.x;
    for (long long i = (long long)blockIdx.x * blockDim.x + threadIdx.x; i < n4; i += stride) {
        float4 v = *(float4*)(x + i * 4);
        float l;
        l = rintf(v.x/delta); l = fminf(fmaxf(l,-128.f),127.f); v.x = l*delta;
        l = rintf(v.y/delta); l = fminf(fmaxf(l,-128.f),127.f); v.y = l*delta;
        l = rintf(v.z/delta); l = fminf(fmaxf(l,-128.f),127.f); v.z = l*delta;
        l = rintf(v.w/delta); l = fminf(fmaxf(l,-128.f),127.f); v.w = l*delta;
        *(float4*)(x + i * 4) = v;
    }
}

// ---------------- self-attn scores S = QK^T / 8 ----------------
__global__ void __launch_bounds__(256) self_scores_kernel(
    const float* __restrict__ q, const float* __restrict__ k, float* __restrict__ S)
{
    __shared__ __align__(16) float Qs[64][68];
    __shared__ __align__(16) float Ks[64][68];
    int tid = threadIdx.x;
    int bh = blockIdx.z, b = bh / NH, h = bh % NH;
    int n0 = blockIdx.x * 64, m0 = blockIdx.y * 64;
    #pragma unroll
    for (int it = 0; it < 4; ++it) {
        int r = (tid >> 4) + it * 16, c = (tid & 15) << 2;
        float4 qv = *(const float4*)(q + ((size_t)(b*NSEQ + n0 + r))*CDIM + h*DH + c);
        Qs[c+0][r]=qv.x; Qs[c+1][r]=qv.y; Qs[c+2][r]=qv.z; Qs[c+3][r]=qv.w;
        float4 kv = *(const float4*)(k + ((size_t)(b*NSEQ + m0 + r))*CDIM + h*DH + c);
        Ks[c+0][r]=kv.x; Ks[c+1][r]=kv.y; Ks[c+2][r]=kv.z; Ks[c+3][r]=kv.w;
    }
    __syncthreads();
    int tx = tid & 15, ty = tid >> 4;
    float acc[4][4];
    #pragma unroll
    for (int i = 0; i < 4; i++)
        #pragma unroll
        for (int j = 0; j < 4; j++) acc[i][j] = 0.f;
    #pragma unroll 8
    for (int d = 0; d < 64; ++d) {
        float4 q4 = *(const float4*)&Qs[d][ty*4];
        float4 k4 = *(const float4*)&Ks[d][tx*4];
        float qa[4]={q4.x,q4.y,q4.z,q4.w}, ka[4]={k4.x,k4.y,k4.z,k4.w};
        #pragma unroll
        for (int i = 0; i < 4; i++)
            #pragma unroll
            for (int j = 0; j < 4; j++) acc[i][j] = fmaf(qa[i], ka[j], acc[i][j]);
    }
    #pragma unroll
    for (int i = 0; i < 4; i++) {
        float4 o = {acc[i][0]*0.125f, acc[i][1]*0.125f, acc[i][2]*0.125f, acc[i][3]*0.125f};
        *(float4*)(S + ((size_t)bh*NSEQ + n0 + ty*4 + i)*NSEQ + m0 + tx*4) = o;
    }
}

// -------- softmax row stats; global max prob = max(1/Z) --------
__global__ void softmax_stats_kernel(const float* __restrict__ S, float* __restrict__ rowmax,
                                     float* __restrict__ rowz, unsigned* wmax, int cols, int stride)
{
    int row = blockIdx.x, tid = threadIdx.x;
    const float* s = S + (size_t)row * stride;
    __shared__ float red[8];
    float m = -3.4e38f;
    for (int i = tid; i < cols; i += 256) m = fmaxf(m, s[i]);
    #pragma unroll
    for (int o = 16; o; o >>= 1) m = fmaxf(m, __shfl_xor_sync(0xffffffffu, m, o));
    if ((tid & 31) == 0) red[tid >> 5] = m;
    __syncthreads();
    float mm = red[0];
    #pragma unroll
    for (int w = 1; w < 8; w++) mm = fmaxf(mm, red[w]);
    __syncthreads();
    float z = 0.f;
    for (int i = tid; i < cols; i += 256) z += expf(s[i] - mm);
    #pragma unroll
    for (int o = 16; o; o >>= 1) z += __shfl_xor_sync(0xffffffffu, z, o);
    if ((tid & 31) == 0) red[tid >> 5] = z;
    __syncthreads();
    if (tid == 0) {
        float zz = 0.f;
        #pragma unroll
        for (int w = 0; w < 8; w++) zz += red[w];
        rowmax[row] = mm; rowz[row] = zz;
        atomicMax(wmax, __float_as_uint(1.0f / zz));
    }
}

// -------- self-attn PV with fused fq_zero on probs --------
__global__ void __launch_bounds__(256) self_pv_kernel(
    const float* __restrict__ S, const float* __restrict__ v,
    const float* __restrict__ rowmax, const float* __restrict__ rowz,
    const unsigned* __restrict__ wmaxbits, float* __restrict__ O)
{
    __shared__ __align__(16) float Ws[64][68];
    __shared__ __align__(16) float Vs[64][68];
    int tid = threadIdx.x;
    int bh = blockIdx.z, b = bh / NH, h = bh % NH;
    int n0 = blockIdx.x * 64;
    int tx = tid & 15, ty = tid >> 4;
    float delta = fmaxf(__uint_as_float(*wmaxbits), 1e-8f) / 255.0f;
    float inv_delta = 1.0f / delta;
    float rm4[4], ri4[4];
    #pragma unroll
    for (int it = 0; it < 4; it++) {
        int r = (tid >> 4) + it * 16;
        rm4[it] = rowmax[(size_t)bh*NSEQ + n0 + r];
        ri4[it] = 1.0f / rowz[(size_t)bh*NSEQ + n0 + r];
    }
    float acc[4][4];
    #pragma unroll
    for (int i = 0; i < 4; i++)
        #pragma unroll
        for (int j = 0; j < 4; j++) acc[i][j] = 0.f;
    for (int mt = 0; mt < 16; ++mt) {
        int m0 = mt * 64;
        __syncthreads();
        #pragma unroll
        for (int it = 0; it < 4; ++it) {
            int r = (tid >> 4) + it * 16, c = (tid & 15) << 2;
            float4 sv = *(const float4*)(S + ((size_t)bh*NSEQ + n0 + r)*NSEQ + m0 + c);
            float rm = rm4[it], ri = ri4[it], p, l;
            p = expf(sv.x-rm); l = rintf(p*ri*inv_delta); l = fminf(fmaxf(l,0.f),255.f); Ws[c+0][r] = l*delta;
            p = expf(sv.y-rm); l = rintf(p*ri*inv_delta); l = fminf(fmaxf(l,0.f),255.f); Ws[c+1][r] = l*delta;
            p = expf(sv.z-rm); l = rintf(p*ri*inv_delta); l = fminf(fmaxf(l,0.f),255.f); Ws[c+2][r] = l*delta;
            p = expf(sv.w-rm); l = rintf(p*ri*inv_delta); l = fminf(fmaxf(l,0.f),255.f); Ws[c+3][r] = l*delta;
            *(float4*)&Vs[r][c] = *(const float4*)(v + ((size_t)(b*NSEQ + m0 + r))*CDIM + h*DH + c);
        }
        __syncthreads();
        #pragma unroll 8
        for (int m = 0; m < 64; m++) {
            float4 w4 = *(const float4*)&Ws[m][ty*4];
            float4 v4 = *(const float4*)&Vs[m][tx*4];
            float wa[4]={w4.x,w4.y,w4.z,w4.w}, va[4]={v4.x,v4.y,v4.z,v4.w};
            #pragma unroll
            for (int i = 0; i < 4; i++)
                #pragma unroll
                for (int j = 0; j < 4; j++) acc[i][j] = fmaf(wa[i], va[j], acc[i][j]);
        }
    }
    #pragma unroll
    for (int i = 0; i < 4; i++) {
        float4 o = {acc[i][0], acc[i][1], acc[i][2], acc[i][3]};
        *(float4*)(O + ((size_t)(b*NSEQ + n0 + ty*4 + i))*CDIM + h*DH + tx*4) = o;
    }
}

// -------- cross-attn scores (M=77, stride 80) --------
__global__ void __launch_bounds__(256) cross_scores_kernel(
    const float* __restrict__ q, const float* __restrict__ k, float* __restrict__ S)
{
    __shared__ __align__(16) float Qs[64][68];
    __shared__ __align__(16) float Ks[80][68];
    int tid = threadIdx.x;
    int bh = blockIdx.y, b = bh / NH, h = bh % NH;
    int n0 = blockIdx.x * 64;
    #pragma unroll
    for (int it = 0; it < 4; ++it) {
        int r = (tid >> 4) + it * 16, c = (tid & 15) << 2;
        float4 qv = *(const float4*)(q + ((size_t)(b*NSEQ + n0 + r))*CDIM + h*DH + c);
        Qs[c+0][r]=qv.x; Qs[c+1][r]=qv.y; Qs[c+2][r]=qv.z; Qs[c+3][r]=qv.w;
    }
    #pragma unroll
    for (int it = 0; it < 5; ++it) {
        int lin = tid + it * 256;
        if (lin < 80 * 16) {
            int r = lin >> 4, c = (lin & 15) << 2;
            float4 kv = (r < MCTX) ? *(const float4*)(k + ((size_t)(b*MCTX + r))*CDIM + h*DH + c)
                                   : make_float4(0.f,0.f,0.f,0.f);
            *(float4*)&Ks[r][c] = kv;
        }
    }
    __syncthreads();
    int tx = tid & 15, ty = tid >> 4;
    float acc[4][5];
    #pragma unroll
    for (int i = 0; i < 4; i++)
        #pragma unroll
        for (int j = 0; j < 5; j++) acc[i][j] = 0.f;
    #pragma unroll 4
    for (int d = 0; d < 64; ++d) {
        float4 q4 = *(const float4*)&Qs[d][ty*4];
        float qa[4]={q4.x,q4.y,q4.z,q4.w};
        #pragma unroll
        for (int jj = 0; jj < 5; jj++) {
            float kv = Ks[tx*5+jj][d];
            #pragma unroll
            for (int i = 0; i < 4; i++) acc[i][jj] = fmaf(qa[i], kv, acc[i][jj]);
        }
    }
    #pragma unroll
    for (int i = 0; i < 4; i++)
        #pragma unroll
        for (int jj = 0; jj < 5; jj++) {
            int m = tx * 5 + jj;
            if (m < MCTX)
                S[((size_t)bh*NSEQ + n0 + ty*4 + i)*80 + m] = acc[i][jj] * 0.125f;
        }
}

// -------- cross-attn PV with fused fq_zero --------
__global__ void __launch_bounds__(256) cross_pv_kernel(
    const float* __restrict__ S, const float* __restrict__ v,
    const float* __restrict__ rowmax, const float* __restrict__ rowz,
    const unsigned* __restrict__ wmaxbits, float* __restrict__ O)
{
    __shared__ __align__(16) float Ws[80][68];
    __shared__ __align__(16) float Vs[80][68];
    int tid = threadIdx.x;
    int bh = blockIdx.y, b = bh / NH, h = bh % NH;
    int n0 = blockIdx.x * 64;
    int tx = tid & 15, ty = tid >> 4;
    float delta = fmaxf(__uint_as_float(*wmaxbits), 1e-8f) / 255.0f;
    float inv_delta = 1.0f / delta;
    #pragma unroll
    for (int it = 0; it < 5; ++it) {
        int lin = tid + it * 256;
        if (lin < MCTX * 16) {
            int r = lin >> 4, c = (lin & 15) << 2;
            *(float4*)&Vs[r][c] = *(const float4*)(v + ((size_t)(b*MCTX + r))*CDIM + h*DH + c);
        }
    }
    #pragma unroll
    for (int it = 0; it < 4; ++it) {
        int r = (tid >> 4) + it * 16;
        float rm = rowmax[(size_t)bh*NSEQ + n0 + r];
        float ri = 1.0f / rowz[(size_t)bh*NSEQ + n0 + r];
        #pragma unroll
        for (int jj = 0; jj < 5; jj++) {
            int m = (tid & 15) * 5 + jj;
            float w = 0.f;
            if (m < MCTX) {
                float s = S[((size_t)bh*NSEQ + n0 + r)*80 + m];
                float p = expf(s - rm);
                float l = rintf(p * ri * inv_delta);
                l = fminf(fmaxf(l, 0.f), 255.f);
                w = l * delta;
            }
            Ws[m][r] = w;
        }
    }
    __syncthreads();
    float acc[4][4];
    #pragma unroll
    for (int i = 0; i < 4; i++)
        #pragma unroll
        for (int j = 0; j < 4; j++) acc[i][j] = 0.f;
    for (int m = 0; m < MCTX; m++) {
        float4 w4 = *(const float4*)&Ws[m][ty*4];
        float4 v4 = *(const float4*)&Vs[m][tx*4];
        float wa[4]={w4.x,w4.y,w4.z,w4.w}, va[4]={v4.x,v4.y,v4.z,v4.w};
        #pragma unroll
        for (int i = 0; i < 4; i++)
            #pragma unroll
            for (int j = 0; j < 4; j++) acc[i][j] = fmaf(wa[i], va[j], acc[i][j]);
    }
    #pragma unroll
    for (int i = 0; i < 4; i++) {
        float4 o = {acc[i][0], acc[i][1], acc[i][2], acc[i][3]};
        *(float4*)(O + ((size_t)(b*NSEQ + n0 + ty*4 + i))*CDIM + h*DH + tx*4) = o;
    }
}

// -------- GEGLU: G = a * gelu(g) --------
__global__ void geglu_kernel(const float* __restrict__ Hh, float* __restrict__ G)
{
    size_t n4 = (size_t)ROWS * FFD / 4;
    size_t stride = (size_t)gridDim.x * blockDim.x;
    for (size_t i = (size_t)blockIdx.x * blockDim.x + threadIdx.x; i < n4; i += stride) {
        size_t col4 = i % (FFD / 4), row = i / (FFD / 4);
        float4 a4 = *(const float4*)(Hh + row * FF2D + col4 * 4);
        float4 g4 = *(const float4*)(Hh + row * FF2D + FFD + col4 * 4);
        float4 o;
        o.x = a4.x * gelu_tanh(g4.x); o.y = a4.y * gelu_tanh(g4.y);
        o.z = a4.z * gelu_tanh(g4.z); o.w = a4.w * gelu_tanh(g4.w);
        *(float4*)(G + i * 4) = o;
    }
}

extern "C" void kernel_launch(void* const* d_in, const int* in_sizes, int n_in,
                              void* d_out, int out_size)
{
    const float* x    = (const float*)d_in[0];
    const float* ctx  = (const float*)d_in[1];
    const float* ln1g = (const float*)d_in[2];
    const float* ln1b = (const float*)d_in[3];
    const float* ln2g = (const float*)d_in[4];
    const float* ln2b = (const float*)d_in[5];
    const float* ln3g = (const float*)d_in[6];
    const float* ln3b = (const float*)d_in[7];
    const float* Wq1  = (const float*)d_in[8];
    const float* Wk1  = (const float*)d_in[9];
    const float* Wv1  = (const float*)d_in[10];
    const float* Wo1  = (const float*)d_in[11];
    const float* bo1  = (const float*)d_in[12];
    const float* Wq2  = (const float*)d_in[13];
    const float* Wk2  = (const float*)d_in[14];
    const float* Wv2  = (const float*)d_in[15];
    const float* Wo2  = (const float*)d_in[16];
    const float* bo2  = (const float*)d_in[17];
    const float* Wff1 = (const float*)d_in[18];
    const float* bff1 = (const float*)d_in[19];
    const float* Wff2 = (const float*)d_in[20];
    const float* bff2 = (const float*)d_in[21];
    float* out = (float*)d_out;

    float* sc = nullptr;
    cudaGetSymbolAddress((void**)&sc, g_scratch);
    float* XN = sc + OFF_XN;  float* Q  = sc + OFF_Q;
    float* K  = sc + OFF_K;   float* V  = sc + OFF_V;
    float* O  = sc + OFF_O;   float* X1 = sc + OFF_X1;
    float* S  = sc + OFF_S;   float* Hb = sc + OFF_H;
    float* G  = sc + OFF_G;   float* RM = sc + OFF_RM;
    float* RZ = sc + OFF_RZ;
    unsigned* AM = (unsigned*)(sc + OFF_AM);

    dim3 g1280(CDIM / 64, ROWS / 128);                 // (20, 64)
    dim3 gcross(CDIM / 64, (CROSSROWS + 127) / 128);   // (20, 5)
    dim3 gff1(FF2D / 64, ROWS / 128);                  // (160, 64)
    long long n4  = (long long)ROWS * CDIM / 4;
    long long n4c = (long long)CROSSROWS * CDIM / 4;

    init_amax_kernel<<<1, 32>>>(AM);

    // ---- block 1: self attention ----
    ln_kernel<<<ROWS, 256>>>(x, ln1g, ln1b, XN);
    tgemm_kernel<false,false,true><<<g1280,256>>>(XN, Wq1, Q, ROWS, CDIM, CDIM, nullptr, nullptr, AM+0);
    tgemm_kernel<false,false,true><<<g1280,256>>>(XN, Wk1, K, ROWS, CDIM, CDIM, nullptr, nullptr, AM+1);
    tgemm_kernel<false,false,true><<<g1280,256>>>(XN, Wv1, V, ROWS, CDIM, CDIM, nullptr, nullptr, AM+2);
    quant_sym_kernel<<<2048,256>>>(Q, n4, AM+0);
    quant_sym_kernel<<<2048,256>>>(K, n4, AM+1);
    quant_sym_kernel<<<2048,256>>>(V, n4, AM+2);
    self_scores_kernel<<<dim3(16,16,BHD),256>>>(Q, K, S);
    softmax_stats_kernel<<<BHD*NSEQ,256>>>(S, RM, RZ, AM+3, NSEQ, NSEQ);
    self_pv_kernel<<<dim3(16,1,BHD),256>>>(S, V, RM, RZ, AM+3, O);
    tgemm_kernel<true,true,false><<<g1280,256>>>(O, Wo1, X1, ROWS, CDIM, CDIM, bo1, x, nullptr);

    // ---- block 2: cross attention ----
    ln_kernel<<<ROWS,256>>>(X1, ln2g, ln2b, XN);
    tgemm_kernel<false,false,true><<<g1280,256>>>(XN, Wq2, Q, ROWS, CDIM, CDIM, nullptr, nullptr, AM+4);
    tgemm_kernel<false,false,true><<<gcross,256>>>(ctx, Wk2, K, CROSSROWS, CDIM, CTXC, nullptr, nullptr, AM+5);
    tgemm_kernel<false,false,true><<<gcross,256>>>(ctx, Wv2, V, CROSSROWS, CDIM, CTXC, nullptr, nullptr, AM+6);
    quant_sym_kernel<<<2048,256>>>(Q, n4, AM+4);
    quant_sym_kernel<<<512,256>>>(K, n4c, AM+5);
    quant_sym_kernel<<<512,256>>>(V, n4c, AM+6);
    cross_scores_kernel<<<dim3(16,BHD),256>>>(Q, K, S);
    softmax_stats_kernel<<<BHD*NSEQ,256>>>(S, RM, RZ, AM+7, MCTX, 80);
    cross_pv_kernel<<<dim3(16,BHD),256>>>(S, V, RM, RZ, AM+7, O);
    tgemm_kernel<true,true,false><<<g1280,256>>>(O, Wo2, X1, ROWS, CDIM, CDIM, bo2, X1, nullptr);

    // ---- block 3: GEGLU FF ----
    ln_kernel<<<ROWS,256>>>(X1, ln3g, ln3b, XN);
    tgemm_kernel<true,false,false><<<gff1,256>>>(XN, Wff1, Hb, ROWS, FF2D, CDIM, bff1, nullptr, nullptr);
    geglu_kernel<<<4096,256>>>(Hb, G);
    tgemm_kernel<true,true,false><<<g1280,256>>>(G, Wff2, out, ROWS, CDIM, FFD, bff2, X1, nullptr);
}

// round 4
// speedup vs baseline: 1.9034x; 1.0663x over previous
#include <cuda_runtime.h>
#include <cstdint>

#define NB 8
#define NSEQ 1024
#define CDIM 1280
#define NH 20
#define DH 64
#define MCTX 77
#define CTXC 768
#define FFD 5120
#define FF2D 10240
#define ROWS (NB*NSEQ)
#define BHD (NB*NH)
#define CROSSROWS (NB*MCTX)

static constexpr size_t SZ_XC = (size_t)ROWS * CDIM;
static constexpr size_t OFF_XN = 0;
static constexpr size_t OFF_Q  = OFF_XN + SZ_XC;
static constexpr size_t OFF_K  = OFF_Q + SZ_XC;
static constexpr size_t OFF_V  = OFF_K + SZ_XC;
static constexpr size_t OFF_O  = OFF_V + SZ_XC;
static constexpr size_t OFF_X1 = OFF_O + SZ_XC;
static constexpr size_t OFF_S  = OFF_X1 + SZ_XC;
static constexpr size_t SZ_S   = (size_t)BHD * NSEQ * NSEQ;
static constexpr size_t OFF_H  = OFF_S + SZ_S;
static constexpr size_t SZ_H   = (size_t)ROWS * FF2D;
static constexpr size_t OFF_G  = OFF_H + SZ_H;
static constexpr size_t SZ_G   = (size_t)ROWS * FFD;
static constexpr size_t OFF_RM = OFF_G + SZ_G;
static constexpr size_t OFF_RZ = OFF_RM + (size_t)BHD * NSEQ;
static constexpr size_t OFF_AM = OFF_RZ + (size_t)BHD * NSEQ;
static constexpr size_t TOTAL_SCRATCH = OFF_AM + 8;

__device__ float g_scratch[TOTAL_SCRATCH];

__global__ void init_amax_kernel(unsigned* amax) {
    if (threadIdx.x < 8) amax[threadIdx.x] = 0u;
}

__device__ __forceinline__ float gelu_tanh(float x) {
    float x3 = x * x * x;
    return 0.5f * x * (1.0f + tanhf(0.7978845608028654f * (x + 0.044715f * x3)));
}

__device__ __forceinline__ uint32_t f2tf32(float f) {
    uint32_t r;
    asm("cvt.rna.tf32.f32 %0, %1;" : "=r"(r) : "f"(f));
    return r;
}

__device__ __forceinline__ void mma_tf32(float* d, const uint32_t* a, const uint32_t* b) {
    asm volatile("mma.sync.aligned.m16n8k8.row.col.f32.tf32.tf32.f32 "
        "{%0,%1,%2,%3}, {%4,%5,%6,%7}, {%8,%9}, {%0,%1,%2,%3};"
        : "+f"(d[0]), "+f"(d[1]), "+f"(d[2]), "+f"(d[3])
        : "r"(a[0]), "r"(a[1]), "r"(a[2]), "r"(a[3]), "r"(b[0]), "r"(b[1]));
}

__device__ __forceinline__ void ldsm4(uint32_t& r0, uint32_t& r1, uint32_t& r2, uint32_t& r3,
                                      uint32_t addr) {
    asm volatile("ldmatrix.sync.aligned.m8n8.x4.shared.b16 {%0,%1,%2,%3}, [%4];"
        : "=r"(r0), "=r"(r1), "=r"(r2), "=r"(r3) : "r"(addr));
}

// ---------------- LayerNorm: one block per row ----------------
__global__ void ln_kernel(const float* __restrict__ x, const float* __restrict__ g,
                          const float* __restrict__ bta, float* __restrict__ out)
{
    __shared__ float sx[CDIM];
    __shared__ float red[8];
    int row = blockIdx.x, tid = threadIdx.x;
    const float* xr = x + (size_t)row * CDIM;
    float s = 0.f;
    for (int i = tid; i < CDIM; i += 256) { float v = xr[i]; sx[i] = v; s += v; }
    #pragma unroll
    for (int o = 16; o; o >>= 1) s += __shfl_xor_sync(0xffffffffu, s, o);
    if ((tid & 31) == 0) red[tid >> 5] = s;
    __syncthreads();
    float tot = 0.f;
    #pragma unroll
    for (int w = 0; w < 8; w++) tot += red[w];
    float mean = tot * (1.0f / (float)CDIM);
    float vs = 0.f;
    for (int i = tid; i < CDIM; i += 256) { float d = sx[i] - mean; vs += d * d; }
    __syncthreads();
    #pragma unroll
    for (int o = 16; o; o >>= 1) vs += __shfl_xor_sync(0xffffffffu, vs, o);
    if ((tid & 31) == 0) red[tid >> 5] = vs;
    __syncthreads();
    float tot2 = 0.f;
    #pragma unroll
    for (int w = 0; w < 8; w++) tot2 += red[w];
    float rstd = rsqrtf(tot2 * (1.0f / (float)CDIM) + 1e-5f);
    for (int i = tid; i < CDIM; i += 256)
        out[(size_t)row * CDIM + i] = (sx[i] - mean) * rstd * g[i] + bta[i];
}

// ============ TF32 tensor-core GEMM, ldmatrix fragment path ============
// block tile 128(M) x 128(N), K-tile 16, double buffered.
// 8 warps: wm = warp&1 (2 M groups of 64), wn = warp>>1 (4 N groups of 32).
// warp tile 64x32 -> 4 mtiles(m16) x 4 ntiles(n8) x 2 ksteps(k8).
// SMEM: As[m][k16] (row = 16 tf32 + pad4), Bs[n][k16] (transposed, same pad).
// pad to 20 words/row => ldmatrix 8-row windows hit disjoint bank quads.
template<bool HAS_BIAS, bool HAS_RES, bool DO_AMAX>
__global__ void __launch_bounds__(256, 2) tgemm_kernel(
    const float* __restrict__ A, const float* __restrict__ Bm, float* __restrict__ Cm,
    int Mn, int Nn, int Kn,
    const float* __restrict__ bias, const float* __restrict__ res, unsigned* amax)
{
    __shared__ __align__(16) uint32_t As[2][128][20];
    __shared__ __align__(16) uint32_t Bs[2][128][20];
    __shared__ float reds[8];
    constexpr uint32_t BUFB = 128 * 20 * 4;

    int tid  = threadIdx.x;
    int lane = tid & 31;
    int warp = tid >> 5;
    int wm = warp & 1;     // 0..1 -> 64 rows each
    int wn = warp >> 1;    // 0..3 -> 32 cols each
    int nBase = blockIdx.x * 128;
    int mBase = blockIdx.y * 128;

    // global A loader: 2 rows x float4 along K
    const int aRow = tid >> 2;        // 0..63 (+64)
    const int aCol = (tid & 3) << 2;  // 0,4,8,12
    // global B loader: [K][N] row-major; scatter-transpose into Bs[n][k]
    const int bRow = tid >> 4;        // k 0..15
    const int bCol = (tid & 15) << 2; // n 0..60 (+64)

    uint32_t asmb = (uint32_t)__cvta_generic_to_shared(&As[0][0][0]);
    uint32_t bsmb = (uint32_t)__cvta_generic_to_shared(&Bs[0][0][0]);
    int r8 = lane & 7, sel = lane >> 3;
    // A ldmatrix lane address: matrix0 rows m0..m0+7 (words k..k+3), m1: +8 rows,
    // m2: words +4, m3: +8 rows & words +4
    uint32_t aoff = asmb + (((wm * 64 + r8 + ((sel & 1) << 3)) * 20 + ((sel >> 1) << 2)) << 2);
    // B ldmatrix lane address: matrix i = ntile i (8 n-rows), words k..k+3
    uint32_t boff = bsmb + (((wn * 32 + (sel << 3) + r8) * 20) << 2);

    float acc[4][4][4];
    #pragma unroll
    for (int i = 0; i < 4; i++)
        #pragma unroll
        for (int j = 0; j < 4; j++)
            #pragma unroll
            for (int l = 0; l < 4; l++) acc[i][j][l] = 0.f;

    float4 ra[2], rb[2];
    // ---- prefetch ktile 0 ----
    #pragma unroll
    for (int i = 0; i < 2; i++) {
        int gr = mBase + aRow + i * 64;
        ra[i] = (gr < Mn) ? *(const float4*)(A + (size_t)gr * Kn + aCol)
                          : make_float4(0.f, 0.f, 0.f, 0.f);
        rb[i] = *(const float4*)(Bm + (size_t)bRow * Nn + (nBase + bCol + i * 64));
    }
    #pragma unroll
    for (int i = 0; i < 2; i++) {
        uint4 av = {f2tf32(ra[i].x), f2tf32(ra[i].y), f2tf32(ra[i].z), f2tf32(ra[i].w)};
        *(uint4*)&As[0][aRow + i * 64][aCol] = av;
        int nb0 = bCol + i * 64;
        Bs[0][nb0 + 0][bRow] = f2tf32(rb[i].x);
        Bs[0][nb0 + 1][bRow] = f2tf32(rb[i].y);
        Bs[0][nb0 + 2][bRow] = f2tf32(rb[i].z);
        Bs[0][nb0 + 3][bRow] = f2tf32(rb[i].w);
    }
    __syncthreads();

    int KT = Kn >> 4;
    int lr = lane >> 2, lc = lane & 3;
    for (int kt = 0; kt < KT; ++kt) {
        int buf = kt & 1;
        uint32_t abuf = aoff + buf * BUFB;
        uint32_t bbuf = boff + buf * BUFB;
        if (kt + 1 < KT) {
            int k0 = (kt + 1) << 4;
            #pragma unroll
            for (int i = 0; i < 2; i++) {
                int gr = mBase + aRow + i * 64;
                ra[i] = (gr < Mn) ? *(const float4*)(A + (size_t)gr * Kn + (k0 + aCol))
                                  : make_float4(0.f, 0.f, 0.f, 0.f);
                rb[i] = *(const float4*)(Bm + (size_t)(k0 + bRow) * Nn + (nBase + bCol + i * 64));
            }
        }
        #pragma unroll
        for (int ks = 0; ks < 2; ks++) {
            uint32_t af[4][4], b0[4], b1[4];
            #pragma unroll
            for (int mt = 0; mt < 4; mt++)
                ldsm4(af[mt][0], af[mt][1], af[mt][2], af[mt][3],
                      abuf + mt * (16 * 20 * 4) + ks * 32);
            ldsm4(b0[0], b0[1], b0[2], b0[3], bbuf + ks * 32);
            ldsm4(b1[0], b1[1], b1[2], b1[3], bbuf + ks * 32 + 16);
            #pragma unroll
            for (int mt = 0; mt < 4; mt++)
                #pragma unroll
                for (int nt = 0; nt < 4; nt++) {
                    uint32_t bb[2] = {b0[nt], b1[nt]};
                    mma_tf32(acc[mt][nt], af[mt], bb);
                }
        }
        if (kt + 1 < KT) {
            int nb = buf ^ 1;
            #pragma unroll
            for (int i = 0; i < 2; i++) {
                uint4 av = {f2tf32(ra[i].x), f2tf32(ra[i].y), f2tf32(ra[i].z), f2tf32(ra[i].w)};
                *(uint4*)&As[nb][aRow + i * 64][aCol] = av;
                int nb0 = bCol + i * 64;
                Bs[nb][nb0 + 0][bRow] = f2tf32(rb[i].x);
                Bs[nb][nb0 + 1][bRow] = f2tf32(rb[i].y);
                Bs[nb][nb0 + 2][bRow] = f2tf32(rb[i].z);
                Bs[nb][nb0 + 3][bRow] = f2tf32(rb[i].w);
            }
            __syncthreads();
        }
    }

    // epilogue: acc c0:(r,c) c1:(r,c+1) c2:(r+8,c) c3:(r+8,c+1)
    float amx = 0.f;
    #pragma unroll
    for (int mt = 0; mt < 4; mt++) {
        #pragma unroll
        for (int nt = 0; nt < 4; nt++) {
            int row0 = mBase + wm * 64 + mt * 16 + lr;
            int col0 = nBase + wn * 32 + nt * 8 + lc * 2;
            #pragma unroll
            for (int half = 0; half < 2; half++) {
                int row = row0 + half * 8;
                if (row < Mn) {
                    float c0 = acc[mt][nt][half * 2 + 0];
                    float c1 = acc[mt][nt][half * 2 + 1];
                    if (HAS_BIAS) { c0 += bias[col0]; c1 += bias[col0 + 1]; }
                    if (HAS_RES) {
                        c0 += res[(size_t)row * Nn + col0];
                        c1 += res[(size_t)row * Nn + col0 + 1];
                    }
                    float2 o = {c0, c1};
                    *(float2*)(Cm + (size_t)row * Nn + col0) = o;
                    if (DO_AMAX) amx = fmaxf(amx, fmaxf(fabsf(c0), fabsf(c1)));
                }
            }
        }
    }
    if (DO_AMAX) {
        #pragma unroll
        for (int o = 16; o; o >>= 1) amx = fmaxf(amx, __shfl_xor_sync(0xffffffffu, amx, o));
        if (lane == 0) reds[warp] = amx;
        __syncthreads();
        if (tid == 0) {
            float m = reds[0];
            #pragma unroll
            for (int w = 1; w < 8; w++) m = fmaxf(m, reds[w]);
            atomicMax(amax, __float_as_uint(m));
        }
    }
}

// ---------------- per-tensor symmetric fake-quant in place ----------------
__global__ void quant_sym_kernel(float* __restrict__ x, long long n4,
                                 const unsigned* __restrict__ amaxbits)
{
    float delta = fmaxf(__uint_as_float(*amaxbits), 1e-8f) / 127.0f;
    long long stride = (long long)gridDim.x * blockDim.x;
    for (long long i = (long long)blockIdx.x * blockDim.x + threadIdx.x; i < n4; i += stride) {
        float4 v = *(float4*)(x + i * 4);
        float l;
        l = rintf(v.x/delta); l = fminf(fmaxf(l,-128.f),127.f); v.x = l*delta;
        l = rintf(v.y/delta); l = fminf(fmaxf(l,-128.f),127.f); v.y = l*delta;
        l = rintf(v.z/delta); l = fminf(fmaxf(l,-128.f),127.f); v.z = l*delta;
        l = rintf(v.w/delta); l = fminf(fmaxf(l,-128.f),127.f); v.w = l*delta;
        *(float4*)(x + i * 4) = v;
    }
}

// ---------------- self-attn scores S = QK^T / 8 ----------------
__global__ void __launch_bounds__(256) self_scores_kernel(
    const float* __restrict__ q, const float* __restrict__ k, float* __restrict__ S)
{
    __shared__ __align__(16) float Qs[64][68];
    __shared__ __align__(16) float Ks[64][68];
    int tid = threadIdx.x;
    int bh = blockIdx.z, b = bh / NH, h = bh % NH;
    int n0 = blockIdx.x * 64, m0 = blockIdx.y * 64;
    #pragma unroll
    for (int it = 0; it < 4; ++it) {
        int r = (tid >> 4) + it * 16, c = (tid & 15) << 2;
        float4 qv = *(const float4*)(q + ((size_t)(b*NSEQ + n0 + r))*CDIM + h*DH + c);
        Qs[c+0][r]=qv.x; Qs[c+1][r]=qv.y; Qs[c+2][r]=qv.z; Qs[c+3][r]=qv.w;
        float4 kv = *(const float4*)(k + ((size_t)(b*NSEQ + m0 + r))*CDIM + h*DH + c);
        Ks[c+0][r]=kv.x; Ks[c+1][r]=kv.y; Ks[c+2][r]=kv.z; Ks[c+3][r]=kv.w;
    }
    __syncthreads();
    int tx = tid & 15, ty = tid >> 4;
    float acc[4][4];
    #pragma unroll
    for (int i = 0; i < 4; i++)
        #pragma unroll
        for (int j = 0; j < 4; j++) acc[i][j] = 0.f;
    #pragma unroll 8
    for (int d = 0; d < 64; ++d) {
        float4 q4 = *(const float4*)&Qs[d][ty*4];
        float4 k4 = *(const float4*)&Ks[d][tx*4];
        float qa[4]={q4.x,q4.y,q4.z,q4.w}, ka[4]={k4.x,k4.y,k4.z,k4.w};
        #pragma unroll
        for (int i = 0; i < 4; i++)
            #pragma unroll
            for (int j = 0; j < 4; j++) acc[i][j] = fmaf(qa[i], ka[j], acc[i][j]);
    }
    #pragma unroll
    for (int i = 0; i < 4; i++) {
        float4 o = {acc[i][0]*0.125f, acc[i][1]*0.125f, acc[i][2]*0.125f, acc[i][3]*0.125f};
        *(float4*)(S + ((size_t)bh*NSEQ + n0 + ty*4 + i)*NSEQ + m0 + tx*4) = o;
    }
}

// -------- softmax row stats; global max prob = max(1/Z) --------
__global__ void softmax_stats_kernel(const float* __restrict__ S, float* __restrict__ rowmax,
                                     float* __restrict__ rowz, unsigned* wmax, int cols, int stride)
{
    int row = blockIdx.x, tid = threadIdx.x;
    const float* s = S + (size_t)row * stride;
    __shared__ float red[8];
    float m = -3.4e38f;
    for (int i = tid; i < cols; i += 256) m = fmaxf(m, s[i]);
    #pragma unroll
    for (int o = 16; o; o >>= 1) m = fmaxf(m, __shfl_xor_sync(0xffffffffu, m, o));
    if ((tid & 31) == 0) red[tid >> 5] = m;
    __syncthreads();
    float mm = red[0];
    #pragma unroll
    for (int w = 1; w < 8; w++) mm = fmaxf(mm, red[w]);
    __syncthreads();
    float z = 0.f;
    for (int i = tid; i < cols; i += 256) z += expf(s[i] - mm);
    #pragma unroll
    for (int o = 16; o; o >>= 1) z += __shfl_xor_sync(0xffffffffu, z, o);
    if ((tid & 31) == 0) red[tid >> 5] = z;
    __syncthreads();
    if (tid == 0) {
        float zz = 0.f;
        #pragma unroll
        for (int w = 0; w < 8; w++) zz += red[w];
        rowmax[row] = mm; rowz[row] = zz;
        atomicMax(wmax, __float_as_uint(1.0f / zz));
    }
}

// -------- self-attn PV with fused fq_zero on probs --------
__global__ void __launch_bounds__(256) self_pv_kernel(
    const float* __restrict__ S, const float* __restrict__ v,
    const float* __restrict__ rowmax, const float* __restrict__ rowz,
    const unsigned* __restrict__ wmaxbits, float* __restrict__ O)
{
    __shared__ __align__(16) float Ws[64][68];
    __shared__ __align__(16) float Vs[64][68];
    int tid = threadIdx.x;
    int bh = blockIdx.z, b = bh / NH, h = bh % NH;
    int n0 = blockIdx.x * 64;
    int tx = tid & 15, ty = tid >> 4;
    float delta = fmaxf(__uint_as_float(*wmaxbits), 1e-8f) / 255.0f;
    float inv_delta = 1.0f / delta;
    float rm4[4], ri4[4];
    #pragma unroll
    for (int it = 0; it < 4; it++) {
        int r = (tid >> 4) + it * 16;
        rm4[it] = rowmax[(size_t)bh*NSEQ + n0 + r];
        ri4[it] = 1.0f / rowz[(size_t)bh*NSEQ + n0 + r];
    }
    float acc[4][4];
    #pragma unroll
    for (int i = 0; i < 4; i++)
        #pragma unroll
        for (int j = 0; j < 4; j++) acc[i][j] = 0.f;
    for (int mt = 0; mt < 16; ++mt) {
        int m0 = mt * 64;
        __syncthreads();
        #pragma unroll
        for (int it = 0; it < 4; ++it) {
            int r = (tid >> 4) + it * 16, c = (tid & 15) << 2;
            float4 sv = *(const float4*)(S + ((size_t)bh*NSEQ + n0 + r)*NSEQ + m0 + c);
            float rm = rm4[it], ri = ri4[it], p, l;
            p = expf(sv.x-rm); l = rintf(p*ri*inv_delta); l = fminf(fmaxf(l,0.f),255.f); Ws[c+0][r] = l*delta;
            p = expf(sv.y-rm); l = rintf(p*ri*inv_delta); l = fminf(fmaxf(l,0.f),255.f); Ws[c+1][r] = l*delta;
            p = expf(sv.z-rm); l = rintf(p*ri*inv_delta); l = fminf(fmaxf(l,0.f),255.f); Ws[c+2][r] = l*delta;
            p = expf(sv.w-rm); l = rintf(p*ri*inv_delta); l = fminf(fmaxf(l,0.f),255.f); Ws[c+3][r] = l*delta;
            *(float4*)&Vs[r][c] = *(const float4*)(v + ((size_t)(b*NSEQ + m0 + r))*CDIM + h*DH + c);
        }
        __syncthreads();
        #pragma unroll 8
        for (int m = 0; m < 64; m++) {
            float4 w4 = *(const float4*)&Ws[m][ty*4];
            float4 v4 = *(const float4*)&Vs[m][tx*4];
            float wa[4]={w4.x,w4.y,w4.z,w4.w}, va[4]={v4.x,v4.y,v4.z,v4.w};
            #pragma unroll
            for (int i = 0; i < 4; i++)
                #pragma unroll
                for (int j = 0; j < 4; j++) acc[i][j] = fmaf(wa[i], va[j], acc[i][j]);
        }
    }
    #pragma unroll
    for (int i = 0; i < 4; i++) {
        float4 o = {acc[i][0], acc[i][1], acc[i][2], acc[i][3]};
        *(float4*)(O + ((size_t)(b*NSEQ + n0 + ty*4 + i))*CDIM + h*DH + tx*4) = o;
    }
}

// -------- cross-attn scores (M=77, stride 80) --------
__global__ void __launch_bounds__(256) cross_scores_kernel(
    const float* __restrict__ q, const float* __restrict__ k, float* __restrict__ S)
{
    __shared__ __align__(16) float Qs[64][68];
    __shared__ __align__(16) float Ks[80][68];
    int tid = threadIdx.x;
    int bh = blockIdx.y, b = bh / NH, h = bh % NH;
    int n0 = blockIdx.x * 64;
    #pragma unroll
    for (int it = 0; it < 4; ++it) {
        int r = (tid >> 4) + it * 16, c = (tid & 15) << 2;
        float4 qv = *(const float4*)(q + ((size_t)(b*NSEQ + n0 + r))*CDIM + h*DH + c);
        Qs[c+0][r]=qv.x; Qs[c+1][r]=qv.y; Qs[c+2][r]=qv.z; Qs[c+3][r]=qv.w;
    }
    #pragma unroll
    for (int it = 0; it < 5; ++it) {
        int lin = tid + it * 256;
        if (lin < 80 * 16) {
            int r = lin >> 4, c = (lin & 15) << 2;
            float4 kv = (r < MCTX) ? *(const float4*)(k + ((size_t)(b*MCTX + r))*CDIM + h*DH + c)
                                   : make_float4(0.f,0.f,0.f,0.f);
            *(float4*)&Ks[r][c] = kv;
        }
    }
    __syncthreads();
    int tx = tid & 15, ty = tid >> 4;
    float acc[4][5];
    #pragma unroll
    for (int i = 0; i < 4; i++)
        #pragma unroll
        for (int j = 0; j < 5; j++) acc[i][j] = 0.f;
    #pragma unroll 4
    for (int d = 0; d < 64; ++d) {
        float4 q4 = *(const float4*)&Qs[d][ty*4];
        float qa[4]={q4.x,q4.y,q4.z,q4.w};
        #pragma unroll
        for (int jj = 0; jj < 5; jj++) {
            float kv = Ks[tx*5+jj][d];
            #pragma unroll
            for (int i = 0; i < 4; i++) acc[i][jj] = fmaf(qa[i], kv, acc[i][jj]);
        }
    }
    #pragma unroll
    for (int i = 0; i < 4; i++)
        #pragma unroll
        for (int jj = 0; jj < 5; jj++) {
            int m = tx * 5 + jj;
            if (m < MCTX)
                S[((size_t)bh*NSEQ + n0 + ty*4 + i)*80 + m] = acc[i][jj] * 0.125f;
        }
}

// -------- cross-attn PV with fused fq_zero --------
__global__ void __launch_bounds__(256) cross_pv_kernel(
    const float* __restrict__ S, const float* __restrict__ v,
    const float* __restrict__ rowmax, const float* __restrict__ rowz,
    const unsigned* __restrict__ wmaxbits, float* __restrict__ O)
{
    __shared__ __align__(16) float Ws[80][68];
    __shared__ __align__(16) float Vs[80][68];
    int tid = threadIdx.x;
    int bh = blockIdx.y, b = bh / NH, h = bh % NH;
    int n0 = blockIdx.x * 64;
    int tx = tid & 15, ty = tid >> 4;
    float delta = fmaxf(__uint_as_float(*wmaxbits), 1e-8f) / 255.0f;
    float inv_delta = 1.0f / delta;
    #pragma unroll
    for (int it = 0; it < 5; ++it) {
        int lin = tid + it * 256;
        if (lin < MCTX * 16) {
            int r = lin >> 4, c = (lin & 15) << 2;
            *(float4*)&Vs[r][c] = *(const float4*)(v + ((size_t)(b*MCTX + r))*CDIM + h*DH + c);
        }
    }
    #pragma unroll
    for (int it = 0; it < 4; ++it) {
        int r = (tid >> 4) + it * 16;
        float rm = rowmax[(size_t)bh*NSEQ + n0 + r];
        float ri = 1.0f / rowz[(size_t)bh*NSEQ + n0 + r];
        #pragma unroll
        for (int jj = 0; jj < 5; jj++) {
            int m = (tid & 15) * 5 + jj;
            float w = 0.f;
            if (m < MCTX) {
                float s = S[((size_t)bh*NSEQ + n0 + r)*80 + m];
                float p = expf(s - rm);
                float l = rintf(p * ri * inv_delta);
                l = fminf(fmaxf(l, 0.f), 255.f);
                w = l * delta;
            }
            Ws[m][r] = w;
        }
    }
    __syncthreads();
    float acc[4][4];
    #pragma unroll
    for (int i = 0; i < 4; i++)
        #pragma unroll
        for (int j = 0; j < 4; j++) acc[i][j] = 0.f;
    for (int m = 0; m < MCTX; m++) {
        float4 w4 = *(const float4*)&Ws[m][ty*4];
        float4 v4 = *(const float4*)&Vs[m][tx*4];
        float wa[4]={w4.x,w4.y,w4.z,w4.w}, va[4]={v4.x,v4.y,v4.z,v4.w};
        #pragma unroll
        for (int i = 0; i < 4; i++)
            #pragma unroll
            for (int j = 0; j < 4; j++) acc[i][j] = fmaf(wa[i], va[j], acc[i][j]);
    }
    #pragma unroll
    for (int i = 0; i < 4; i++) {
        float4 o = {acc[i][0], acc[i][1], acc[i][2], acc[i][3]};
        *(float4*)(O + ((size_t)(b*NSEQ + n0 + ty*4 + i))*CDIM + h*DH + tx*4) = o;
    }
}

// -------- GEGLU: G = a * gelu(g) --------
__global__ void geglu_kernel(const float* __restrict__ Hh, float* __restrict__ G)
{
    size_t n4 = (size_t)ROWS * FFD / 4;
    size_t stride = (size_t)gridDim.x * blockDim.x;
    for (size_t i = (size_t)blockIdx.x * blockDim.x + threadIdx.x; i < n4; i += stride) {
        size_t col4 = i % (FFD / 4), row = i / (FFD / 4);
        float4 a4 = *(const float4*)(Hh + row * FF2D + col4 * 4);
        float4 g4 = *(const float4*)(Hh + row * FF2D + FFD + col4 * 4);
        float4 o;
        o.x = a4.x * gelu_tanh(g4.x); o.y = a4.y * gelu_tanh(g4.y);
        o.z = a4.z * gelu_tanh(g4.z); o.w = a4.w * gelu_tanh(g4.w);
        *(float4*)(G + i * 4) = o;
    }
}

extern "C" void kernel_launch(void* const* d_in, const int* in_sizes, int n_in,
                              void* d_out, int out_size)
{
    const float* x    = (const float*)d_in[0];
    const float* ctx  = (const float*)d_in[1];
    const float* ln1g = (const float*)d_in[2];
    const float* ln1b = (const float*)d_in[3];
    const float* ln2g = (const float*)d_in[4];
    const float* ln2b = (const float*)d_in[5];
    const float* ln3g = (const float*)d_in[6];
    const float* ln3b = (const float*)d_in[7];
    const float* Wq1  = (const float*)d_in[8];
    const float* Wk1  = (const float*)d_in[9];
    const float* Wv1  = (const float*)d_in[10];
    const float* Wo1  = (const float*)d_in[11];
    const float* bo1  = (const float*)d_in[12];
    const float* Wq2  = (const float*)d_in[13];
    const float* Wk2  = (const float*)d_in[14];
    const float* Wv2  = (const float*)d_in[15];
    const float* Wo2  = (const float*)d_in[16];
    const float* bo2  = (const float*)d_in[17];
    const float* Wff1 = (const float*)d_in[18];
    const float* bff1 = (const float*)d_in[19];
    const float* Wff2 = (const float*)d_in[20];
    const float* bff2 = (const float*)d_in[21];
    float* out = (float*)d_out;

    float* sc = nullptr;
    cudaGetSymbolAddress((void**)&sc, g_scratch);
    float* XN = sc + OFF_XN;  float* Q  = sc + OFF_Q;
    float* K  = sc + OFF_K;   float* V  = sc + OFF_V;
    float* O  = sc + OFF_O;   float* X1 = sc + OFF_X1;
    float* S  = sc + OFF_S;   float* Hb = sc + OFF_H;
    float* G  = sc + OFF_G;   float* RM = sc + OFF_RM;
    float* RZ = sc + OFF_RZ;
    unsigned* AM = (unsigned*)(sc + OFF_AM);

    dim3 g1280(CDIM / 128, ROWS / 128);                 // (10, 64)
    dim3 gcross(CDIM / 128, (CROSSROWS + 127) / 128);   // (10, 5)
    dim3 gff1(FF2D / 128, ROWS / 128);                  // (80, 64)
    long long n4  = (long long)ROWS * CDIM / 4;
    long long n4c = (long long)CROSSROWS * CDIM / 4;

    init_amax_kernel<<<1, 32>>>(AM);

    // ---- block 1: self attention ----
    ln_kernel<<<ROWS, 256>>>(x, ln1g, ln1b, XN);
    tgemm_kernel<false,false,true><<<g1280,256>>>(XN, Wq1, Q, ROWS, CDIM, CDIM, nullptr, nullptr, AM+0);
    tgemm_kernel<false,false,true><<<g1280,256>>>(XN, Wk1, K, ROWS, CDIM, CDIM, nullptr, nullptr, AM+1);
    tgemm_kernel<false,false,true><<<g1280,256>>>(XN, Wv1, V, ROWS, CDIM, CDIM, nullptr, nullptr, AM+2);
    quant_sym_kernel<<<2048,256>>>(Q, n4, AM+0);
    quant_sym_kernel<<<2048,256>>>(K, n4, AM+1);
    quant_sym_kernel<<<2048,256>>>(V, n4, AM+2);
    self_scores_kernel<<<dim3(16,16,BHD),256>>>(Q, K, S);
    softmax_stats_kernel<<<BHD*NSEQ,256>>>(S, RM, RZ, AM+3, NSEQ, NSEQ);
    self_pv_kernel<<<dim3(16,1,BHD),256>>>(S, V, RM, RZ, AM+3, O);
    tgemm_kernel<true,true,false><<<g1280,256>>>(O, Wo1, X1, ROWS, CDIM, CDIM, bo1, x, nullptr);

    // ---- block 2: cross attention ----
    ln_kernel<<<ROWS,256>>>(X1, ln2g, ln2b, XN);
    tgemm_kernel<false,false,true><<<g1280,256>>>(XN, Wq2, Q, ROWS, CDIM, CDIM, nullptr, nullptr, AM+4);
    tgemm_kernel<false,false,true><<<gcross,256>>>(ctx, Wk2, K, CROSSROWS, CDIM, CTXC, nullptr, nullptr, AM+5);
    tgemm_kernel<false,false,true><<<gcross,256>>>(ctx, Wv2, V, CROSSROWS, CDIM, CTXC, nullptr, nullptr, AM+6);
    quant_sym_kernel<<<2048,256>>>(Q, n4, AM+4);
    quant_sym_kernel<<<512,256>>>(K, n4c, AM+5);
    quant_sym_kernel<<<512,256>>>(V, n4c, AM+6);
    cross_scores_kernel<<<dim3(16,BHD),256>>>(Q, K, S);
    softmax_stats_kernel<<<BHD*NSEQ,256>>>(S, RM, RZ, AM+7, MCTX, 80);
    cross_pv_kernel<<<dim3(16,BHD),256>>>(S, V, RM, RZ, AM+7, O);
    tgemm_kernel<true,true,false><<<g1280,256>>>(O, Wo2, X1, ROWS, CDIM, CDIM, bo2, X1, nullptr);

    // ---- block 3: GEGLU FF ----
    ln_kernel<<<ROWS,256>>>(X1, ln3g, ln3b, XN);
    tgemm_kernel<true,false,false><<<gff1,256>>>(XN, Wff1, Hb, ROWS, FF2D, CDIM, bff1, nullptr, nullptr);
    geglu_kernel<<<4096,256>>>(Hb, G);
    tgemm_kernel<true,true,false><<<g1280,256>>>(G, Wff2, out, ROWS, CDIM, FFD, bff2, X1, nullptr);
}

// round 5
// speedup vs baseline: 2.2562x; 1.1854x over previous
#include <cuda_runtime.h>
#include <cstdint>

#define NB 8
#define NSEQ 1024
#define CDIM 1280
#define NH 20
#define DH 64
#define MCTX 77
#define CTXC 768
#define FFD 5120
#define FF2D 10240
#define ROWS (NB*NSEQ)
#define BHD (NB*NH)
#define CROSSROWS (NB*MCTX)

static constexpr size_t SZ_XC = (size_t)ROWS * CDIM;
static constexpr size_t OFF_XN = 0;
static constexpr size_t OFF_Q  = OFF_XN + SZ_XC;
static constexpr size_t OFF_K  = OFF_Q + SZ_XC;
static constexpr size_t OFF_V  = OFF_K + SZ_XC;
static constexpr size_t OFF_O  = OFF_V + SZ_XC;
static constexpr size_t OFF_X1 = OFF_O + SZ_XC;
static constexpr size_t OFF_S  = OFF_X1 + SZ_XC;
static constexpr size_t SZ_S   = (size_t)BHD * NSEQ * NSEQ;
static constexpr size_t OFF_H  = OFF_S + SZ_S;
static constexpr size_t SZ_H   = (size_t)ROWS * FF2D;
static constexpr size_t OFF_G  = OFF_H + SZ_H;
static constexpr size_t SZ_G   = (size_t)ROWS * FFD;
static constexpr size_t OFF_RM = OFF_G + SZ_G;
static constexpr size_t OFF_RZ = OFF_RM + (size_t)BHD * NSEQ;
static constexpr size_t OFF_AM = OFF_RZ + (size_t)BHD * NSEQ;
// tf32-preconverted weights + ctx
static constexpr size_t SZ_W1  = (size_t)CDIM * CDIM;     // 1638400
static constexpr size_t SZ_WK2 = (size_t)CTXC * CDIM;     // 983040
static constexpr size_t SZ_WF1 = (size_t)CDIM * FF2D;
static constexpr size_t SZ_WF2 = (size_t)FFD * CDIM;
static constexpr size_t SZ_CTXB = (size_t)CROSSROWS * CTXC;
static constexpr size_t OFF_WQ1 = OFF_AM + 8;
static constexpr size_t OFF_WK1 = OFF_WQ1 + SZ_W1;
static constexpr size_t OFF_WV1 = OFF_WK1 + SZ_W1;
static constexpr size_t OFF_WO1 = OFF_WV1 + SZ_W1;
static constexpr size_t OFF_WQ2 = OFF_WO1 + SZ_W1;
static constexpr size_t OFF_WO2 = OFF_WQ2 + SZ_W1;
static constexpr size_t OFF_WK2 = OFF_WO2 + SZ_W1;
static constexpr size_t OFF_WV2 = OFF_WK2 + SZ_WK2;
static constexpr size_t OFF_WF1 = OFF_WV2 + SZ_WK2;
static constexpr size_t OFF_WF2 = OFF_WF1 + SZ_WF1;
static constexpr size_t OFF_CTX = OFF_WF2 + SZ_WF2;
static constexpr size_t TOTAL_SCRATCH = OFF_CTX + SZ_CTXB;

__device__ __align__(256) float g_scratch[TOTAL_SCRATCH];

__global__ void init_amax_kernel(unsigned* amax) {
    if (threadIdx.x < 8) amax[threadIdx.x] = 0u;
}

__device__ __forceinline__ float gelu_tanh(float x) {
    float x3 = x * x * x;
    return 0.5f * x * (1.0f + tanhf(0.7978845608028654f * (x + 0.044715f * x3)));
}

__device__ __forceinline__ uint32_t f2tf32(float f) {
    uint32_t r;
    asm("cvt.rna.tf32.f32 %0, %1;" : "=r"(r) : "f"(f));
    return r;
}
__device__ __forceinline__ float tf32r(float f) { return __uint_as_float(f2tf32(f)); }

__device__ __forceinline__ void mma_tf32(float* d, const uint32_t* a, const uint32_t* b) {
    asm volatile("mma.sync.aligned.m16n8k8.row.col.f32.tf32.tf32.f32 "
        "{%0,%1,%2,%3}, {%4,%5,%6,%7}, {%8,%9}, {%0,%1,%2,%3};"
        : "+f"(d[0]), "+f"(d[1]), "+f"(d[2]), "+f"(d[3])
        : "r"(a[0]), "r"(a[1]), "r"(a[2]), "r"(a[3]), "r"(b[0]), "r"(b[1]));
}

__device__ __forceinline__ void ldsm4(uint32_t& r0, uint32_t& r1, uint32_t& r2, uint32_t& r3,
                                      uint32_t addr) {
    asm volatile("ldmatrix.sync.aligned.m8n8.x4.shared.b16 {%0,%1,%2,%3}, [%4];"
        : "=r"(r0), "=r"(r1), "=r"(r2), "=r"(r3) : "r"(addr));
}

__device__ __forceinline__ void cp_async16(uint32_t dst, const void* src, int srcsize) {
    asm volatile("cp.async.ca.shared.global [%0], [%1], 16, %2;"
                 :: "r"(dst), "l"(src), "r"(srcsize));
}

// -------- tf32 pre-convert (weights / ctx) --------
__global__ void conv_tf32_kernel(const float* __restrict__ src, float* __restrict__ dst,
                                 long long n4)
{
    long long stride = (long long)gridDim.x * blockDim.x;
    for (long long i = (long long)blockIdx.x * blockDim.x + threadIdx.x; i < n4; i += stride) {
        float4 v = *(const float4*)(src + i * 4);
        v.x = tf32r(v.x); v.y = tf32r(v.y); v.z = tf32r(v.z); v.w = tf32r(v.w);
        *(float4*)(dst + i * 4) = v;
    }
}

// ---------------- LayerNorm: one block per row (tf32-rounded out) ----------------
__global__ void ln_kernel(const float* __restrict__ x, const float* __restrict__ g,
                          const float* __restrict__ bta, float* __restrict__ out)
{
    __shared__ float sx[CDIM];
    __shared__ float red[8];
    int row = blockIdx.x, tid = threadIdx.x;
    const float* xr = x + (size_t)row * CDIM;
    float s = 0.f;
    for (int i = tid; i < CDIM; i += 256) { float v = xr[i]; sx[i] = v; s += v; }
    #pragma unroll
    for (int o = 16; o; o >>= 1) s += __shfl_xor_sync(0xffffffffu, s, o);
    if ((tid & 31) == 0) red[tid >> 5] = s;
    __syncthreads();
    float tot = 0.f;
    #pragma unroll
    for (int w = 0; w < 8; w++) tot += red[w];
    float mean = tot * (1.0f / (float)CDIM);
    float vs = 0.f;
    for (int i = tid; i < CDIM; i += 256) { float d = sx[i] - mean; vs += d * d; }
    __syncthreads();
    #pragma unroll
    for (int o = 16; o; o >>= 1) vs += __shfl_xor_sync(0xffffffffu, vs, o);
    if ((tid & 31) == 0) red[tid >> 5] = vs;
    __syncthreads();
    float tot2 = 0.f;
    #pragma unroll
    for (int w = 0; w < 8; w++) tot2 += red[w];
    float rstd = rsqrtf(tot2 * (1.0f / (float)CDIM) + 1e-5f);
    for (int i = tid; i < CDIM; i += 256)
        out[(size_t)row * CDIM + i] = tf32r((sx[i] - mean) * rstd * g[i] + bta[i]);
}

// ============ TF32 tensor-core GEMM, cp.async 3-stage + ldmatrix ============
// All operands are pre-rounded to tf32 in global memory: NO conversion in loop.
// block tile 128(M) x 128(N), K-tile 16.
// As[stage][m][k16] pad 20; Bs[stage][k16][n128] pad 136 (bank-bijective LDS).
template<bool HAS_BIAS, bool HAS_RES, bool DO_AMAX>
__global__ void __launch_bounds__(256, 2) tgemm_kernel(
    const float* __restrict__ A, const float* __restrict__ Bm, float* __restrict__ Cm,
    int Mn, int Nn, int Kn,
    const float* __restrict__ bias, const float* __restrict__ res, unsigned* amax)
{
    constexpr int ST = 3;
    constexpr uint32_t ABYTES = 128 * 20 * 4;
    constexpr uint32_t BBYTES = 16 * 136 * 4;
    __shared__ __align__(16) uint32_t As[ST][128][20];
    __shared__ __align__(16) float    Bs[ST][16][136];
    __shared__ float reds[8];

    int tid  = threadIdx.x;
    int lane = tid & 31;
    int warp = tid >> 5;
    int wm = warp & 1;     // 2 M groups of 64
    int wn = warp >> 1;    // 4 N groups of 32
    int nBase = blockIdx.x * 128;
    int mBase = blockIdx.y * 128;

    uint32_t asmb = (uint32_t)__cvta_generic_to_shared(&As[0][0][0]);
    uint32_t bsmb = (uint32_t)__cvta_generic_to_shared(&Bs[0][0][0]);

    // loader indices (2 x 16B chunks each for A and B per stage)
    const int aR0 = tid >> 2;              // A row (0..63, +64)
    const int aC  = (tid & 3) << 2;        // A word col 0/4/8/12
    const int bK0 = tid >> 5;              // B k row (0..7, +8)
    const int bN  = (tid & 31) << 2;       // B word col 0..124

    int r8 = lane & 7, sel = lane >> 3;
    uint32_t aoff = asmb + (((wm * 64 + r8 + ((sel & 1) << 3)) * 20 + ((sel >> 1) << 2)) << 2);

    float acc[4][4][4];
    #pragma unroll
    for (int i = 0; i < 4; i++)
        #pragma unroll
        for (int j = 0; j < 4; j++)
            #pragma unroll
            for (int l = 0; l < 4; l++) acc[i][j][l] = 0.f;

    int KT = Kn >> 4;

    auto issue_stage = [&](int s, int k0) {
        #pragma unroll
        for (int i = 0; i < 2; i++) {
            int r = aR0 + i * 64;
            int gr = mBase + r;
            int ok = (gr < Mn);
            const float* src = A + (size_t)(ok ? gr : 0) * Kn + k0 + aC;
            cp_async16(asmb + s * ABYTES + ((r * 20 + aC) << 2), src, ok ? 16 : 0);
        }
        #pragma unroll
        for (int i = 0; i < 2; i++) {
            int kr = bK0 + i * 8;
            const float* src = Bm + (size_t)(k0 + kr) * Nn + nBase + bN;
            cp_async16(bsmb + s * BBYTES + ((kr * 136 + bN) << 2), src, 16);
        }
        asm volatile("cp.async.commit_group;" ::: "memory");
    };

    issue_stage(0, 0);
    issue_stage(1, 16);

    int lr = lane >> 2, lc = lane & 3;
    for (int kt = 0; kt < KT; ++kt) {
        int buf = kt % ST;
        asm volatile("cp.async.wait_group 1;" ::: "memory");
        __syncthreads();
        if (kt + 2 < KT) issue_stage((kt + 2) % ST, (kt + 2) << 4);

        uint32_t abuf = aoff + buf * ABYTES;
        #pragma unroll
        for (int ks = 0; ks < 2; ks++) {
            uint32_t af[4][4], bf[4][2];
            #pragma unroll
            for (int mt = 0; mt < 4; mt++)
                ldsm4(af[mt][0], af[mt][1], af[mt][2], af[mt][3],
                      abuf + mt * (16 * 20 * 4) + ks * 32);
            #pragma unroll
            for (int nt = 0; nt < 4; nt++) {
                int col = wn * 32 + nt * 8 + lr;
                bf[nt][0] = __float_as_uint(Bs[buf][ks * 8 + lc][col]);
                bf[nt][1] = __float_as_uint(Bs[buf][ks * 8 + lc + 4][col]);
            }
            #pragma unroll
            for (int mt = 0; mt < 4; mt++)
                #pragma unroll
                for (int nt = 0; nt < 4; nt++)
                    mma_tf32(acc[mt][nt], af[mt], bf[nt]);
        }
        __syncthreads();
    }

    // epilogue
    float amx = 0.f;
    #pragma unroll
    for (int mt = 0; mt < 4; mt++) {
        #pragma unroll
        for (int nt = 0; nt < 4; nt++) {
            int row0 = mBase + wm * 64 + mt * 16 + lr;
            int col0 = nBase + wn * 32 + nt * 8 + lc * 2;
            #pragma unroll
            for (int half = 0; half < 2; half++) {
                int row = row0 + half * 8;
                if (row < Mn) {
                    float c0 = acc[mt][nt][half * 2 + 0];
                    float c1 = acc[mt][nt][half * 2 + 1];
                    if (HAS_BIAS) { c0 += bias[col0]; c1 += bias[col0 + 1]; }
                    if (HAS_RES) {
                        c0 += res[(size_t)row * Nn + col0];
                        c1 += res[(size_t)row * Nn + col0 + 1];
                    }
                    float2 o = {c0, c1};
                    *(float2*)(Cm + (size_t)row * Nn + col0) = o;
                    if (DO_AMAX) amx = fmaxf(amx, fmaxf(fabsf(c0), fabsf(c1)));
                }
            }
        }
    }
    if (DO_AMAX) {
        #pragma unroll
        for (int o = 16; o; o >>= 1) amx = fmaxf(amx, __shfl_xor_sync(0xffffffffu, amx, o));
        if (lane == 0) reds[warp] = amx;
        __syncthreads();
        if (tid == 0) {
            float m = reds[0];
            #pragma unroll
            for (int w = 1; w < 8; w++) m = fmaxf(m, reds[w]);
            atomicMax(amax, __float_as_uint(m));
        }
    }
}

// ---------------- per-tensor symmetric fake-quant in place ----------------
__global__ void quant_sym_kernel(float* __restrict__ x, long long n4,
                                 const unsigned* __restrict__ amaxbits)
{
    float delta = fmaxf(__uint_as_float(*amaxbits), 1e-8f) / 127.0f;
    long long stride = (long long)gridDim.x * blockDim.x;
    for (long long i = (long long)blockIdx.x * blockDim.x + threadIdx.x; i < n4; i += stride) {
        float4 v = *(float4*)(x + i * 4);
        float l;
        l = rintf(v.x/delta); l = fminf(fmaxf(l,-128.f),127.f); v.x = l*delta;
        l = rintf(v.y/delta); l = fminf(fmaxf(l,-128.f),127.f); v.y = l*delta;
        l = rintf(v.z/delta); l = fminf(fmaxf(l,-128.f),127.f); v.z = l*delta;
        l = rintf(v.w/delta); l = fminf(fmaxf(l,-128.f),127.f); v.w = l*delta;
        *(float4*)(x + i * 4) = v;
    }
}

// ---------------- self-attn scores S = QK^T / 8 ----------------
__global__ void __launch_bounds__(256) self_scores_kernel(
    const float* __restrict__ q, const float* __restrict__ k, float* __restrict__ S)
{
    __shared__ __align__(16) float Qs[64][68];
    __shared__ __align__(16) float Ks[64][68];
    int tid = threadIdx.x;
    int bh = blockIdx.z, b = bh / NH, h = bh % NH;
    int n0 = blockIdx.x * 64, m0 = blockIdx.y * 64;
    #pragma unroll
    for (int it = 0; it < 4; ++it) {
        int r = (tid >> 4) + it * 16, c = (tid & 15) << 2;
        float4 qv = *(const float4*)(q + ((size_t)(b*NSEQ + n0 + r))*CDIM + h*DH + c);
        Qs[c+0][r]=qv.x; Qs[c+1][r]=qv.y; Qs[c+2][r]=qv.z; Qs[c+3][r]=qv.w;
        float4 kv = *(const float4*)(k + ((size_t)(b*NSEQ + m0 + r))*CDIM + h*DH + c);
        Ks[c+0][r]=kv.x; Ks[c+1][r]=kv.y; Ks[c+2][r]=kv.z; Ks[c+3][r]=kv.w;
    }
    __syncthreads();
    int tx = tid & 15, ty = tid >> 4;
    float acc[4][4];
    #pragma unroll
    for (int i = 0; i < 4; i++)
        #pragma unroll
        for (int j = 0; j < 4; j++) acc[i][j] = 0.f;
    #pragma unroll 8
    for (int d = 0; d < 64; ++d) {
        float4 q4 = *(const float4*)&Qs[d][ty*4];
        float4 k4 = *(const float4*)&Ks[d][tx*4];
        float qa[4]={q4.x,q4.y,q4.z,q4.w}, ka[4]={k4.x,k4.y,k4.z,k4.w};
        #pragma unroll
        for (int i = 0; i < 4; i++)
            #pragma unroll
            for (int j = 0; j < 4; j++) acc[i][j] = fmaf(qa[i], ka[j], acc[i][j]);
    }
    #pragma unroll
    for (int i = 0; i < 4; i++) {
        float4 o = {acc[i][0]*0.125f, acc[i][1]*0.125f, acc[i][2]*0.125f, acc[i][3]*0.125f};
        *(float4*)(S + ((size_t)bh*NSEQ + n0 + ty*4 + i)*NSEQ + m0 + tx*4) = o;
    }
}

// -------- softmax row stats; global max prob = max(1/Z) --------
__global__ void softmax_stats_kernel(const float* __restrict__ S, float* __restrict__ rowmax,
                                     float* __restrict__ rowz, unsigned* wmax, int cols, int stride)
{
    int row = blockIdx.x, tid = threadIdx.x;
    const float* s = S + (size_t)row * stride;
    __shared__ float red[8];
    float m = -3.4e38f;
    for (int i = tid; i < cols; i += 256) m = fmaxf(m, s[i]);
    #pragma unroll
    for (int o = 16; o; o >>= 1) m = fmaxf(m, __shfl_xor_sync(0xffffffffu, m, o));
    if ((tid & 31) == 0) red[tid >> 5] = m;
    __syncthreads();
    float mm = red[0];
    #pragma unroll
    for (int w = 1; w < 8; w++) mm = fmaxf(mm, red[w]);
    __syncthreads();
    float z = 0.f;
    for (int i = tid; i < cols; i += 256) z += expf(s[i] - mm);
    #pragma unroll
    for (int o = 16; o; o >>= 1) z += __shfl_xor_sync(0xffffffffu, z, o);
    if ((tid & 31) == 0) red[tid >> 5] = z;
    __syncthreads();
    if (tid == 0) {
        float zz = 0.f;
        #pragma unroll
        for (int w = 0; w < 8; w++) zz += red[w];
        rowmax[row] = mm; rowz[row] = zz;
        atomicMax(wmax, __float_as_uint(1.0f / zz));
    }
}

// -------- self-attn PV with fused fq_zero on probs (O tf32-rounded) --------
__global__ void __launch_bounds__(256) self_pv_kernel(
    const float* __restrict__ S, const float* __restrict__ v,
    const float* __restrict__ rowmax, const float* __restrict__ rowz,
    const unsigned* __restrict__ wmaxbits, float* __restrict__ O)
{
    __shared__ __align__(16) float Ws[64][68];
    __shared__ __align__(16) float Vs[64][68];
    int tid = threadIdx.x;
    int bh = blockIdx.z, b = bh / NH, h = bh % NH;
    int n0 = blockIdx.x * 64;
    int tx = tid & 15, ty = tid >> 4;
    float delta = fmaxf(__uint_as_float(*wmaxbits), 1e-8f) / 255.0f;
    float inv_delta = 1.0f / delta;
    float rm4[4], ri4[4];
    #pragma unroll
    for (int it = 0; it < 4; it++) {
        int r = (tid >> 4) + it * 16;
        rm4[it] = rowmax[(size_t)bh*NSEQ + n0 + r];
        ri4[it] = 1.0f / rowz[(size_t)bh*NSEQ + n0 + r];
    }
    float acc[4][4];
    #pragma unroll
    for (int i = 0; i < 4; i++)
        #pragma unroll
        for (int j = 0; j < 4; j++) acc[i][j] = 0.f;
    for (int mt = 0; mt < 16; ++mt) {
        int m0 = mt * 64;
        __syncthreads();
        #pragma unroll
        for (int it = 0; it < 4; ++it) {
            int r = (tid >> 4) + it * 16, c = (tid & 15) << 2;
            float4 sv = *(const float4*)(S + ((size_t)bh*NSEQ + n0 + r)*NSEQ + m0 + c);
            float rm = rm4[it], ri = ri4[it], p, l;
            p = expf(sv.x-rm); l = rintf(p*ri*inv_delta); l = fminf(fmaxf(l,0.f),255.f); Ws[c+0][r] = l*delta;
            p = expf(sv.y-rm); l = rintf(p*ri*inv_delta); l = fminf(fmaxf(l,0.f),255.f); Ws[c+1][r] = l*delta;
            p = expf(sv.z-rm); l = rintf(p*ri*inv_delta); l = fminf(fmaxf(l,0.f),255.f); Ws[c+2][r] = l*delta;
            p = expf(sv.w-rm); l = rintf(p*ri*inv_delta); l = fminf(fmaxf(l,0.f),255.f); Ws[c+3][r] = l*delta;
            *(float4*)&Vs[r][c] = *(const float4*)(v + ((size_t)(b*NSEQ + m0 + r))*CDIM + h*DH + c);
        }
        __syncthreads();
        #pragma unroll 8
        for (int m = 0; m < 64; m++) {
            float4 w4 = *(const float4*)&Ws[m][ty*4];
            float4 v4 = *(const float4*)&Vs[m][tx*4];
            float wa[4]={w4.x,w4.y,w4.z,w4.w}, va[4]={v4.x,v4.y,v4.z,v4.w};
            #pragma unroll
            for (int i = 0; i < 4; i++)
                #pragma unroll
                for (int j = 0; j < 4; j++) acc[i][j] = fmaf(wa[i], va[j], acc[i][j]);
        }
    }
    #pragma unroll
    for (int i = 0; i < 4; i++) {
        float4 o = {tf32r(acc[i][0]), tf32r(acc[i][1]), tf32r(acc[i][2]), tf32r(acc[i][3])};
        *(float4*)(O + ((size_t)(b*NSEQ + n0 + ty*4 + i))*CDIM + h*DH + tx*4) = o;
    }
}

// -------- cross-attn scores (M=77, stride 80) --------
__global__ void __launch_bounds__(256) cross_scores_kernel(
    const float* __restrict__ q, const float* __restrict__ k, float* __restrict__ S)
{
    __shared__ __align__(16) float Qs[64][68];
    __shared__ __align__(16) float Ks[80][68];
    int tid = threadIdx.x;
    int bh = blockIdx.y, b = bh / NH, h = bh % NH;
    int n0 = blockIdx.x * 64;
    #pragma unroll
    for (int it = 0; it < 4; ++it) {
        int r = (tid >> 4) + it * 16, c = (tid & 15) << 2;
        float4 qv = *(const float4*)(q + ((size_t)(b*NSEQ + n0 + r))*CDIM + h*DH + c);
        Qs[c+0][r]=qv.x; Qs[c+1][r]=qv.y; Qs[c+2][r]=qv.z; Qs[c+3][r]=qv.w;
    }
    #pragma unroll
    for (int it = 0; it < 5; ++it) {
        int lin = tid + it * 256;
        if (lin < 80 * 16) {
            int r = lin >> 4, c = (lin & 15) << 2;
            float4 kv = (r < MCTX) ? *(const float4*)(k + ((size_t)(b*MCTX + r))*CDIM + h*DH + c)
                                   : make_float4(0.f,0.f,0.f,0.f);
            *(float4*)&Ks[r][c] = kv;
        }
    }
    __syncthreads();
    int tx = tid & 15, ty = tid >> 4;
    float acc[4][5];
    #pragma unroll
    for (int i = 0; i < 4; i++)
        #pragma unroll
        for (int j = 0; j < 5; j++) acc[i][j] = 0.f;
    #pragma unroll 4
    for (int d = 0; d < 64; ++d) {
        float4 q4 = *(const float4*)&Qs[d][ty*4];
        float qa[4]={q4.x,q4.y,q4.z,q4.w};
        #pragma unroll
        for (int jj = 0; jj < 5; jj++) {
            float kv = Ks[tx*5+jj][d];
            #pragma unroll
            for (int i = 0; i < 4; i++) acc[i][jj] = fmaf(qa[i], kv, acc[i][jj]);
        }
    }
    #pragma unroll
    for (int i = 0; i < 4; i++)
        #pragma unroll
        for (int jj = 0; jj < 5; jj++) {
            int m = tx * 5 + jj;
            if (m < MCTX)
                S[((size_t)bh*NSEQ + n0 + ty*4 + i)*80 + m] = acc[i][jj] * 0.125f;
        }
}

// -------- cross-attn PV with fused fq_zero (O tf32-rounded) --------
__global__ void __launch_bounds__(256) cross_pv_kernel(
    const float* __restrict__ S, const float* __restrict__ v,
    const float* __restrict__ rowmax, const float* __restrict__ rowz,
    const unsigned* __restrict__ wmaxbits, float* __restrict__ O)
{
    __shared__ __align__(16) float Ws[80][68];
    __shared__ __align__(16) float Vs[80][68];
    int tid = threadIdx.x;
    int bh = blockIdx.y, b = bh / NH, h = bh % NH;
    int n0 = blockIdx.x * 64;
    int tx = tid & 15, ty = tid >> 4;
    float delta = fmaxf(__uint_as_float(*wmaxbits), 1e-8f) / 255.0f;
    float inv_delta = 1.0f / delta;
    #pragma unroll
    for (int it = 0; it < 5; ++it) {
        int lin = tid + it * 256;
        if (lin < MCTX * 16) {
            int r = lin >> 4, c = (lin & 15) << 2;
            *(float4*)&Vs[r][c] = *(const float4*)(v + ((size_t)(b*MCTX + r))*CDIM + h*DH + c);
        }
    }
    #pragma unroll
    for (int it = 0; it < 4; ++it) {
        int r = (tid >> 4) + it * 16;
        float rm = rowmax[(size_t)bh*NSEQ + n0 + r];
        float ri = 1.0f / rowz[(size_t)bh*NSEQ + n0 + r];
        #pragma unroll
        for (int jj = 0; jj < 5; jj++) {
            int m = (tid & 15) * 5 + jj;
            float w = 0.f;
            if (m < MCTX) {
                float s = S[((size_t)bh*NSEQ + n0 + r)*80 + m];
                float p = expf(s - rm);
                float l = rintf(p * ri * inv_delta);
                l = fminf(fmaxf(l, 0.f), 255.f);
                w = l * delta;
            }
            Ws[m][r] = w;
        }
    }
    __syncthreads();
    float acc[4][4];
    #pragma unroll
    for (int i = 0; i < 4; i++)
        #pragma unroll
        for (int j = 0; j < 4; j++) acc[i][j] = 0.f;
    for (int m = 0; m < MCTX; m++) {
        float4 w4 = *(const float4*)&Ws[m][ty*4];
        float4 v4 = *(const float4*)&Vs[m][tx*4];
        float wa[4]={w4.x,w4.y,w4.z,w4.w}, va[4]={v4.x,v4.y,v4.z,v4.w};
        #pragma unroll
        for (int i = 0; i < 4; i++)
            #pragma unroll
            for (int j = 0; j < 4; j++) acc[i][j] = fmaf(wa[i], va[j], acc[i][j]);
    }
    #pragma unroll
    for (int i = 0; i < 4; i++) {
        float4 o = {tf32r(acc[i][0]), tf32r(acc[i][1]), tf32r(acc[i][2]), tf32r(acc[i][3])};
        *(float4*)(O + ((size_t)(b*NSEQ + n0 + ty*4 + i))*CDIM + h*DH + tx*4) = o;
    }
}

// -------- GEGLU: G = a * gelu(g)  (tf32-rounded out) --------
__global__ void geglu_kernel(const float* __restrict__ Hh, float* __restrict__ G)
{
    size_t n4 = (size_t)ROWS * FFD / 4;
    size_t stride = (size_t)gridDim.x * blockDim.x;
    for (size_t i = (size_t)blockIdx.x * blockDim.x + threadIdx.x; i < n4; i += stride) {
        size_t col4 = i % (FFD / 4), row = i / (FFD / 4);
        float4 a4 = *(const float4*)(Hh + row * FF2D + col4 * 4);
        float4 g4 = *(const float4*)(Hh + row * FF2D + FFD + col4 * 4);
        float4 o;
        o.x = tf32r(a4.x * gelu_tanh(g4.x)); o.y = tf32r(a4.y * gelu_tanh(g4.y));
        o.z = tf32r(a4.z * gelu_tanh(g4.z)); o.w = tf32r(a4.w * gelu_tanh(g4.w));
        *(float4*)(G + i * 4) = o;
    }
}

extern "C" void kernel_launch(void* const* d_in, const int* in_sizes, int n_in,
                              void* d_out, int out_size)
{
    const float* x    = (const float*)d_in[0];
    const float* ctx  = (const float*)d_in[1];
    const float* ln1g = (const float*)d_in[2];
    const float* ln1b = (const float*)d_in[3];
    const float* ln2g = (const float*)d_in[4];
    const float* ln2b = (const float*)d_in[5];
    const float* ln3g = (const float*)d_in[6];
    const float* ln3b = (const float*)d_in[7];
    const float* Wq1  = (const float*)d_in[8];
    const float* Wk1  = (const float*)d_in[9];
    const float* Wv1  = (const float*)d_in[10];
    const float* Wo1  = (const float*)d_in[11];
    const float* bo1  = (const float*)d_in[12];
    const float* Wq2  = (const float*)d_in[13];
    const float* Wk2  = (const float*)d_in[14];
    const float* Wv2  = (const float*)d_in[15];
    const float* Wo2  = (const float*)d_in[16];
    const float* bo2  = (const float*)d_in[17];
    const float* Wff1 = (const float*)d_in[18];
    const float* bff1 = (const float*)d_in[19];
    const float* Wff2 = (const float*)d_in[20];
    const float* bff2 = (const float*)d_in[21];
    float* out = (float*)d_out;

    float* sc = nullptr;
    cudaGetSymbolAddress((void**)&sc, g_scratch);
    float* XN = sc + OFF_XN;  float* Q  = sc + OFF_Q;
    float* K  = sc + OFF_K;   float* V  = sc + OFF_V;
    float* O  = sc + OFF_O;   float* X1 = sc + OFF_X1;
    float* S  = sc + OFF_S;   float* Hb = sc + OFF_H;
    float* G  = sc + OFF_G;   float* RM = sc + OFF_RM;
    float* RZ = sc + OFF_RZ;
    unsigned* AM = (unsigned*)(sc + OFF_AM);
    float* cWq1 = sc + OFF_WQ1; float* cWk1 = sc + OFF_WK1;
    float* cWv1 = sc + OFF_WV1; float* cWo1 = sc + OFF_WO1;
    float* cWq2 = sc + OFF_WQ2; float* cWo2 = sc + OFF_WO2;
    float* cWk2 = sc + OFF_WK2; float* cWv2 = sc + OFF_WV2;
    float* cWf1 = sc + OFF_WF1; float* cWf2 = sc + OFF_WF2;
    float* cCtx = sc + OFF_CTX;

    dim3 g1280(CDIM / 128, ROWS / 128);                 // (10, 64)
    dim3 gcross(CDIM / 128, (CROSSROWS + 127) / 128);   // (10, 5)
    dim3 gff1(FF2D / 128, ROWS / 128);                  // (80, 64)
    long long n4  = (long long)ROWS * CDIM / 4;
    long long n4c = (long long)CROSSROWS * CDIM / 4;

    init_amax_kernel<<<1, 32>>>(AM);

    // ---- pre-convert weights + ctx to tf32 (GEMM-input only) ----
    conv_tf32_kernel<<<1024,256>>>(Wq1,  cWq1, (long long)SZ_W1/4);
    conv_tf32_kernel<<<1024,256>>>(Wk1,  cWk1, (long long)SZ_W1/4);
    conv_tf32_kernel<<<1024,256>>>(Wv1,  cWv1, (long long)SZ_W1/4);
    conv_tf32_kernel<<<1024,256>>>(Wo1,  cWo1, (long long)SZ_W1/4);
    conv_tf32_kernel<<<1024,256>>>(Wq2,  cWq2, (long long)SZ_W1/4);
    conv_tf32_kernel<<<1024,256>>>(Wo2,  cWo2, (long long)SZ_W1/4);
    conv_tf32_kernel<<<1024,256>>>(Wk2,  cWk2, (long long)SZ_WK2/4);
    conv_tf32_kernel<<<1024,256>>>(Wv2,  cWv2, (long long)SZ_WK2/4);
    conv_tf32_kernel<<<2048,256>>>(Wff1, cWf1, (long long)SZ_WF1/4);
    conv_tf32_kernel<<<2048,256>>>(Wff2, cWf2, (long long)SZ_WF2/4);
    conv_tf32_kernel<<<512,256>>>(ctx,   cCtx, (long long)SZ_CTXB/4);

    // ---- block 1: self attention ----
    ln_kernel<<<ROWS, 256>>>(x, ln1g, ln1b, XN);
    tgemm_kernel<false,false,true><<<g1280,256>>>(XN, cWq1, Q, ROWS, CDIM, CDIM, nullptr, nullptr, AM+0);
    tgemm_kernel<false,false,true><<<g1280,256>>>(XN, cWk1, K, ROWS, CDIM, CDIM, nullptr, nullptr, AM+1);
    tgemm_kernel<false,false,true><<<g1280,256>>>(XN, cWv1, V, ROWS, CDIM, CDIM, nullptr, nullptr, AM+2);
    quant_sym_kernel<<<2048,256>>>(Q, n4, AM+0);
    quant_sym_kernel<<<2048,256>>>(K, n4, AM+1);
    quant_sym_kernel<<<2048,256>>>(V, n4, AM+2);
    self_scores_kernel<<<dim3(16,16,BHD),256>>>(Q, K, S);
    softmax_stats_kernel<<<BHD*NSEQ,256>>>(S, RM, RZ, AM+3, NSEQ, NSEQ);
    self_pv_kernel<<<dim3(16,1,BHD),256>>>(S, V, RM, RZ, AM+3, O);
    tgemm_kernel<true,true,false><<<g1280,256>>>(O, cWo1, X1, ROWS, CDIM, CDIM, bo1, x, nullptr);

    // ---- block 2: cross attention ----
    ln_kernel<<<ROWS,256>>>(X1, ln2g, ln2b, XN);
    tgemm_kernel<false,false,true><<<g1280,256>>>(XN, cWq2, Q, ROWS, CDIM, CDIM, nullptr, nullptr, AM+4);
    tgemm_kernel<false,false,true><<<gcross,256>>>(cCtx, cWk2, K, CROSSROWS, CDIM, CTXC, nullptr, nullptr, AM+5);
    tgemm_kernel<false,false,true><<<gcross,256>>>(cCtx, cWv2, V, CROSSROWS, CDIM, CTXC, nullptr, nullptr, AM+6);
    quant_sym_kernel<<<2048,256>>>(Q, n4, AM+4);
    quant_sym_kernel<<<512,256>>>(K, n4c, AM+5);
    quant_sym_kernel<<<512,256>>>(V, n4c, AM+6);
    cross_scores_kernel<<<dim3(16,BHD),256>>>(Q, K, S);
    softmax_stats_kernel<<<BHD*NSEQ,256>>>(S, RM, RZ, AM+7, MCTX, 80);
    cross_pv_kernel<<<dim3(16,BHD),256>>>(S, V, RM, RZ, AM+7, O);
    tgemm_kernel<true,true,false><<<g1280,256>>>(O, cWo2, X1, ROWS, CDIM, CDIM, bo2, X1, nullptr);

    // ---- block 3: GEGLU FF ----
    ln_kernel<<<ROWS,256>>>(X1, ln3g, ln3b, XN);
    tgemm_kernel<true,false,false><<<gff1,256>>>(XN, cWf1, Hb, ROWS, FF2D, CDIM, bff1, nullptr, nullptr);
    geglu_kernel<<<4096,256>>>(Hb, G);
    tgemm_kernel<true,true,false><<<g1280,256>>>(G, cWf2, out, ROWS, CDIM, FFD, bff2, X1, nullptr);
}

// round 6
// speedup vs baseline: 2.7186x; 1.2050x over previous
#include <cuda_runtime.h>
#include <cstdint>

#define NB 8
#define NSEQ 1024
#define CDIM 1280
#define NH 20
#define DH 64
#define MCTX 77
#define CTXC 768
#define FFD 5120
#define FF2D 10240
#define ROWS (NB*NSEQ)
#define BHD (NB*NH)
#define CROSSROWS (NB*MCTX)

static constexpr size_t SZ_XC = (size_t)ROWS * CDIM;
static constexpr size_t OFF_XN = 0;
static constexpr size_t OFF_Q  = OFF_XN + SZ_XC;
static constexpr size_t OFF_K  = OFF_Q + SZ_XC;
static constexpr size_t OFF_V  = OFF_K + SZ_XC;
static constexpr size_t OFF_O  = OFF_V + SZ_XC;
static constexpr size_t OFF_X1 = OFF_O + SZ_XC;
static constexpr size_t OFF_S  = OFF_X1 + SZ_XC;
static constexpr size_t SZ_S   = (size_t)BHD * NSEQ * NSEQ;
static constexpr size_t OFF_H  = OFF_S + SZ_S;
static constexpr size_t SZ_H   = (size_t)ROWS * FF2D;
static constexpr size_t OFF_G  = OFF_H + SZ_H;
static constexpr size_t SZ_G   = (size_t)ROWS * FFD;
static constexpr size_t OFF_RM = OFF_G + SZ_G;
static constexpr size_t OFF_RZ = OFF_RM + (size_t)BHD * NSEQ;
static constexpr size_t OFF_AM = OFF_RZ + (size_t)BHD * NSEQ;
// tf32-preconverted weights + ctx
static constexpr size_t SZ_W1  = (size_t)CDIM * CDIM;
static constexpr size_t SZ_WK2 = (size_t)CTXC * CDIM;
static constexpr size_t SZ_WF1 = (size_t)CDIM * FF2D;
static constexpr size_t SZ_WF2 = (size_t)FFD * CDIM;
static constexpr size_t SZ_CTXB = (size_t)CROSSROWS * CTXC;
static constexpr size_t OFF_WQ1 = OFF_AM + 8;
static constexpr size_t OFF_WK1 = OFF_WQ1 + SZ_W1;
static constexpr size_t OFF_WV1 = OFF_WK1 + SZ_W1;
static constexpr size_t OFF_WO1 = OFF_WV1 + SZ_W1;
static constexpr size_t OFF_WQ2 = OFF_WO1 + SZ_W1;
static constexpr size_t OFF_WO2 = OFF_WQ2 + SZ_W1;
static constexpr size_t OFF_WK2 = OFF_WO2 + SZ_W1;
static constexpr size_t OFF_WV2 = OFF_WK2 + SZ_WK2;
static constexpr size_t OFF_WF1 = OFF_WV2 + SZ_WK2;
static constexpr size_t OFF_WF2 = OFF_WF1 + SZ_WF1;
static constexpr size_t OFF_CTX = OFF_WF2 + SZ_WF2;
// int8 level tensors (self-attention)
static constexpr size_t SZ_S8F  = (size_t)ROWS * CDIM / 4;   // bytes held in floats
static constexpr size_t OFF_LQ8 = OFF_CTX + SZ_CTXB;
static constexpr size_t OFF_LK8 = OFF_LQ8 + SZ_S8F;
static constexpr size_t OFF_LVT = OFF_LK8 + SZ_S8F;
static constexpr size_t TOTAL_SCRATCH = OFF_LVT + SZ_S8F;

__device__ __align__(256) float g_scratch[TOTAL_SCRATCH];

__global__ void init_amax_kernel(unsigned* amax) {
    if (threadIdx.x < 8) amax[threadIdx.x] = 0u;
}

__device__ __forceinline__ float gelu_tanh(float x) {
    float x3 = x * x * x;
    return 0.5f * x * (1.0f + tanhf(0.7978845608028654f * (x + 0.044715f * x3)));
}

__device__ __forceinline__ uint32_t f2tf32(float f) {
    uint32_t r;
    asm("cvt.rna.tf32.f32 %0, %1;" : "=r"(r) : "f"(f));
    return r;
}
__device__ __forceinline__ float tf32r(float f) { return __uint_as_float(f2tf32(f)); }

__device__ __forceinline__ void mma_tf32(float* d, const uint32_t* a, const uint32_t* b) {
    asm volatile("mma.sync.aligned.m16n8k8.row.col.f32.tf32.tf32.f32 "
        "{%0,%1,%2,%3}, {%4,%5,%6,%7}, {%8,%9}, {%0,%1,%2,%3};"
        : "+f"(d[0]), "+f"(d[1]), "+f"(d[2]), "+f"(d[3])
        : "r"(a[0]), "r"(a[1]), "r"(a[2]), "r"(a[3]), "r"(b[0]), "r"(b[1]));
}

__device__ __forceinline__ void mma_s8(int* d, const uint32_t* a, const uint32_t* b) {
    asm volatile("mma.sync.aligned.m16n8k32.row.col.s32.s8.s8.s32 "
        "{%0,%1,%2,%3}, {%4,%5,%6,%7}, {%8,%9}, {%0,%1,%2,%3};"
        : "+r"(d[0]), "+r"(d[1]), "+r"(d[2]), "+r"(d[3])
        : "r"(a[0]), "r"(a[1]), "r"(a[2]), "r"(a[3]), "r"(b[0]), "r"(b[1]));
}

__device__ __forceinline__ void mma_u8s8(int* d, const uint32_t* a, const uint32_t* b) {
    asm volatile("mma.sync.aligned.m16n8k32.row.col.s32.u8.s8.s32 "
        "{%0,%1,%2,%3}, {%4,%5,%6,%7}, {%8,%9}, {%0,%1,%2,%3};"
        : "+r"(d[0]), "+r"(d[1]), "+r"(d[2]), "+r"(d[3])
        : "r"(a[0]), "r"(a[1]), "r"(a[2]), "r"(a[3]), "r"(b[0]), "r"(b[1]));
}

__device__ __forceinline__ void ldsm4(uint32_t& r0, uint32_t& r1, uint32_t& r2, uint32_t& r3,
                                      uint32_t addr) {
    asm volatile("ldmatrix.sync.aligned.m8n8.x4.shared.b16 {%0,%1,%2,%3}, [%4];"
        : "=r"(r0), "=r"(r1), "=r"(r2), "=r"(r3) : "r"(addr));
}

__device__ __forceinline__ void cp_async16(uint32_t dst, const void* src, int srcsize) {
    asm volatile("cp.async.ca.shared.global [%0], [%1], 16, %2;"
                 :: "r"(dst), "l"(src), "r"(srcsize));
}

__device__ __forceinline__ int clamp_i(int v, int lo, int hi) {
    return v < lo ? lo : (v > hi ? hi : v);
}

__device__ __forceinline__ uint32_t pack_s8x4(float4 v, float inv) {
    int a = clamp_i(__float2int_rn(v.x * inv), -128, 127);
    int b = clamp_i(__float2int_rn(v.y * inv), -128, 127);
    int c = clamp_i(__float2int_rn(v.z * inv), -128, 127);
    int d = clamp_i(__float2int_rn(v.w * inv), -128, 127);
    return (a & 255) | ((b & 255) << 8) | ((c & 255) << 16) | ((d & 255) << 24);
}

// -------- tf32 pre-convert --------
__global__ void conv_tf32_kernel(const float* __restrict__ src, float* __restrict__ dst,
                                 long long n4)
{
    long long stride = (long long)gridDim.x * blockDim.x;
    for (long long i = (long long)blockIdx.x * blockDim.x + threadIdx.x; i < n4; i += stride) {
        float4 v = *(const float4*)(src + i * 4);
        v.x = tf32r(v.x); v.y = tf32r(v.y); v.z = tf32r(v.z); v.w = tf32r(v.w);
        *(float4*)(dst + i * 4) = v;
    }
}

// ---------------- LayerNorm (tf32-rounded out) ----------------
__global__ void ln_kernel(const float* __restrict__ x, const float* __restrict__ g,
                          const float* __restrict__ bta, float* __restrict__ out)
{
    __shared__ float sx[CDIM];
    __shared__ float red[8];
    int row = blockIdx.x, tid = threadIdx.x;
    const float* xr = x + (size_t)row * CDIM;
    float s = 0.f;
    for (int i = tid; i < CDIM; i += 256) { float v = xr[i]; sx[i] = v; s += v; }
    #pragma unroll
    for (int o = 16; o; o >>= 1) s += __shfl_xor_sync(0xffffffffu, s, o);
    if ((tid & 31) == 0) red[tid >> 5] = s;
    __syncthreads();
    float tot = 0.f;
    #pragma unroll
    for (int w = 0; w < 8; w++) tot += red[w];
    float mean = tot * (1.0f / (float)CDIM);
    float vs = 0.f;
    for (int i = tid; i < CDIM; i += 256) { float d = sx[i] - mean; vs += d * d; }
    __syncthreads();
    #pragma unroll
    for (int o = 16; o; o >>= 1) vs += __shfl_xor_sync(0xffffffffu, vs, o);
    if ((tid & 31) == 0) red[tid >> 5] = vs;
    __syncthreads();
    float tot2 = 0.f;
    #pragma unroll
    for (int w = 0; w < 8; w++) tot2 += red[w];
    float rstd = rsqrtf(tot2 * (1.0f / (float)CDIM) + 1e-5f);
    for (int i = tid; i < CDIM; i += 256)
        out[(size_t)row * CDIM + i] = tf32r((sx[i] - mean) * rstd * g[i] + bta[i]);
}

// ============ TF32 GEMM, cp.async 3-stage + ldmatrix (unchanged from R5) ============
template<bool HAS_BIAS, bool HAS_RES, bool DO_AMAX>
__global__ void __launch_bounds__(256, 2) tgemm_kernel(
    const float* __restrict__ A, const float* __restrict__ Bm, float* __restrict__ Cm,
    int Mn, int Nn, int Kn,
    const float* __restrict__ bias, const float* __restrict__ res, unsigned* amax)
{
    constexpr int ST = 3;
    constexpr uint32_t ABYTES = 128 * 20 * 4;
    constexpr uint32_t BBYTES = 16 * 136 * 4;
    __shared__ __align__(16) uint32_t As[ST][128][20];
    __shared__ __align__(16) float    Bs[ST][16][136];
    __shared__ float reds[8];

    int tid  = threadIdx.x;
    int lane = tid & 31;
    int warp = tid >> 5;
    int wm = warp & 1;
    int wn = warp >> 1;
    int nBase = blockIdx.x * 128;
    int mBase = blockIdx.y * 128;

    uint32_t asmb = (uint32_t)__cvta_generic_to_shared(&As[0][0][0]);
    uint32_t bsmb = (uint32_t)__cvta_generic_to_shared(&Bs[0][0][0]);

    const int aR0 = tid >> 2;
    const int aC  = (tid & 3) << 2;
    const int bK0 = tid >> 5;
    const int bN  = (tid & 31) << 2;

    int r8 = lane & 7, sel = lane >> 3;
    uint32_t aoff = asmb + (((wm * 64 + r8 + ((sel & 1) << 3)) * 20 + ((sel >> 1) << 2)) << 2);

    float acc[4][4][4];
    #pragma unroll
    for (int i = 0; i < 4; i++)
        #pragma unroll
        for (int j = 0; j < 4; j++)
            #pragma unroll
            for (int l = 0; l < 4; l++) acc[i][j][l] = 0.f;

    int KT = Kn >> 4;

    auto issue_stage = [&](int s, int k0) {
        #pragma unroll
        for (int i = 0; i < 2; i++) {
            int r = aR0 + i * 64;
            int gr = mBase + r;
            int ok = (gr < Mn);
            const float* src = A + (size_t)(ok ? gr : 0) * Kn + k0 + aC;
            cp_async16(asmb + s * ABYTES + ((r * 20 + aC) << 2), src, ok ? 16 : 0);
        }
        #pragma unroll
        for (int i = 0; i < 2; i++) {
            int kr = bK0 + i * 8;
            const float* src = Bm + (size_t)(k0 + kr) * Nn + nBase + bN;
            cp_async16(bsmb + s * BBYTES + ((kr * 136 + bN) << 2), src, 16);
        }
        asm volatile("cp.async.commit_group;" ::: "memory");
    };

    issue_stage(0, 0);
    issue_stage(1, 16);

    int lr = lane >> 2, lc = lane & 3;
    for (int kt = 0; kt < KT; ++kt) {
        int buf = kt % ST;
        asm volatile("cp.async.wait_group 1;" ::: "memory");
        __syncthreads();
        if (kt + 2 < KT) issue_stage((kt + 2) % ST, (kt + 2) << 4);

        uint32_t abuf = aoff + buf * ABYTES;
        #pragma unroll
        for (int ks = 0; ks < 2; ks++) {
            uint32_t af[4][4], bf[4][2];
            #pragma unroll
            for (int mt = 0; mt < 4; mt++)
                ldsm4(af[mt][0], af[mt][1], af[mt][2], af[mt][3],
                      abuf + mt * (16 * 20 * 4) + ks * 32);
            #pragma unroll
            for (int nt = 0; nt < 4; nt++) {
                int col = wn * 32 + nt * 8 + lr;
                bf[nt][0] = __float_as_uint(Bs[buf][ks * 8 + lc][col]);
                bf[nt][1] = __float_as_uint(Bs[buf][ks * 8 + lc + 4][col]);
            }
            #pragma unroll
            for (int mt = 0; mt < 4; mt++)
                #pragma unroll
                for (int nt = 0; nt < 4; nt++)
                    mma_tf32(acc[mt][nt], af[mt], bf[nt]);
        }
        __syncthreads();
    }

    float amx = 0.f;
    #pragma unroll
    for (int mt = 0; mt < 4; mt++) {
        #pragma unroll
        for (int nt = 0; nt < 4; nt++) {
            int row0 = mBase + wm * 64 + mt * 16 + lr;
            int col0 = nBase + wn * 32 + nt * 8 + lc * 2;
            #pragma unroll
            for (int half = 0; half < 2; half++) {
                int row = row0 + half * 8;
                if (row < Mn) {
                    float c0 = acc[mt][nt][half * 2 + 0];
                    float c1 = acc[mt][nt][half * 2 + 1];
                    if (HAS_BIAS) { c0 += bias[col0]; c1 += bias[col0 + 1]; }
                    if (HAS_RES) {
                        c0 += res[(size_t)row * Nn + col0];
                        c1 += res[(size_t)row * Nn + col0 + 1];
                    }
                    float2 o = {c0, c1};
                    *(float2*)(Cm + (size_t)row * Nn + col0) = o;
                    if (DO_AMAX) amx = fmaxf(amx, fmaxf(fabsf(c0), fabsf(c1)));
                }
            }
        }
    }
    if (DO_AMAX) {
        #pragma unroll
        for (int o = 16; o; o >>= 1) amx = fmaxf(amx, __shfl_xor_sync(0xffffffffu, amx, o));
        if (lane == 0) reds[warp] = amx;
        __syncthreads();
        if (tid == 0) {
            float m = reds[0];
            #pragma unroll
            for (int w = 1; w < 8; w++) m = fmaxf(m, reds[w]);
            atomicMax(amax, __float_as_uint(m));
        }
    }
}

// -------- fp32 fake-quant in place (cross path) --------
__global__ void quant_sym_kernel(float* __restrict__ x, long long n4,
                                 const unsigned* __restrict__ amaxbits)
{
    float delta = fmaxf(__uint_as_float(*amaxbits), 1e-8f) / 127.0f;
    long long stride = (long long)gridDim.x * blockDim.x;
    for (long long i = (long long)blockIdx.x * blockDim.x + threadIdx.x; i < n4; i += stride) {
        float4 v = *(float4*)(x + i * 4);
        float l;
        l = rintf(v.x/delta); l = fminf(fmaxf(l,-128.f),127.f); v.x = l*delta;
        l = rintf(v.y/delta); l = fminf(fmaxf(l,-128.f),127.f); v.y = l*delta;
        l = rintf(v.z/delta); l = fminf(fmaxf(l,-128.f),127.f); v.z = l*delta;
        l = rintf(v.w/delta); l = fminf(fmaxf(l,-128.f),127.f); v.w = l*delta;
        *(float4*)(x + i * 4) = v;
    }
}

// -------- s8 level quant: fp32 -> int8 levels (same layout) --------
__global__ void quant_s8_kernel(const float* __restrict__ x, int8_t* __restrict__ L,
                                long long n16, const unsigned* __restrict__ amaxbits)
{
    float delta = fmaxf(__uint_as_float(*amaxbits), 1e-8f) / 127.0f;
    float inv = 1.0f / delta;
    long long stride = (long long)gridDim.x * blockDim.x;
    for (long long i = (long long)blockIdx.x * blockDim.x + threadIdx.x; i < n16; i += stride) {
        const float4* p = (const float4*)(x + i * 16);
        uint4 o;
        o.x = pack_s8x4(p[0], inv);
        o.y = pack_s8x4(p[1], inv);
        o.z = pack_s8x4(p[2], inv);
        o.w = pack_s8x4(p[3], inv);
        *(uint4*)(L + i * 16) = o;
    }
}

// -------- V quant + per-head transpose: fp32 [b*seq][h*64+d] -> s8 [bh][d][seq] --------
__global__ void __launch_bounds__(256) quant_v_t_kernel(const float* __restrict__ V,
                                                        int8_t* __restrict__ LVT,
                                                        const unsigned* __restrict__ amaxbits)
{
    __shared__ int8_t T[64][80];
    float delta = fmaxf(__uint_as_float(*amaxbits), 1e-8f) / 127.0f;
    float inv = 1.0f / delta;
    int tid = threadIdx.x;
    int bh = blockIdx.y, b = bh / NH, h = bh % NH;
    int m0 = blockIdx.x * 64;
    #pragma unroll
    for (int i = 0; i < 4; i++) {
        int lin = tid + i * 256;          // 0..1023
        int r = lin >> 4;                 // m 0..63
        int c4 = (lin & 15) << 2;         // d
        float4 v = *(const float4*)(V + ((size_t)(b*NSEQ + m0 + r))*CDIM + h*DH + c4);
        T[c4+0][r] = (int8_t)clamp_i(__float2int_rn(v.x*inv), -128, 127);
        T[c4+1][r] = (int8_t)clamp_i(__float2int_rn(v.y*inv), -128, 127);
        T[c4+2][r] = (int8_t)clamp_i(__float2int_rn(v.z*inv), -128, 127);
        T[c4+3][r] = (int8_t)clamp_i(__float2int_rn(v.w*inv), -128, 127);
    }
    __syncthreads();
    int d = tid >> 2, ch = (tid & 3) << 4;
    int4 val = *(int4*)&T[d][ch];
    *(int4*)(LVT + ((size_t)(bh*DH + d))*NSEQ + m0 + ch) = val;
}

// ======== self-attn scores, int8 tensor cores: S = (dq*dk/8) * (Lq @ Lk^T) ========
// block: one bh, 128n x 128m. 8 warps: wn=warp&1 (64n), wm=warp>>1 (32m).
__global__ void __launch_bounds__(256) self_scores_i8_kernel(
    const int8_t* __restrict__ LQ, const int8_t* __restrict__ LK,
    float* __restrict__ S, const unsigned* __restrict__ am)
{
    __shared__ __align__(16) int8_t Qs[128][80];
    __shared__ __align__(16) int8_t Ks[128][80];
    float dq = fmaxf(__uint_as_float(am[0]), 1e-8f) / 127.0f;
    float dk = fmaxf(__uint_as_float(am[1]), 1e-8f) / 127.0f;
    float scale = dq * dk * 0.125f;
    int tid = threadIdx.x, lane = tid & 31, warp = tid >> 5;
    int bh = blockIdx.z, b = bh / NH, h = bh % NH;
    int n0 = blockIdx.x * 128, m0 = blockIdx.y * 128;

    #pragma unroll
    for (int i = 0; i < 2; i++) {
        int lin = tid + i * 256;
        int r = lin >> 2, ch = (lin & 3) << 4;
        *(int4*)&Qs[r][ch] = *(const int4*)(LQ + ((size_t)(b*NSEQ + n0 + r))*CDIM + h*DH + ch);
        *(int4*)&Ks[r][ch] = *(const int4*)(LK + ((size_t)(b*NSEQ + m0 + r))*CDIM + h*DH + ch);
    }
    __syncthreads();

    int wn = warp & 1, wm = warp >> 1;
    int gr = lane >> 2, gc = lane & 3;
    int acc[4][4][4];
    #pragma unroll
    for (int i = 0; i < 4; i++)
        #pragma unroll
        for (int j = 0; j < 4; j++)
            #pragma unroll
            for (int l = 0; l < 4; l++) acc[i][j][l] = 0;

    #pragma unroll
    for (int ks = 0; ks < 2; ks++) {
        uint32_t af[4][4], bf[4][2];
        #pragma unroll
        for (int nt = 0; nt < 4; nt++) {
            int row = wn * 64 + nt * 16 + gr;
            af[nt][0] = *(const uint32_t*)&Qs[row][ks*32 + gc*4];
            af[nt][1] = *(const uint32_t*)&Qs[row + 8][ks*32 + gc*4];
            af[nt][2] = *(const uint32_t*)&Qs[row][ks*32 + 16 + gc*4];
            af[nt][3] = *(const uint32_t*)&Qs[row + 8][ks*32 + 16 + gc*4];
        }
        #pragma unroll
        for (int mt = 0; mt < 4; mt++) {
            int col = wm * 32 + mt * 8 + gr;
            bf[mt][0] = *(const uint32_t*)&Ks[col][ks*32 + gc*4];
            bf[mt][1] = *(const uint32_t*)&Ks[col][ks*32 + 16 + gc*4];
        }
        #pragma unroll
        for (int nt = 0; nt < 4; nt++)
            #pragma unroll
            for (int mt = 0; mt < 4; mt++)
                mma_s8(acc[nt][mt], af[nt], bf[mt]);
    }

    #pragma unroll
    for (int nt = 0; nt < 4; nt++) {
        #pragma unroll
        for (int mt = 0; mt < 4; mt++) {
            int row0 = n0 + wn * 64 + nt * 16 + gr;
            int col0 = m0 + wm * 32 + mt * 8 + gc * 2;
            #pragma unroll
            for (int half = 0; half < 2; half++) {
                int row = row0 + half * 8;
                float2 o = {scale * (float)acc[nt][mt][half*2+0],
                            scale * (float)acc[nt][mt][half*2+1]};
                *(float2*)(S + ((size_t)bh*NSEQ + row)*NSEQ + col0) = o;
            }
        }
    }
}

// -------- softmax row stats; global max prob = max(1/Z) --------
__global__ void softmax_stats_kernel(const float* __restrict__ S, float* __restrict__ rowmax,
                                     float* __restrict__ rowz, unsigned* wmax, int cols, int stride)
{
    int row = blockIdx.x, tid = threadIdx.x;
    const float* s = S + (size_t)row * stride;
    __shared__ float red[8];
    float m = -3.4e38f;
    for (int i = tid; i < cols; i += 256) m = fmaxf(m, s[i]);
    #pragma unroll
    for (int o = 16; o; o >>= 1) m = fmaxf(m, __shfl_xor_sync(0xffffffffu, m, o));
    if ((tid & 31) == 0) red[tid >> 5] = m;
    __syncthreads();
    float mm = red[0];
    #pragma unroll
    for (int w = 1; w < 8; w++) mm = fmaxf(mm, red[w]);
    __syncthreads();
    float z = 0.f;
    for (int i = tid; i < cols; i += 256) z += __expf(s[i] - mm);
    #pragma unroll
    for (int o = 16; o; o >>= 1) z += __shfl_xor_sync(0xffffffffu, z, o);
    if ((tid & 31) == 0) red[tid >> 5] = z;
    __syncthreads();
    if (tid == 0) {
        float zz = 0.f;
        #pragma unroll
        for (int w = 0; w < 8; w++) zz += red[w];
        rowmax[row] = mm; rowz[row] = zz;
        atomicMax(wmax, __float_as_uint(1.0f / zz));
    }
}

// ======== self-attn PV, u8 x s8 tensor cores, fused fq_zero ========
// block: one bh, 128n x 64d. loop m chunks of 128. 8 warps: wn=warp&1, wd=warp>>1.
__global__ void __launch_bounds__(256) self_pv_i8_kernel(
    const float* __restrict__ S, const int8_t* __restrict__ LVT,
    const float* __restrict__ RM, const float* __restrict__ RZ,
    const unsigned* __restrict__ am, float* __restrict__ O)
{
    __shared__ __align__(16) uint8_t Lws[128][144];
    __shared__ __align__(16) int8_t  VTs[64][144];
    __shared__ float rmS[128], riS[128];
    float dv = fmaxf(__uint_as_float(am[2]), 1e-8f) / 127.0f;
    float dw = fmaxf(__uint_as_float(am[3]), 1e-8f) / 255.0f;
    float inv_dw = 1.0f / dw;
    float oscale = dw * dv;
    int tid = threadIdx.x, lane = tid & 31, warp = tid >> 5;
    int bh = blockIdx.y, b = bh / NH, h = bh % NH;
    int n0 = blockIdx.x * 128;
    if (tid < 128) {
        rmS[tid] = RM[(size_t)bh*NSEQ + n0 + tid];
        riS[tid] = 1.0f / RZ[(size_t)bh*NSEQ + n0 + tid];
    }
    int wn = warp & 1, wd = warp >> 1;
    int gr = lane >> 2, gc = lane & 3;
    int acc[4][2][4];
    #pragma unroll
    for (int i = 0; i < 4; i++)
        #pragma unroll
        for (int j = 0; j < 2; j++)
            #pragma unroll
            for (int l = 0; l < 4; l++) acc[i][j][l] = 0;

    for (int mc = 0; mc < 8; mc++) {
        __syncthreads();
        // quantize S tile 128n x 128m -> u8 levels
        #pragma unroll
        for (int i = 0; i < 16; i++) {
            int lin = tid + i * 256;
            int n = lin >> 5, w = lin & 31;
            float4 sv = *(const float4*)(S + ((size_t)bh*NSEQ + n0 + n)*NSEQ + mc*128 + w*4);
            float rm = rmS[n];
            float f = riS[n] * inv_dw;
            int l0 = min(255, __float2int_rn(__expf(sv.x - rm) * f));
            int l1 = min(255, __float2int_rn(__expf(sv.y - rm) * f));
            int l2 = min(255, __float2int_rn(__expf(sv.z - rm) * f));
            int l3 = min(255, __float2int_rn(__expf(sv.w - rm) * f));
            *(uint32_t*)&Lws[n][w*4] = (uint32_t)l0 | ((uint32_t)l1 << 8)
                                     | ((uint32_t)l2 << 16) | ((uint32_t)l3 << 24);
        }
        // load V^T tile 64d x 128m
        #pragma unroll
        for (int i = 0; i < 2; i++) {
            int lin = tid + i * 256;
            int d = lin >> 3, ch = (lin & 7) << 4;
            *(int4*)&VTs[d][ch] = *(const int4*)(LVT + ((size_t)(bh*DH + d))*NSEQ + mc*128 + ch);
        }
        __syncthreads();
        #pragma unroll
        for (int ks = 0; ks < 4; ks++) {
            uint32_t af[4][4], bf[2][2];
            #pragma unroll
            for (int nt = 0; nt < 4; nt++) {
                int row = wn * 64 + nt * 16 + gr;
                af[nt][0] = *(const uint32_t*)&Lws[row][ks*32 + gc*4];
                af[nt][1] = *(const uint32_t*)&Lws[row + 8][ks*32 + gc*4];
                af[nt][2] = *(const uint32_t*)&Lws[row][ks*32 + 16 + gc*4];
                af[nt][3] = *(const uint32_t*)&Lws[row + 8][ks*32 + 16 + gc*4];
            }
            #pragma unroll
            for (int dt = 0; dt < 2; dt++) {
                int col = wd * 16 + dt * 8 + gr;
                bf[dt][0] = *(const uint32_t*)&VTs[col][ks*32 + gc*4];
                bf[dt][1] = *(const uint32_t*)&VTs[col][ks*32 + 16 + gc*4];
            }
            #pragma unroll
            for (int nt = 0; nt < 4; nt++)
                #pragma unroll
                for (int dt = 0; dt < 2; dt++)
                    mma_u8s8(acc[nt][dt], af[nt], bf[dt]);
        }
    }
    #pragma unroll
    for (int nt = 0; nt < 4; nt++) {
        #pragma unroll
        for (int dt = 0; dt < 2; dt++) {
            int row0 = n0 + wn * 64 + nt * 16 + gr;
            int col0 = wd * 16 + dt * 8 + gc * 2;
            #pragma unroll
            for (int half = 0; half < 2; half++) {
                int row = row0 + half * 8;
                float2 o = {tf32r(oscale * (float)acc[nt][dt][half*2+0]),
                            tf32r(oscale * (float)acc[nt][dt][half*2+1])};
                *(float2*)(O + ((size_t)(b*NSEQ + row))*CDIM + h*DH + col0) = o;
            }
        }
    }
}

// -------- cross-attn scores (fp32, M=77, stride 80) --------
__global__ void __launch_bounds__(256) cross_scores_kernel(
    const float* __restrict__ q, const float* __restrict__ k, float* __restrict__ S)
{
    __shared__ __align__(16) float Qs[64][68];
    __shared__ __align__(16) float Ks[80][68];
    int tid = threadIdx.x;
    int bh = blockIdx.y, b = bh / NH, h = bh % NH;
    int n0 = blockIdx.x * 64;
    #pragma unroll
    for (int it = 0; it < 4; ++it) {
        int r = (tid >> 4) + it * 16, c = (tid & 15) << 2;
        float4 qv = *(const float4*)(q + ((size_t)(b*NSEQ + n0 + r))*CDIM + h*DH + c);
        Qs[c+0][r]=qv.x; Qs[c+1][r]=qv.y; Qs[c+2][r]=qv.z; Qs[c+3][r]=qv.w;
    }
    #pragma unroll
    for (int it = 0; it < 5; ++it) {
        int lin = tid + it * 256;
        if (lin < 80 * 16) {
            int r = lin >> 4, c = (lin & 15) << 2;
            float4 kv = (r < MCTX) ? *(const float4*)(k + ((size_t)(b*MCTX + r))*CDIM + h*DH + c)
                                   : make_float4(0.f,0.f,0.f,0.f);
            *(float4*)&Ks[r][c] = kv;
        }
    }
    __syncthreads();
    int tx = tid & 15, ty = tid >> 4;
    float acc[4][5];
    #pragma unroll
    for (int i = 0; i < 4; i++)
        #pragma unroll
        for (int j = 0; j < 5; j++) acc[i][j] = 0.f;
    #pragma unroll 4
    for (int d = 0; d < 64; ++d) {
        float4 q4 = *(const float4*)&Qs[d][ty*4];
        float qa[4]={q4.x,q4.y,q4.z,q4.w};
        #pragma unroll
        for (int jj = 0; jj < 5; jj++) {
            float kv = Ks[tx*5+jj][d];
            #pragma unroll
            for (int i = 0; i < 4; i++) acc[i][jj] = fmaf(qa[i], kv, acc[i][jj]);
        }
    }
    #pragma unroll
    for (int i = 0; i < 4; i++)
        #pragma unroll
        for (int jj = 0; jj < 5; jj++) {
            int m = tx * 5 + jj;
            if (m < MCTX)
                S[((size_t)bh*NSEQ + n0 + ty*4 + i)*80 + m] = acc[i][jj] * 0.125f;
        }
}

// -------- cross-attn PV (fp32) --------
__global__ void __launch_bounds__(256) cross_pv_kernel(
    const float* __restrict__ S, const float* __restrict__ v,
    const float* __restrict__ rowmax, const float* __restrict__ rowz,
    const unsigned* __restrict__ wmaxbits, float* __restrict__ O)
{
    __shared__ __align__(16) float Ws[80][68];
    __shared__ __align__(16) float Vs[80][68];
    int tid = threadIdx.x;
    int bh = blockIdx.y, b = bh / NH, h = bh % NH;
    int n0 = blockIdx.x * 64;
    int tx = tid & 15, ty = tid >> 4;
    float delta = fmaxf(__uint_as_float(*wmaxbits), 1e-8f) / 255.0f;
    float inv_delta = 1.0f / delta;
    #pragma unroll
    for (int it = 0; it < 5; ++it) {
        int lin = tid + it * 256;
        if (lin < MCTX * 16) {
            int r = lin >> 4, c = (lin & 15) << 2;
            *(float4*)&Vs[r][c] = *(const float4*)(v + ((size_t)(b*MCTX + r))*CDIM + h*DH + c);
        }
    }
    #pragma unroll
    for (int it = 0; it < 4; ++it) {
        int r = (tid >> 4) + it * 16;
        float rm = rowmax[(size_t)bh*NSEQ + n0 + r];
        float ri = 1.0f / rowz[(size_t)bh*NSEQ + n0 + r];
        #pragma unroll
        for (int jj = 0; jj < 5; jj++) {
            int m = (tid & 15) * 5 + jj;
            float w = 0.f;
            if (m < MCTX) {
                float s = S[((size_t)bh*NSEQ + n0 + r)*80 + m];
                float p = __expf(s - rm);
                float l = rintf(p * ri * inv_delta);
                l = fminf(fmaxf(l, 0.f), 255.f);
                w = l * delta;
            }
            Ws[m][r] = w;
        }
    }
    __syncthreads();
    float acc[4][4];
    #pragma unroll
    for (int i = 0; i < 4; i++)
        #pragma unroll
        for (int j = 0; j < 4; j++) acc[i][j] = 0.f;
    for (int m = 0; m < MCTX; m++) {
        float4 w4 = *(const float4*)&Ws[m][ty*4];
        float4 v4 = *(const float4*)&Vs[m][tx*4];
        float wa[4]={w4.x,w4.y,w4.z,w4.w}, va[4]={v4.x,v4.y,v4.z,v4.w};
        #pragma unroll
        for (int i = 0; i < 4; i++)
            #pragma unroll
            for (int j = 0; j < 4; j++) acc[i][j] = fmaf(wa[i], va[j], acc[i][j]);
    }
    #pragma unroll
    for (int i = 0; i < 4; i++) {
        float4 o = {tf32r(acc[i][0]), tf32r(acc[i][1]), tf32r(acc[i][2]), tf32r(acc[i][3])};
        *(float4*)(O + ((size_t)(b*NSEQ + n0 + ty*4 + i))*CDIM + h*DH + tx*4) = o;
    }
}

// -------- GEGLU (tf32-rounded out) --------
__global__ void geglu_kernel(const float* __restrict__ Hh, float* __restrict__ G)
{
    size_t n4 = (size_t)ROWS * FFD / 4;
    size_t stride = (size_t)gridDim.x * blockDim.x;
    for (size_t i = (size_t)blockIdx.x * blockDim.x + threadIdx.x; i < n4; i += stride) {
        size_t col4 = i % (FFD / 4), row = i / (FFD / 4);
        float4 a4 = *(const float4*)(Hh + row * FF2D + col4 * 4);
        float4 g4 = *(const float4*)(Hh + row * FF2D + FFD + col4 * 4);
        float4 o;
        o.x = tf32r(a4.x * gelu_tanh(g4.x)); o.y = tf32r(a4.y * gelu_tanh(g4.y));
        o.z = tf32r(a4.z * gelu_tanh(g4.z)); o.w = tf32r(a4.w * gelu_tanh(g4.w));
        *(float4*)(G + i * 4) = o;
    }
}

extern "C" void kernel_launch(void* const* d_in, const int* in_sizes, int n_in,
                              void* d_out, int out_size)
{
    const float* x    = (const float*)d_in[0];
    const float* ctx  = (const float*)d_in[1];
    const float* ln1g = (const float*)d_in[2];
    const float* ln1b = (const float*)d_in[3];
    const float* ln2g = (const float*)d_in[4];
    const float* ln2b = (const float*)d_in[5];
    const float* ln3g = (const float*)d_in[6];
    const float* ln3b = (const float*)d_in[7];
    const float* Wq1  = (const float*)d_in[8];
    const float* Wk1  = (const float*)d_in[9];
    const float* Wv1  = (const float*)d_in[10];
    const float* Wo1  = (const float*)d_in[11];
    const float* bo1  = (const float*)d_in[12];
    const float* Wq2  = (const float*)d_in[13];
    const float* Wk2  = (const float*)d_in[14];
    const float* Wv2  = (const float*)d_in[15];
    const float* Wo2  = (const float*)d_in[16];
    const float* bo2  = (const float*)d_in[17];
    const float* Wff1 = (const float*)d_in[18];
    const float* bff1 = (const float*)d_in[19];
    const float* Wff2 = (const float*)d_in[20];
    const float* bff2 = (const float*)d_in[21];
    float* out = (float*)d_out;

    float* sc = nullptr;
    cudaGetSymbolAddress((void**)&sc, g_scratch);
    float* XN = sc + OFF_XN;  float* Q  = sc + OFF_Q;
    float* K  = sc + OFF_K;   float* V  = sc + OFF_V;
    float* O  = sc + OFF_O;   float* X1 = sc + OFF_X1;
    float* S  = sc + OFF_S;   float* Hb = sc + OFF_H;
    float* G  = sc + OFF_G;   float* RM = sc + OFF_RM;
    float* RZ = sc + OFF_RZ;
    unsigned* AM = (unsigned*)(sc + OFF_AM);
    float* cWq1 = sc + OFF_WQ1; float* cWk1 = sc + OFF_WK1;
    float* cWv1 = sc + OFF_WV1; float* cWo1 = sc + OFF_WO1;
    float* cWq2 = sc + OFF_WQ2; float* cWo2 = sc + OFF_WO2;
    float* cWk2 = sc + OFF_WK2; float* cWv2 = sc + OFF_WV2;
    float* cWf1 = sc + OFF_WF1; float* cWf2 = sc + OFF_WF2;
    float* cCtx = sc + OFF_CTX;
    int8_t* LQ8 = (int8_t*)(sc + OFF_LQ8);
    int8_t* LK8 = (int8_t*)(sc + OFF_LK8);
    int8_t* LVT = (int8_t*)(sc + OFF_LVT);

    dim3 g1280(CDIM / 128, ROWS / 128);
    dim3 gcross(CDIM / 128, (CROSSROWS + 127) / 128);
    dim3 gff1(FF2D / 128, ROWS / 128);
    long long n4  = (long long)ROWS * CDIM / 4;
    long long n16 = (long long)ROWS * CDIM / 16;
    long long n4c = (long long)CROSSROWS * CDIM / 4;

    init_amax_kernel<<<1, 32>>>(AM);

    // ---- pre-convert weights + ctx to tf32 ----
    conv_tf32_kernel<<<1024,256>>>(Wq1,  cWq1, (long long)SZ_W1/4);
    conv_tf32_kernel<<<1024,256>>>(Wk1,  cWk1, (long long)SZ_W1/4);
    conv_tf32_kernel<<<1024,256>>>(Wv1,  cWv1, (long long)SZ_W1/4);
    conv_tf32_kernel<<<1024,256>>>(Wo1,  cWo1, (long long)SZ_W1/4);
    conv_tf32_kernel<<<1024,256>>>(Wq2,  cWq2, (long long)SZ_W1/4);
    conv_tf32_kernel<<<1024,256>>>(Wo2,  cWo2, (long long)SZ_W1/4);
    conv_tf32_kernel<<<1024,256>>>(Wk2,  cWk2, (long long)SZ_WK2/4);
    conv_tf32_kernel<<<1024,256>>>(Wv2,  cWv2, (long long)SZ_WK2/4);
    conv_tf32_kernel<<<2048,256>>>(Wff1, cWf1, (long long)SZ_WF1/4);
    conv_tf32_kernel<<<2048,256>>>(Wff2, cWf2, (long long)SZ_WF2/4);
    conv_tf32_kernel<<<512,256>>>(ctx,   cCtx, (long long)SZ_CTXB/4);

    // ---- block 1: self attention (int8 tensor-core path) ----
    ln_kernel<<<ROWS, 256>>>(x, ln1g, ln1b, XN);
    tgemm_kernel<false,false,true><<<g1280,256>>>(XN, cWq1, Q, ROWS, CDIM, CDIM, nullptr, nullptr, AM+0);
    tgemm_kernel<false,false,true><<<g1280,256>>>(XN, cWk1, K, ROWS, CDIM, CDIM, nullptr, nullptr, AM+1);
    tgemm_kernel<false,false,true><<<g1280,256>>>(XN, cWv1, V, ROWS, CDIM, CDIM, nullptr, nullptr, AM+2);
    quant_s8_kernel<<<1024,256>>>(Q, LQ8, n16, AM+0);
    quant_s8_kernel<<<1024,256>>>(K, LK8, n16, AM+1);
    quant_v_t_kernel<<<dim3(NSEQ/64, BHD),256>>>(V, LVT, AM+2);
    self_scores_i8_kernel<<<dim3(8,8,BHD),256>>>(LQ8, LK8, S, AM);
    softmax_stats_kernel<<<BHD*NSEQ,256>>>(S, RM, RZ, AM+3, NSEQ, NSEQ);
    self_pv_i8_kernel<<<dim3(8,BHD),256>>>(S, LVT, RM, RZ, AM, O);
    tgemm_kernel<true,true,false><<<g1280,256>>>(O, cWo1, X1, ROWS, CDIM, CDIM, bo1, x, nullptr);

    // ---- block 2: cross attention (fp32 path, small) ----
    ln_kernel<<<ROWS,256>>>(X1, ln2g, ln2b, XN);
    tgemm_kernel<false,false,true><<<g1280,256>>>(XN, cWq2, Q, ROWS, CDIM, CDIM, nullptr, nullptr, AM+4);
    tgemm_kernel<false,false,true><<<gcross,256>>>(cCtx, cWk2, K, CROSSROWS, CDIM, CTXC, nullptr, nullptr, AM+5);
    tgemm_kernel<false,false,true><<<gcross,256>>>(cCtx, cWv2, V, CROSSROWS, CDIM, CTXC, nullptr, nullptr, AM+6);
    quant_sym_kernel<<<2048,256>>>(Q, n4, AM+4);
    quant_sym_kernel<<<512,256>>>(K, n4c, AM+5);
    quant_sym_kernel<<<512,256>>>(V, n4c, AM+6);
    cross_scores_kernel<<<dim3(16,BHD),256>>>(Q, K, S);
    softmax_stats_kernel<<<BHD*NSEQ,256>>>(S, RM, RZ, AM+7, MCTX, 80);
    cross_pv_kernel<<<dim3(16,BHD),256>>>(S, V, RM, RZ, AM+7, O);
    tgemm_kernel<true,true,false><<<g1280,256>>>(O, cWo2, X1, ROWS, CDIM, CDIM, bo2, X1, nullptr);

    // ---- block 3: GEGLU FF ----
    ln_kernel<<<ROWS,256>>>(X1, ln3g, ln3b, XN);
    tgemm_kernel<true,false,false><<<gff1,256>>>(XN, cWf1, Hb, ROWS, FF2D, CDIM, bff1, nullptr, nullptr);
    geglu_kernel<<<4096,256>>>(Hb, G);
    tgemm_kernel<true,true,false><<<g1280,256>>>(G, cWf2, out, ROWS, CDIM, FFD, bff2, X1, nullptr);
}

// round 7
// speedup vs baseline: 2.9040x; 1.0682x over previous
#include <cuda_runtime.h>
#include <cstdint>

#define NB 8
#define NSEQ 1024
#define CDIM 1280
#define NH 20
#define DH 64
#define MCTX 77
#define CTXC 768
#define FFD 5120
#define FF2D 10240
#define ROWS (NB*NSEQ)
#define BHD (NB*NH)
#define CROSSROWS (NB*MCTX)

static constexpr size_t SZ_XC = (size_t)ROWS * CDIM;
static constexpr size_t OFF_XN = 0;
static constexpr size_t OFF_Q  = OFF_XN + SZ_XC;
static constexpr size_t OFF_K  = OFF_Q + SZ_XC;
static constexpr size_t OFF_V  = OFF_K + SZ_XC;
static constexpr size_t OFF_O  = OFF_V + SZ_XC;
static constexpr size_t OFF_X1 = OFF_O + SZ_XC;
static constexpr size_t OFF_S  = OFF_X1 + SZ_XC;
static constexpr size_t SZ_S   = (size_t)BHD * NSEQ * NSEQ;
static constexpr size_t OFF_H  = OFF_S + SZ_S;
static constexpr size_t SZ_H   = (size_t)ROWS * FF2D;
static constexpr size_t OFF_G  = OFF_H + SZ_H;
static constexpr size_t SZ_G   = (size_t)ROWS * FFD;
static constexpr size_t OFF_RM = OFF_G + SZ_G;
static constexpr size_t OFF_RZ = OFF_RM + (size_t)BHD * NSEQ;
static constexpr size_t OFF_AM = OFF_RZ + (size_t)BHD * NSEQ;
static constexpr size_t SZ_W1  = (size_t)CDIM * CDIM;
static constexpr size_t SZ_WK2 = (size_t)CTXC * CDIM;
static constexpr size_t SZ_WF1 = (size_t)CDIM * FF2D;
static constexpr size_t SZ_WF2 = (size_t)FFD * CDIM;
static constexpr size_t SZ_CTXB = (size_t)CROSSROWS * CTXC;
static constexpr size_t OFF_WQ1 = OFF_AM + 8;
static constexpr size_t OFF_WK1 = OFF_WQ1 + SZ_W1;
static constexpr size_t OFF_WV1 = OFF_WK1 + SZ_W1;
static constexpr size_t OFF_WO1 = OFF_WV1 + SZ_W1;
static constexpr size_t OFF_WQ2 = OFF_WO1 + SZ_W1;
static constexpr size_t OFF_WO2 = OFF_WQ2 + SZ_W1;
static constexpr size_t OFF_WK2 = OFF_WO2 + SZ_W1;
static constexpr size_t OFF_WV2 = OFF_WK2 + SZ_WK2;
static constexpr size_t OFF_WF1 = OFF_WV2 + SZ_WK2;
static constexpr size_t OFF_WF2 = OFF_WF1 + SZ_WF1;
static constexpr size_t OFF_CTX = OFF_WF2 + SZ_WF2;
static constexpr size_t SZ_S8F  = (size_t)ROWS * CDIM / 4;
static constexpr size_t OFF_LQ8 = OFF_CTX + SZ_CTXB;
static constexpr size_t OFF_LK8 = OFF_LQ8 + SZ_S8F;
static constexpr size_t OFF_LVT = OFF_LK8 + SZ_S8F;
static constexpr size_t TOTAL_SCRATCH = OFF_LVT + SZ_S8F;

__device__ __align__(256) float g_scratch[TOTAL_SCRATCH];

__global__ void init_amax_kernel(unsigned* amax) {
    if (threadIdx.x < 8) amax[threadIdx.x] = 0u;
}

__device__ __forceinline__ float gelu_tanh(float x) {
    float x3 = x * x * x;
    return 0.5f * x * (1.0f + tanhf(0.7978845608028654f * (x + 0.044715f * x3)));
}

__device__ __forceinline__ uint32_t f2tf32(float f) {
    uint32_t r;
    asm("cvt.rna.tf32.f32 %0, %1;" : "=r"(r) : "f"(f));
    return r;
}
__device__ __forceinline__ float tf32r(float f) { return __uint_as_float(f2tf32(f)); }

__device__ __forceinline__ void mma_tf32(float* d, const uint32_t* a, const uint32_t* b) {
    asm volatile("mma.sync.aligned.m16n8k8.row.col.f32.tf32.tf32.f32 "
        "{%0,%1,%2,%3}, {%4,%5,%6,%7}, {%8,%9}, {%0,%1,%2,%3};"
        : "+f"(d[0]), "+f"(d[1]), "+f"(d[2]), "+f"(d[3])
        : "r"(a[0]), "r"(a[1]), "r"(a[2]), "r"(a[3]), "r"(b[0]), "r"(b[1]));
}

__device__ __forceinline__ void mma_s8(int* d, const uint32_t* a, const uint32_t* b) {
    asm volatile("mma.sync.aligned.m16n8k32.row.col.s32.s8.s8.s32 "
        "{%0,%1,%2,%3}, {%4,%5,%6,%7}, {%8,%9}, {%0,%1,%2,%3};"
        : "+r"(d[0]), "+r"(d[1]), "+r"(d[2]), "+r"(d[3])
        : "r"(a[0]), "r"(a[1]), "r"(a[2]), "r"(a[3]), "r"(b[0]), "r"(b[1]));
}

__device__ __forceinline__ void mma_u8s8(int* d, const uint32_t* a, const uint32_t* b) {
    asm volatile("mma.sync.aligned.m16n8k32.row.col.s32.u8.s8.s32 "
        "{%0,%1,%2,%3}, {%4,%5,%6,%7}, {%8,%9}, {%0,%1,%2,%3};"
        : "+r"(d[0]), "+r"(d[1]), "+r"(d[2]), "+r"(d[3])
        : "r"(a[0]), "r"(a[1]), "r"(a[2]), "r"(a[3]), "r"(b[0]), "r"(b[1]));
}

__device__ __forceinline__ void ldsm4(uint32_t& r0, uint32_t& r1, uint32_t& r2, uint32_t& r3,
                                      uint32_t addr) {
    asm volatile("ldmatrix.sync.aligned.m8n8.x4.shared.b16 {%0,%1,%2,%3}, [%4];"
        : "=r"(r0), "=r"(r1), "=r"(r2), "=r"(r3) : "r"(addr));
}

__device__ __forceinline__ void cp_async16(uint32_t dst, const void* src, int srcsize) {
    asm volatile("cp.async.cg.shared.global [%0], [%1], 16, %2;"
                 :: "r"(dst), "l"(src), "r"(srcsize));
}

__device__ __forceinline__ int clamp_i(int v, int lo, int hi) {
    return v < lo ? lo : (v > hi ? hi : v);
}

__device__ __forceinline__ uint32_t pack_s8x4(float4 v, float inv) {
    int a = clamp_i(__float2int_rn(v.x * inv), -128, 127);
    int b = clamp_i(__float2int_rn(v.y * inv), -128, 127);
    int c = clamp_i(__float2int_rn(v.z * inv), -128, 127);
    int d = clamp_i(__float2int_rn(v.w * inv), -128, 127);
    return (a & 255) | ((b & 255) << 8) | ((c & 255) << 16) | ((d & 255) << 24);
}

// -------- merged tf32 pre-convert: one launch, 11 jobs --------
#define NCONV 11
struct ConvJobs {
    const float* src[NCONV];
    float* dst[NCONV];
    long long n4[NCONV];
};
__global__ void conv_tf32_multi(ConvJobs j) {
    int y = blockIdx.y;
    const float* s = j.src[y];
    float* d = j.dst[y];
    long long n4 = j.n4[y];
    long long stride = (long long)gridDim.x * blockDim.x;
    for (long long i = (long long)blockIdx.x * blockDim.x + threadIdx.x; i < n4; i += stride) {
        float4 v = *(const float4*)(s + i * 4);
        v.x = tf32r(v.x); v.y = tf32r(v.y); v.z = tf32r(v.z); v.w = tf32r(v.w);
        *(float4*)(d + i * 4) = v;
    }
}

// ---------------- LayerNorm (tf32-rounded out) ----------------
__global__ void ln_kernel(const float* __restrict__ x, const float* __restrict__ g,
                          const float* __restrict__ bta, float* __restrict__ out)
{
    __shared__ float sx[CDIM];
    __shared__ float red[8];
    int row = blockIdx.x, tid = threadIdx.x;
    const float* xr = x + (size_t)row * CDIM;
    float s = 0.f;
    for (int i = tid; i < CDIM; i += 256) { float v = xr[i]; sx[i] = v; s += v; }
    #pragma unroll
    for (int o = 16; o; o >>= 1) s += __shfl_xor_sync(0xffffffffu, s, o);
    if ((tid & 31) == 0) red[tid >> 5] = s;
    __syncthreads();
    float tot = 0.f;
    #pragma unroll
    for (int w = 0; w < 8; w++) tot += red[w];
    float mean = tot * (1.0f / (float)CDIM);
    float vs = 0.f;
    for (int i = tid; i < CDIM; i += 256) { float d = sx[i] - mean; vs += d * d; }
    __syncthreads();
    #pragma unroll
    for (int o = 16; o; o >>= 1) vs += __shfl_xor_sync(0xffffffffu, vs, o);
    if ((tid & 31) == 0) red[tid >> 5] = vs;
    __syncthreads();
    float tot2 = 0.f;
    #pragma unroll
    for (int w = 0; w < 8; w++) tot2 += red[w];
    float rstd = rsqrtf(tot2 * (1.0f / (float)CDIM) + 1e-5f);
    for (int i = tid; i < CDIM; i += 256)
        out[(size_t)row * CDIM + i] = tf32r((sx[i] - mean) * rstd * g[i] + bta[i]);
}

// ============ TF32 GEMM: cp.async 3-stage, ONE barrier/ktile, exact group accounting ============
template<bool HAS_BIAS, bool HAS_RES, bool DO_AMAX>
__global__ void __launch_bounds__(256, 2) tgemm_kernel(
    const float* __restrict__ A, const float* __restrict__ Bm, float* __restrict__ Cm,
    int Mn, int Nn, int Kn,
    const float* __restrict__ bias, const float* __restrict__ res, unsigned* amax)
{
    constexpr int ST = 3;
    constexpr uint32_t ABYTES = 128 * 20 * 4;
    constexpr uint32_t BBYTES = 16 * 136 * 4;
    __shared__ __align__(16) uint32_t As[ST][128][20];
    __shared__ __align__(16) float    Bs[ST][16][136];
    __shared__ float reds[8];

    int tid  = threadIdx.x;
    int lane = tid & 31;
    int warp = tid >> 5;
    int wm = warp & 1;
    int wn = warp >> 1;
    int nBase = blockIdx.x * 128;
    int mBase = blockIdx.y * 128;

    uint32_t asmb = (uint32_t)__cvta_generic_to_shared(&As[0][0][0]);
    uint32_t bsmb = (uint32_t)__cvta_generic_to_shared(&Bs[0][0][0]);

    const int aR0 = tid >> 2;
    const int aC  = (tid & 3) << 2;
    const int bK0 = tid >> 5;
    const int bN  = (tid & 31) << 2;

    int r8 = lane & 7, sel = lane >> 3;
    uint32_t aoff = asmb + (((wm * 64 + r8 + ((sel & 1) << 3)) * 20 + ((sel >> 1) << 2)) << 2);

    float acc[4][4][4];
    #pragma unroll
    for (int i = 0; i < 4; i++)
        #pragma unroll
        for (int j = 0; j < 4; j++)
            #pragma unroll
            for (int l = 0; l < 4; l++) acc[i][j][l] = 0.f;

    int KT = Kn >> 4;

    auto issue_stage = [&](int s, int k0) {
        #pragma unroll
        for (int i = 0; i < 2; i++) {
            int r = aR0 + i * 64;
            int gr = mBase + r;
            int ok = (gr < Mn);
            const float* src = A + (size_t)(ok ? gr : 0) * Kn + k0 + aC;
            cp_async16(asmb + s * ABYTES + ((r * 20 + aC) << 2), src, ok ? 16 : 0);
        }
        #pragma unroll
        for (int i = 0; i < 2; i++) {
            int kr = bK0 + i * 8;
            const float* src = Bm + (size_t)(k0 + kr) * Nn + nBase + bN;
            cp_async16(bsmb + s * BBYTES + ((kr * 136 + bN) << 2), src, 16);
        }
        asm volatile("cp.async.commit_group;" ::: "memory");
    };

    issue_stage(0, 0);
    issue_stage(1, 16);

    int lr = lane >> 2, lc = lane & 3;
    for (int kt = 0; kt < KT; ++kt) {
        int buf = kt % ST;
        asm volatile("cp.async.wait_group 1;" ::: "memory");
        __syncthreads();
        // issue AFTER the barrier: every warp has finished reading stage (kt-1)%3,
        // which is exactly the stage (kt+2)%3 overwritten here. No tail barrier needed.
        if (kt + 2 < KT) issue_stage((kt + 2) % ST, (kt + 2) << 4);
        else asm volatile("cp.async.commit_group;" ::: "memory"); // keep group count exact

        uint32_t abuf = aoff + buf * ABYTES;
        #pragma unroll
        for (int ks = 0; ks < 2; ks++) {
            uint32_t af[4][4], bf[4][2];
            #pragma unroll
            for (int mt = 0; mt < 4; mt++)
                ldsm4(af[mt][0], af[mt][1], af[mt][2], af[mt][3],
                      abuf + mt * (16 * 20 * 4) + ks * 32);
            #pragma unroll
            for (int nt = 0; nt < 4; nt++) {
                int col = wn * 32 + nt * 8 + lr;
                bf[nt][0] = __float_as_uint(Bs[buf][ks * 8 + lc][col]);
                bf[nt][1] = __float_as_uint(Bs[buf][ks * 8 + lc + 4][col]);
            }
            #pragma unroll
            for (int mt = 0; mt < 4; mt++)
                #pragma unroll
                for (int nt = 0; nt < 4; nt++)
                    mma_tf32(acc[mt][nt], af[mt], bf[nt]);
        }
    }

    float amx = 0.f;
    #pragma unroll
    for (int mt = 0; mt < 4; mt++) {
        #pragma unroll
        for (int nt = 0; nt < 4; nt++) {
            int row0 = mBase + wm * 64 + mt * 16 + lr;
            int col0 = nBase + wn * 32 + nt * 8 + lc * 2;
            #pragma unroll
            for (int half = 0; half < 2; half++) {
                int row = row0 + half * 8;
                if (row < Mn) {
                    float c0 = acc[mt][nt][half * 2 + 0];
                    float c1 = acc[mt][nt][half * 2 + 1];
                    if (HAS_BIAS) { c0 += bias[col0]; c1 += bias[col0 + 1]; }
                    if (HAS_RES) {
                        c0 += res[(size_t)row * Nn + col0];
                        c1 += res[(size_t)row * Nn + col0 + 1];
                    }
                    float2 o = {c0, c1};
                    *(float2*)(Cm + (size_t)row * Nn + col0) = o;
                    if (DO_AMAX) amx = fmaxf(amx, fmaxf(fabsf(c0), fabsf(c1)));
                }
            }
        }
    }
    if (DO_AMAX) {
        #pragma unroll
        for (int o = 16; o; o >>= 1) amx = fmaxf(amx, __shfl_xor_sync(0xffffffffu, amx, o));
        if (lane == 0) reds[warp] = amx;
        __syncthreads();
        if (tid == 0) {
            float m = reds[0];
            #pragma unroll
            for (int w = 1; w < 8; w++) m = fmaxf(m, reds[w]);
            atomicMax(amax, __float_as_uint(m));
        }
    }
}

// -------- fp32 fake-quant in place (cross path) --------
__global__ void quant_sym_kernel(float* __restrict__ x, long long n4,
                                 const unsigned* __restrict__ amaxbits)
{
    float delta = fmaxf(__uint_as_float(*amaxbits), 1e-8f) / 127.0f;
    long long stride = (long long)gridDim.x * blockDim.x;
    for (long long i = (long long)blockIdx.x * blockDim.x + threadIdx.x; i < n4; i += stride) {
        float4 v = *(float4*)(x + i * 4);
        float l;
        l = rintf(v.x/delta); l = fminf(fmaxf(l,-128.f),127.f); v.x = l*delta;
        l = rintf(v.y/delta); l = fminf(fmaxf(l,-128.f),127.f); v.y = l*delta;
        l = rintf(v.z/delta); l = fminf(fmaxf(l,-128.f),127.f); v.z = l*delta;
        l = rintf(v.w/delta); l = fminf(fmaxf(l,-128.f),127.f); v.w = l*delta;
        *(float4*)(x + i * 4) = v;
    }
}

// -------- s8 level quant --------
__global__ void quant_s8_kernel(const float* __restrict__ x, int8_t* __restrict__ L,
                                long long n16, const unsigned* __restrict__ amaxbits)
{
    float delta = fmaxf(__uint_as_float(*amaxbits), 1e-8f) / 127.0f;
    float inv = 1.0f / delta;
    long long stride = (long long)gridDim.x * blockDim.x;
    for (long long i = (long long)blockIdx.x * blockDim.x + threadIdx.x; i < n16; i += stride) {
        const float4* p = (const float4*)(x + i * 16);
        uint4 o;
        o.x = pack_s8x4(p[0], inv);
        o.y = pack_s8x4(p[1], inv);
        o.z = pack_s8x4(p[2], inv);
        o.w = pack_s8x4(p[3], inv);
        *(uint4*)(L + i * 16) = o;
    }
}

// -------- V quant + per-head transpose --------
__global__ void __launch_bounds__(256) quant_v_t_kernel(const float* __restrict__ V,
                                                        int8_t* __restrict__ LVT,
                                                        const unsigned* __restrict__ amaxbits)
{
    __shared__ int8_t T[64][80];
    float delta = fmaxf(__uint_as_float(*amaxbits), 1e-8f) / 127.0f;
    float inv = 1.0f / delta;
    int tid = threadIdx.x;
    int bh = blockIdx.y, b = bh / NH, h = bh % NH;
    int m0 = blockIdx.x * 64;
    #pragma unroll
    for (int i = 0; i < 4; i++) {
        int lin = tid + i * 256;
        int r = lin >> 4;
        int c4 = (lin & 15) << 2;
        float4 v = *(const float4*)(V + ((size_t)(b*NSEQ + m0 + r))*CDIM + h*DH + c4);
        T[c4+0][r] = (int8_t)clamp_i(__float2int_rn(v.x*inv), -128, 127);
        T[c4+1][r] = (int8_t)clamp_i(__float2int_rn(v.y*inv), -128, 127);
        T[c4+2][r] = (int8_t)clamp_i(__float2int_rn(v.z*inv), -128, 127);
        T[c4+3][r] = (int8_t)clamp_i(__float2int_rn(v.w*inv), -128, 127);
    }
    __syncthreads();
    int d = tid >> 2, ch = (tid & 3) << 4;
    int4 val = *(int4*)&T[d][ch];
    *(int4*)(LVT + ((size_t)(bh*DH + d))*NSEQ + m0 + ch) = val;
}

// ======== self-attn scores, int8 tensor cores ========
__global__ void __launch_bounds__(256) self_scores_i8_kernel(
    const int8_t* __restrict__ LQ, const int8_t* __restrict__ LK,
    float* __restrict__ S, const unsigned* __restrict__ am)
{
    __shared__ __align__(16) int8_t Qs[128][80];
    __shared__ __align__(16) int8_t Ks[128][80];
    float dq = fmaxf(__uint_as_float(am[0]), 1e-8f) / 127.0f;
    float dk = fmaxf(__uint_as_float(am[1]), 1e-8f) / 127.0f;
    float scale = dq * dk * 0.125f;
    int tid = threadIdx.x, lane = tid & 31, warp = tid >> 5;
    int bh = blockIdx.z, b = bh / NH, h = bh % NH;
    int n0 = blockIdx.x * 128, m0 = blockIdx.y * 128;

    #pragma unroll
    for (int i = 0; i < 2; i++) {
        int lin = tid + i * 256;
        int r = lin >> 2, ch = (lin & 3) << 4;
        *(int4*)&Qs[r][ch] = *(const int4*)(LQ + ((size_t)(b*NSEQ + n0 + r))*CDIM + h*DH + ch);
        *(int4*)&Ks[r][ch] = *(const int4*)(LK + ((size_t)(b*NSEQ + m0 + r))*CDIM + h*DH + ch);
    }
    __syncthreads();

    int wn = warp & 1, wm = warp >> 1;
    int gr = lane >> 2, gc = lane & 3;
    int acc[4][4][4];
    #pragma unroll
    for (int i = 0; i < 4; i++)
        #pragma unroll
        for (int j = 0; j < 4; j++)
            #pragma unroll
            for (int l = 0; l < 4; l++) acc[i][j][l] = 0;

    #pragma unroll
    for (int ks = 0; ks < 2; ks++) {
        uint32_t af[4][4], bf[4][2];
        #pragma unroll
        for (int nt = 0; nt < 4; nt++) {
            int row = wn * 64 + nt * 16 + gr;
            af[nt][0] = *(const uint32_t*)&Qs[row][ks*32 + gc*4];
            af[nt][1] = *(const uint32_t*)&Qs[row + 8][ks*32 + gc*4];
            af[nt][2] = *(const uint32_t*)&Qs[row][ks*32 + 16 + gc*4];
            af[nt][3] = *(const uint32_t*)&Qs[row + 8][ks*32 + 16 + gc*4];
        }
        #pragma unroll
        for (int mt = 0; mt < 4; mt++) {
            int col = wm * 32 + mt * 8 + gr;
            bf[mt][0] = *(const uint32_t*)&Ks[col][ks*32 + gc*4];
            bf[mt][1] = *(const uint32_t*)&Ks[col][ks*32 + 16 + gc*4];
        }
        #pragma unroll
        for (int nt = 0; nt < 4; nt++)
            #pragma unroll
            for (int mt = 0; mt < 4; mt++)
                mma_s8(acc[nt][mt], af[nt], bf[mt]);
    }

    #pragma unroll
    for (int nt = 0; nt < 4; nt++) {
        #pragma unroll
        for (int mt = 0; mt < 4; mt++) {
            int row0 = n0 + wn * 64 + nt * 16 + gr;
            int col0 = m0 + wm * 32 + mt * 8 + gc * 2;
            #pragma unroll
            for (int half = 0; half < 2; half++) {
                int row = row0 + half * 8;
                float2 o = {scale * (float)acc[nt][mt][half*2+0],
                            scale * (float)acc[nt][mt][half*2+1]};
                *(float2*)(S + ((size_t)bh*NSEQ + row)*NSEQ + col0) = o;
            }
        }
    }
}

// -------- softmax row stats --------
__global__ void softmax_stats_kernel(const float* __restrict__ S, float* __restrict__ rowmax,
                                     float* __restrict__ rowz, unsigned* wmax, int cols, int stride)
{
    int row = blockIdx.x, tid = threadIdx.x;
    const float* s = S + (size_t)row * stride;
    __shared__ float red[8];
    float m = -3.4e38f;
    for (int i = tid; i < cols; i += 256) m = fmaxf(m, s[i]);
    #pragma unroll
    for (int o = 16; o; o >>= 1) m = fmaxf(m, __shfl_xor_sync(0xffffffffu, m, o));
    if ((tid & 31) == 0) red[tid >> 5] = m;
    __syncthreads();
    float mm = red[0];
    #pragma unroll
    for (int w = 1; w < 8; w++) mm = fmaxf(mm, red[w]);
    __syncthreads();
    float z = 0.f;
    for (int i = tid; i < cols; i += 256) z += __expf(s[i] - mm);
    #pragma unroll
    for (int o = 16; o; o >>= 1) z += __shfl_xor_sync(0xffffffffu, z, o);
    if ((tid & 31) == 0) red[tid >> 5] = z;
    __syncthreads();
    if (tid == 0) {
        float zz = 0.f;
        #pragma unroll
        for (int w = 0; w < 8; w++) zz += red[w];
        rowmax[row] = mm; rowz[row] = zz;
        atomicMax(wmax, __float_as_uint(1.0f / zz));
    }
}

// ======== self-attn PV, u8 x s8 tensor cores ========
__global__ void __launch_bounds__(256) self_pv_i8_kernel(
    const float* __restrict__ S, const int8_t* __restrict__ LVT,
    const float* __restrict__ RM, const float* __restrict__ RZ,
    const unsigned* __restrict__ am, float* __restrict__ O)
{
    __shared__ __align__(16) uint8_t Lws[128][144];
    __shared__ __align__(16) int8_t  VTs[64][144];
    __shared__ float rmS[128], riS[128];
    float dv = fmaxf(__uint_as_float(am[2]), 1e-8f) / 127.0f;
    float dw = fmaxf(__uint_as_float(am[3]), 1e-8f) / 255.0f;
    float inv_dw = 1.0f / dw;
    float oscale = dw * dv;
    int tid = threadIdx.x, lane = tid & 31, warp = tid >> 5;
    int bh = blockIdx.y, b = bh / NH, h = bh % NH;
    int n0 = blockIdx.x * 128;
    if (tid < 128) {
        rmS[tid] = RM[(size_t)bh*NSEQ + n0 + tid];
        riS[tid] = 1.0f / RZ[(size_t)bh*NSEQ + n0 + tid];
    }
    int wn = warp & 1, wd = warp >> 1;
    int gr = lane >> 2, gc = lane & 3;
    int acc[4][2][4];
    #pragma unroll
    for (int i = 0; i < 4; i++)
        #pragma unroll
        for (int j = 0; j < 2; j++)
            #pragma unroll
            for (int l = 0; l < 4; l++) acc[i][j][l] = 0;

    for (int mc = 0; mc < 8; mc++) {
        __syncthreads();
        #pragma unroll
        for (int i = 0; i < 16; i++) {
            int lin = tid + i * 256;
            int n = lin >> 5, w = lin & 31;
            float4 sv = *(const float4*)(S + ((size_t)bh*NSEQ + n0 + n)*NSEQ + mc*128 + w*4);
            float rm = rmS[n];
            float f = riS[n] * inv_dw;
            int l0 = min(255, __float2int_rn(__expf(sv.x - rm) * f));
            int l1 = min(255, __float2int_rn(__expf(sv.y - rm) * f));
            int l2 = min(255, __float2int_rn(__expf(sv.z - rm) * f));
            int l3 = min(255, __float2int_rn(__expf(sv.w - rm) * f));
            *(uint32_t*)&Lws[n][w*4] = (uint32_t)l0 | ((uint32_t)l1 << 8)
                                     | ((uint32_t)l2 << 16) | ((uint32_t)l3 << 24);
        }
        #pragma unroll
        for (int i = 0; i < 2; i++) {
            int lin = tid + i * 256;
            int d = lin >> 3, ch = (lin & 7) << 4;
            *(int4*)&VTs[d][ch] = *(const int4*)(LVT + ((size_t)(bh*DH + d))*NSEQ + mc*128 + ch);
        }
        __syncthreads();
        #pragma unroll
        for (int ks = 0; ks < 4; ks++) {
            uint32_t af[4][4], bf[2][2];
            #pragma unroll
            for (int nt = 0; nt < 4; nt++) {
                int row = wn * 64 + nt * 16 + gr;
                af[nt][0] = *(const uint32_t*)&Lws[row][ks*32 + gc*4];
                af[nt][1] = *(const uint32_t*)&Lws[row + 8][ks*32 + gc*4];
                af[nt][2] = *(const uint32_t*)&Lws[row][ks*32 + 16 + gc*4];
                af[nt][3] = *(const uint32_t*)&Lws[row + 8][ks*32 + 16 + gc*4];
            }
            #pragma unroll
            for (int dt = 0; dt < 2; dt++) {
                int col = wd * 16 + dt * 8 + gr;
                bf[dt][0] = *(const uint32_t*)&VTs[col][ks*32 + gc*4];
                bf[dt][1] = *(const uint32_t*)&VTs[col][ks*32 + 16 + gc*4];
            }
            #pragma unroll
            for (int nt = 0; nt < 4; nt++)
                #pragma unroll
                for (int dt = 0; dt < 2; dt++)
                    mma_u8s8(acc[nt][dt], af[nt], bf[dt]);
        }
    }
    #pragma unroll
    for (int nt = 0; nt < 4; nt++) {
        #pragma unroll
        for (int dt = 0; dt < 2; dt++) {
            int row0 = n0 + wn * 64 + nt * 16 + gr;
            int col0 = wd * 16 + dt * 8 + gc * 2;
            #pragma unroll
            for (int half = 0; half < 2; half++) {
                int row = row0 + half * 8;
                float2 o = {tf32r(oscale * (float)acc[nt][dt][half*2+0]),
                            tf32r(oscale * (float)acc[nt][dt][half*2+1])};
                *(float2*)(O + ((size_t)(b*NSEQ + row))*CDIM + h*DH + col0) = o;
            }
        }
    }
}

// -------- cross-attn scores (fp32, M=77, stride 80) --------
__global__ void __launch_bounds__(256) cross_scores_kernel(
    const float* __restrict__ q, const float* __restrict__ k, float* __restrict__ S)
{
    __shared__ __align__(16) float Qs[64][68];
    __shared__ __align__(16) float Ks[80][68];
    int tid = threadIdx.x;
    int bh = blockIdx.y, b = bh / NH, h = bh % NH;
    int n0 = blockIdx.x * 64;
    #pragma unroll
    for (int it = 0; it < 4; ++it) {
        int r = (tid >> 4) + it * 16, c = (tid & 15) << 2;
        float4 qv = *(const float4*)(q + ((size_t)(b*NSEQ + n0 + r))*CDIM + h*DH + c);
        Qs[c+0][r]=qv.x; Qs[c+1][r]=qv.y; Qs[c+2][r]=qv.z; Qs[c+3][r]=qv.w;
    }
    #pragma unroll
    for (int it = 0; it < 5; ++it) {
        int lin = tid + it * 256;
        if (lin < 80 * 16) {
            int r = lin >> 4, c = (lin & 15) << 2;
            float4 kv = (r < MCTX) ? *(const float4*)(k + ((size_t)(b*MCTX + r))*CDIM + h*DH + c)
                                   : make_float4(0.f,0.f,0.f,0.f);
            *(float4*)&Ks[r][c] = kv;
        }
    }
    __syncthreads();
    int tx = tid & 15, ty = tid >> 4;
    float acc[4][5];
    #pragma unroll
    for (int i = 0; i < 4; i++)
        #pragma unroll
        for (int j = 0; j < 5; j++) acc[i][j] = 0.f;
    #pragma unroll 4
    for (int d = 0; d < 64; ++d) {
        float4 q4 = *(const float4*)&Qs[d][ty*4];
        float qa[4]={q4.x,q4.y,q4.z,q4.w};
        #pragma unroll
        for (int jj = 0; jj < 5; jj++) {
            float kv = Ks[tx*5+jj][d];
            #pragma unroll
            for (int i = 0; i < 4; i++) acc[i][jj] = fmaf(qa[i], kv, acc[i][jj]);
        }
    }
    #pragma unroll
    for (int i = 0; i < 4; i++)
        #pragma unroll
        for (int jj = 0; jj < 5; jj++) {
            int m = tx * 5 + jj;
            if (m < MCTX)
                S[((size_t)bh*NSEQ + n0 + ty*4 + i)*80 + m] = acc[i][jj] * 0.125f;
        }
}

// -------- cross-attn PV (fp32) --------
__global__ void __launch_bounds__(256) cross_pv_kernel(
    const float* __restrict__ S, const float* __restrict__ v,
    const float* __restrict__ rowmax, const float* __restrict__ rowz,
    const unsigned* __restrict__ wmaxbits, float* __restrict__ O)
{
    __shared__ __align__(16) float Ws[80][68];
    __shared__ __align__(16) float Vs[80][68];
    int tid = threadIdx.x;
    int bh = blockIdx.y, b = bh / NH, h = bh % NH;
    int n0 = blockIdx.x * 64;
    int tx = tid & 15, ty = tid >> 4;
    float delta = fmaxf(__uint_as_float(*wmaxbits), 1e-8f) / 255.0f;
    float inv_delta = 1.0f / delta;
    #pragma unroll
    for (int it = 0; it < 5; ++it) {
        int lin = tid + it * 256;
        if (lin < MCTX * 16) {
            int r = lin >> 4, c = (lin & 15) << 2;
            *(float4*)&Vs[r][c] = *(const float4*)(v + ((size_t)(b*MCTX + r))*CDIM + h*DH + c);
        }
    }
    #pragma unroll
    for (int it = 0; it < 4; ++it) {
        int r = (tid >> 4) + it * 16;
        float rm = rowmax[(size_t)bh*NSEQ + n0 + r];
        float ri = 1.0f / rowz[(size_t)bh*NSEQ + n0 + r];
        #pragma unroll
        for (int jj = 0; jj < 5; jj++) {
            int m = (tid & 15) * 5 + jj;
            float w = 0.f;
            if (m < MCTX) {
                float s = S[((size_t)bh*NSEQ + n0 + r)*80 + m];
                float p = __expf(s - rm);
                float l = rintf(p * ri * inv_delta);
                l = fminf(fmaxf(l, 0.f), 255.f);
                w = l * delta;
            }
            Ws[m][r] = w;
        }
    }
    __syncthreads();
    float acc[4][4];
    #pragma unroll
    for (int i = 0; i < 4; i++)
        #pragma unroll
        for (int j = 0; j < 4; j++) acc[i][j] = 0.f;
    for (int m = 0; m < MCTX; m++) {
        float4 w4 = *(const float4*)&Ws[m][ty*4];
        float4 v4 = *(const float4*)&Vs[m][tx*4];
        float wa[4]={w4.x,w4.y,w4.z,w4.w}, va[4]={v4.x,v4.y,v4.z,v4.w};
        #pragma unroll
        for (int i = 0; i < 4; i++)
            #pragma unroll
            for (int j = 0; j < 4; j++) acc[i][j] = fmaf(wa[i], va[j], acc[i][j]);
    }
    #pragma unroll
    for (int i = 0; i < 4; i++) {
        float4 o = {tf32r(acc[i][0]), tf32r(acc[i][1]), tf32r(acc[i][2]), tf32r(acc[i][3])};
        *(float4*)(O + ((size_t)(b*NSEQ + n0 + ty*4 + i))*CDIM + h*DH + tx*4) = o;
    }
}

// -------- GEGLU (tf32-rounded out) --------
__global__ void geglu_kernel(const float* __restrict__ Hh, float* __restrict__ G)
{
    size_t n4 = (size_t)ROWS * FFD / 4;
    size_t stride = (size_t)gridDim.x * blockDim.x;
    for (size_t i = (size_t)blockIdx.x * blockDim.x + threadIdx.x; i < n4; i += stride) {
        size_t col4 = i % (FFD / 4), row = i / (FFD / 4);
        float4 a4 = *(const float4*)(Hh + row * FF2D + col4 * 4);
        float4 g4 = *(const float4*)(Hh + row * FF2D + FFD + col4 * 4);
        float4 o;
        o.x = tf32r(a4.x * gelu_tanh(g4.x)); o.y = tf32r(a4.y * gelu_tanh(g4.y));
        o.z = tf32r(a4.z * gelu_tanh(g4.z)); o.w = tf32r(a4.w * gelu_tanh(g4.w));
        *(float4*)(G + i * 4) = o;
    }
}

extern "C" void kernel_launch(void* const* d_in, const int* in_sizes, int n_in,
                              void* d_out, int out_size)
{
    const float* x    = (const float*)d_in[0];
    const float* ctx  = (const float*)d_in[1];
    const float* ln1g = (const float*)d_in[2];
    const float* ln1b = (const float*)d_in[3];
    const float* ln2g = (const float*)d_in[4];
    const float* ln2b = (const float*)d_in[5];
    const float* ln3g = (const float*)d_in[6];
    const float* ln3b = (const float*)d_in[7];
    const float* Wq1  = (const float*)d_in[8];
    const float* Wk1  = (const float*)d_in[9];
    const float* Wv1  = (const float*)d_in[10];
    const float* Wo1  = (const float*)d_in[11];
    const float* bo1  = (const float*)d_in[12];
    const float* Wq2  = (const float*)d_in[13];
    const float* Wk2  = (const float*)d_in[14];
    const float* Wv2  = (const float*)d_in[15];
    const float* Wo2  = (const float*)d_in[16];
    const float* bo2  = (const float*)d_in[17];
    const float* Wff1 = (const float*)d_in[18];
    const float* bff1 = (const float*)d_in[19];
    const float* Wff2 = (const float*)d_in[20];
    const float* bff2 = (const float*)d_in[21];
    float* out = (float*)d_out;

    float* sc = nullptr;
    cudaGetSymbolAddress((void**)&sc, g_scratch);
    float* XN = sc + OFF_XN;  float* Q  = sc + OFF_Q;
    float* K  = sc + OFF_K;   float* V  = sc + OFF_V;
    float* O  = sc + OFF_O;   float* X1 = sc + OFF_X1;
    float* S  = sc + OFF_S;   float* Hb = sc + OFF_H;
    float* G  = sc + OFF_G;   float* RM = sc + OFF_RM;
    float* RZ = sc + OFF_RZ;
    unsigned* AM = (unsigned*)(sc + OFF_AM);
    float* cWq1 = sc + OFF_WQ1; float* cWk1 = sc + OFF_WK1;
    float* cWv1 = sc + OFF_WV1; float* cWo1 = sc + OFF_WO1;
    float* cWq2 = sc + OFF_WQ2; float* cWo2 = sc + OFF_WO2;
    float* cWk2 = sc + OFF_WK2; float* cWv2 = sc + OFF_WV2;
    float* cWf1 = sc + OFF_WF1; float* cWf2 = sc + OFF_WF2;
    float* cCtx = sc + OFF_CTX;
    int8_t* LQ8 = (int8_t*)(sc + OFF_LQ8);
    int8_t* LK8 = (int8_t*)(sc + OFF_LK8);
    int8_t* LVT = (int8_t*)(sc + OFF_LVT);

    dim3 g1280(CDIM / 128, ROWS / 128);
    dim3 gcross(CDIM / 128, (CROSSROWS + 127) / 128);
    dim3 gff1(FF2D / 128, ROWS / 128);
    long long n4  = (long long)ROWS * CDIM / 4;
    long long n16 = (long long)ROWS * CDIM / 16;
    long long n4c = (long long)CROSSROWS * CDIM / 4;

    init_amax_kernel<<<1, 32>>>(AM);

    // ---- merged tf32 pre-convert (one launch, 11 jobs) ----
    ConvJobs cj;
    cj.src[0]=Wq1;  cj.dst[0]=cWq1; cj.n4[0]=(long long)SZ_W1/4;
    cj.src[1]=Wk1;  cj.dst[1]=cWk1; cj.n4[1]=(long long)SZ_W1/4;
    cj.src[2]=Wv1;  cj.dst[2]=cWv1; cj.n4[2]=(long long)SZ_W1/4;
    cj.src[3]=Wo1;  cj.dst[3]=cWo1; cj.n4[3]=(long long)SZ_W1/4;
    cj.src[4]=Wq2;  cj.dst[4]=cWq2; cj.n4[4]=(long long)SZ_W1/4;
    cj.src[5]=Wo2;  cj.dst[5]=cWo2; cj.n4[5]=(long long)SZ_W1/4;
    cj.src[6]=Wk2;  cj.dst[6]=cWk2; cj.n4[6]=(long long)SZ_WK2/4;
    cj.src[7]=Wv2;  cj.dst[7]=cWv2; cj.n4[7]=(long long)SZ_WK2/4;
    cj.src[8]=Wff1; cj.dst[8]=cWf1; cj.n4[8]=(long long)SZ_WF1/4;
    cj.src[9]=Wff2; cj.dst[9]=cWf2; cj.n4[9]=(long long)SZ_WF2/4;
    cj.src[10]=ctx; cj.dst[10]=cCtx; cj.n4[10]=(long long)SZ_CTXB/4;
    conv_tf32_multi<<<dim3(512, NCONV), 256>>>(cj);

    // ---- block 1: self attention (int8 tensor-core path) ----
    ln_kernel<<<ROWS, 256>>>(x, ln1g, ln1b, XN);
    tgemm_kernel<false,false,true><<<g1280,256>>>(XN, cWq1, Q, ROWS, CDIM, CDIM, nullptr, nullptr, AM+0);
    tgemm_kernel<false,false,true><<<g1280,256>>>(XN, cWk1, K, ROWS, CDIM, CDIM, nullptr, nullptr, AM+1);
    tgemm_kernel<false,false,true><<<g1280,256>>>(XN, cWv1, V, ROWS, CDIM, CDIM, nullptr, nullptr, AM+2);
    quant_s8_kernel<<<1024,256>>>(Q, LQ8, n16, AM+0);
    quant_s8_kernel<<<1024,256>>>(K, LK8, n16, AM+1);
    quant_v_t_kernel<<<dim3(NSEQ/64, BHD),256>>>(V, LVT, AM+2);
    self_scores_i8_kernel<<<dim3(8,8,BHD),256>>>(LQ8, LK8, S, AM);
    softmax_stats_kernel<<<BHD*NSEQ,256>>>(S, RM, RZ, AM+3, NSEQ, NSEQ);
    self_pv_i8_kernel<<<dim3(8,BHD),256>>>(S, LVT, RM, RZ, AM, O);
    tgemm_kernel<true,true,false><<<g1280,256>>>(O, cWo1, X1, ROWS, CDIM, CDIM, bo1, x, nullptr);

    // ---- block 2: cross attention (fp32 path, small) ----
    ln_kernel<<<ROWS,256>>>(X1, ln2g, ln2b, XN);
    tgemm_kernel<false,false,true><<<g1280,256>>>(XN, cWq2, Q, ROWS, CDIM, CDIM, nullptr, nullptr, AM+4);
    tgemm_kernel<false,false,true><<<gcross,256>>>(cCtx, cWk2, K, CROSSROWS, CDIM, CTXC, nullptr, nullptr, AM+5);
    tgemm_kernel<false,false,true><<<gcross,256>>>(cCtx, cWv2, V, CROSSROWS, CDIM, CTXC, nullptr, nullptr, AM+6);
    quant_sym_kernel<<<2048,256>>>(Q, n4, AM+4);
    quant_sym_kernel<<<512,256>>>(K, n4c, AM+5);
    quant_sym_kernel<<<512,256>>>(V, n4c, AM+6);
    cross_scores_kernel<<<dim3(16,BHD),256>>>(Q, K, S);
    softmax_stats_kernel<<<BHD*NSEQ,256>>>(S, RM, RZ, AM+7, MCTX, 80);
    cross_pv_kernel<<<dim3(16,BHD),256>>>(S, V, RM, RZ, AM+7, O);
    tgemm_kernel<true,true,false><<<g1280,256>>>(O, cWo2, X1, ROWS, CDIM, CDIM, bo2, X1, nullptr);

    // ---- block 3: GEGLU FF ----
    ln_kernel<<<ROWS,256>>>(X1, ln3g, ln3b, XN);
    tgemm_kernel<true,false,false><<<gff1,256>>>(XN, cWf1, Hb, ROWS, FF2D, CDIM, bff1, nullptr, nullptr);
    geglu_kernel<<<4096,256>>>(Hb, G);
    tgemm_kernel<true,true,false><<<g1280,256>>>(G, cWf2, out, ROWS, CDIM, FFD, bff2, X1, nullptr);
}